// round 1
// baseline (speedup 1.0000x reference)
#include <cuda_runtime.h>
#include <cuda_bf16.h>
#include <math.h>

// Problem constants (fixed by the dataset)
#define NNODES 100000
#define EHALF  1600000
#define NEDGE  (2*EHALF)     // 3,200,000 symmetrized directed edges
#define NFEAT  512
#define NHID   256
#define NOUT   64
#define KORD   10            // Chebyshev order

// ---------------------------------------------------------------------------
// Scratch (static device globals; allocation APIs are forbidden)
// ---------------------------------------------------------------------------
__device__ float g_hid[(size_t)NNODES * NHID];       // MLP hidden
__device__ float g_bufA[(size_t)NNODES * NOUT];      // x / rotating Tx buffer
__device__ float g_bufB[(size_t)NNODES * NOUT];
__device__ float g_bufC[(size_t)NNODES * NOUT];
__device__ float g_W1T[(size_t)NFEAT * NHID];        // W1 transposed [512,256]
__device__ float g_W2T[(size_t)NHID * NOUT];         // W2 transposed [256,64]
__device__ int   g_deg[NNODES];
__device__ float g_dinv[NNODES];
__device__ int   g_rowptr[NNODES + 1];
__device__ int   g_cursor[NNODES];
__device__ int   g_cols[NEDGE];
__device__ float g_norms[NEDGE];
__device__ float g_coe[KORD + 1];

// ---------------------------------------------------------------------------
// Chebyshev coefficients: coe[i] = 2/(K+1) * sum_j relu(temp[j]) * cos(i*theta_j)
// coe[0] is stored pre-halved (reference uses coe[0]/2).
// ---------------------------------------------------------------------------
__global__ void cheb_coeffs_kernel(const float* __restrict__ temp) {
    int i = threadIdx.x;
    if (i > KORD) return;
    const float PI = 3.14159265358979323846f;
    float s = 0.0f;
    for (int j = 0; j <= KORD; j++) {
        float t = fmaxf(temp[j], 0.0f);
        float theta = (KORD - j + 0.5f) * PI / (KORD + 1);
        s += t * cosf((float)i * theta);
    }
    float c = (2.0f / (KORD + 1)) * s;
    if (i == 0) c *= 0.5f;
    g_coe[i] = c;
}

// ---------------------------------------------------------------------------
// Transpose (rows x cols) -> (cols x rows)
// ---------------------------------------------------------------------------
__global__ void transpose_kernel(const float* __restrict__ in, float* __restrict__ out,
                                 int rows, int cols) {
    __shared__ float tile[32][33];
    int x = blockIdx.x * 32 + threadIdx.x;   // col
    int y = blockIdx.y * 32 + threadIdx.y;   // row
    if (x < cols && y < rows) tile[threadIdx.y][threadIdx.x] = in[(size_t)y * cols + x];
    __syncthreads();
    int tx = blockIdx.y * 32 + threadIdx.x;  // along rows
    int ty = blockIdx.x * 32 + threadIdx.y;  // along cols
    if (tx < rows && ty < cols) out[(size_t)ty * rows + tx] = tile[threadIdx.x][threadIdx.y];
}

// ---------------------------------------------------------------------------
// SGEMM1: C[N,256] = relu(A[N,512] @ BT[512,256] + bias)
// BM=128, BN=128, BK=8, TM=TN=8, 256 threads.
// ---------------------------------------------------------------------------
__global__ __launch_bounds__(256)
void sgemm1_relu_kernel(const float* __restrict__ A, const float* __restrict__ BT,
                        const float* __restrict__ bias, float* __restrict__ C, int nrows) {
    const int K = NFEAT, NC = NHID;
    __shared__ float As[8][128];
    __shared__ float Bs[8][128];
    int tid = threadIdx.x;
    int row0 = blockIdx.x * 128;
    int col0 = blockIdx.y * 128;

    int aRow = tid >> 1;            // 0..127
    int aCol = (tid & 1) * 4;       // 0 or 4
    int bRow = tid >> 5;            // 0..7
    int bCol = (tid & 31) * 4;      // 0..124

    int tr = (tid >> 4) * 8;        // 0..120
    int tc = (tid & 15) * 8;        // 0..120

    float acc[8][8];
#pragma unroll
    for (int i = 0; i < 8; i++)
#pragma unroll
        for (int j = 0; j < 8; j++) acc[i][j] = 0.0f;

    for (int k0 = 0; k0 < K; k0 += 8) {
        float4 av;
        int gr = row0 + aRow;
        if (gr < nrows) av = *(const float4*)&A[(size_t)gr * K + k0 + aCol];
        else            av = make_float4(0.f, 0.f, 0.f, 0.f);
        As[aCol + 0][aRow] = av.x;
        As[aCol + 1][aRow] = av.y;
        As[aCol + 2][aRow] = av.z;
        As[aCol + 3][aRow] = av.w;
        float4 bv = *(const float4*)&BT[(size_t)(k0 + bRow) * NC + col0 + bCol];
        *(float4*)&Bs[bRow][bCol] = bv;
        __syncthreads();
#pragma unroll
        for (int k = 0; k < 8; k++) {
            float4 a0 = *(float4*)&As[k][tr];
            float4 a1 = *(float4*)&As[k][tr + 4];
            float4 b0 = *(float4*)&Bs[k][tc];
            float4 b1 = *(float4*)&Bs[k][tc + 4];
            float am[8] = {a0.x, a0.y, a0.z, a0.w, a1.x, a1.y, a1.z, a1.w};
            float bn[8] = {b0.x, b0.y, b0.z, b0.w, b1.x, b1.y, b1.z, b1.w};
#pragma unroll
            for (int i = 0; i < 8; i++)
#pragma unroll
                for (int j = 0; j < 8; j++) acc[i][j] += am[i] * bn[j];
        }
        __syncthreads();
    }
#pragma unroll
    for (int i = 0; i < 8; i++) {
        int gr = row0 + tr + i;
        if (gr >= nrows) continue;
#pragma unroll
        for (int j = 0; j < 8; j += 4) {
            float4 o;
            o.x = fmaxf(acc[i][j + 0] + bias[col0 + tc + j + 0], 0.f);
            o.y = fmaxf(acc[i][j + 1] + bias[col0 + tc + j + 1], 0.f);
            o.z = fmaxf(acc[i][j + 2] + bias[col0 + tc + j + 2], 0.f);
            o.w = fmaxf(acc[i][j + 3] + bias[col0 + tc + j + 3], 0.f);
            *(float4*)&C[(size_t)gr * NC + col0 + tc + j] = o;
        }
    }
}

// ---------------------------------------------------------------------------
// SGEMM2: C[N,64] = A[N,256] @ BT[256,64] + bias
// BM=64, BN=64, BK=16, TM=TN=4, 256 threads.
// ---------------------------------------------------------------------------
__global__ __launch_bounds__(256)
void sgemm2_kernel(const float* __restrict__ A, const float* __restrict__ BT,
                   const float* __restrict__ bias, float* __restrict__ C, int nrows) {
    const int K = NHID, NC = NOUT;
    __shared__ float As[16][64];
    __shared__ float Bs[16][64];
    int tid = threadIdx.x;
    int row0 = blockIdx.x * 64;

    int aRow = tid >> 2;           // 0..63
    int aCol = (tid & 3) * 4;      // 0..12
    int bRow = tid >> 4;           // 0..15
    int bCol = (tid & 15) * 4;     // 0..60

    int tr = (tid >> 4) * 4;       // 0..60
    int tc = (tid & 15) * 4;       // 0..60

    float acc[4][4];
#pragma unroll
    for (int i = 0; i < 4; i++)
#pragma unroll
        for (int j = 0; j < 4; j++) acc[i][j] = 0.0f;

    for (int k0 = 0; k0 < K; k0 += 16) {
        float4 av;
        int gr = row0 + aRow;
        if (gr < nrows) av = *(const float4*)&A[(size_t)gr * K + k0 + aCol];
        else            av = make_float4(0.f, 0.f, 0.f, 0.f);
        As[aCol + 0][aRow] = av.x;
        As[aCol + 1][aRow] = av.y;
        As[aCol + 2][aRow] = av.z;
        As[aCol + 3][aRow] = av.w;
        float4 bv = *(const float4*)&BT[(size_t)(k0 + bRow) * NC + bCol];
        *(float4*)&Bs[bRow][bCol] = bv;
        __syncthreads();
#pragma unroll
        for (int k = 0; k < 16; k++) {
            float4 a0 = *(float4*)&As[k][tr];
            float4 b0 = *(float4*)&Bs[k][tc];
            float am[4] = {a0.x, a0.y, a0.z, a0.w};
            float bn[4] = {b0.x, b0.y, b0.z, b0.w};
#pragma unroll
            for (int i = 0; i < 4; i++)
#pragma unroll
                for (int j = 0; j < 4; j++) acc[i][j] += am[i] * bn[j];
        }
        __syncthreads();
    }
#pragma unroll
    for (int i = 0; i < 4; i++) {
        int gr = row0 + tr + i;
        if (gr >= nrows) continue;
        float4 o;
        o.x = acc[i][0] + bias[tc + 0];
        o.y = acc[i][1] + bias[tc + 1];
        o.z = acc[i][2] + bias[tc + 2];
        o.w = acc[i][3] + bias[tc + 3];
        *(float4*)&C[(size_t)gr * NC + tc] = o;
    }
}

// ---------------------------------------------------------------------------
// Graph preprocessing: degree, dinv, rowptr (scan), CSR scatter
// ---------------------------------------------------------------------------
__global__ void degree_kernel(const int* __restrict__ row, int nedge) {
    int e = blockIdx.x * blockDim.x + threadIdx.x;
    if (e >= nedge) return;
    atomicAdd(&g_deg[row[e]], 1);
}

__global__ void dinv_kernel(int n) {
    int i = blockIdx.x * blockDim.x + threadIdx.x;
    if (i >= n) return;
    int d = g_deg[i];
    g_dinv[i] = (d > 0) ? rsqrtf((float)d) : 0.0f;
}

__global__ void scan_kernel(int n) {
    __shared__ int sums[1024];
    int tid = threadIdx.x;
    int chunk = (n + 1023) / 1024;
    int start = tid * chunk;
    int end = min(start + chunk, n);
    int s = 0;
    for (int i = start; i < end; i++) s += g_deg[i];
    sums[tid] = s;
    __syncthreads();
    for (int off = 1; off < 1024; off <<= 1) {
        int v = 0;
        if (tid >= off) v = sums[tid - off];
        __syncthreads();
        if (tid >= off) sums[tid] += v;
        __syncthreads();
    }
    int prefix = (tid == 0) ? 0 : sums[tid - 1];
    for (int i = start; i < end; i++) {
        g_rowptr[i] = prefix;
        prefix += g_deg[i];
    }
    if (tid == 1023) g_rowptr[n] = prefix;
}

__global__ void build_csr_kernel(const int* __restrict__ row, const int* __restrict__ col,
                                 int nedge) {
    int e = blockIdx.x * blockDim.x + threadIdx.x;
    if (e >= nedge) return;
    int r = row[e];
    int c = col[e];
    int pos = g_rowptr[r] + atomicAdd(&g_cursor[r], 1);
    g_cols[pos] = c;
    g_norms[pos] = -g_dinv[r] * g_dinv[c];
}

// ---------------------------------------------------------------------------
// Propagation (CSR SpMM, one warp per node, lane owns float2 of 64 feats)
// ---------------------------------------------------------------------------
__device__ __forceinline__ float2 csr_gather(const float* __restrict__ v, int r, int lane) {
    int beg = g_rowptr[r];
    int end = g_rowptr[r + 1];
    float2 acc = make_float2(0.f, 0.f);
    for (int j = beg; j < end; j += 32) {
        int cnt = min(32, end - j);
        int   myc = 0;
        float myn = 0.f;
        if (lane < cnt) { myc = g_cols[j + lane]; myn = g_norms[j + lane]; }
        for (int t = 0; t < cnt; t++) {
            int   c = __shfl_sync(0xffffffffu, myc, t);
            float w = __shfl_sync(0xffffffffu, myn, t);
            float2 vv = *(const float2*)&v[(size_t)c * NOUT + lane * 2];
            acc.x = fmaf(w, vv.x, acc.x);
            acc.y = fmaf(w, vv.y, acc.y);
        }
    }
    return acc;
}

// Tx1 = prop(x);  out = coe[0](pre-halved)*x + coe[1]*Tx1
__global__ __launch_bounds__(256)
void prop_first_kernel(const float* __restrict__ x, float* __restrict__ Tx1,
                       float* __restrict__ out, int n) {
    int warp = (blockIdx.x * blockDim.x + threadIdx.x) >> 5;
    int lane = threadIdx.x & 31;
    if (warp >= n) return;
    float2 acc = csr_gather(x, warp, lane);
    size_t idx = (size_t)warp * NOUT + lane * 2;
    float c0 = g_coe[0];   // pre-halved
    float c1 = g_coe[1];
    float2 xv = *(const float2*)&x[idx];
    *(float2*)&Tx1[idx] = acc;
    float2 o;
    o.x = c0 * xv.x + c1 * acc.x;
    o.y = c0 * xv.y + c1 * acc.y;
    *(float2*)&out[idx] = o;
}

// Tx2 = 2*prop(Tx1) - Tx0;  out += coe[ci]*Tx2
__global__ __launch_bounds__(256)
void prop_step_kernel(const float* __restrict__ Tx1, const float* __restrict__ Tx0,
                      float* __restrict__ Tx2, float* __restrict__ out, int ci, int n) {
    int warp = (blockIdx.x * blockDim.x + threadIdx.x) >> 5;
    int lane = threadIdx.x & 31;
    if (warp >= n) return;
    float2 acc = csr_gather(Tx1, warp, lane);
    size_t idx = (size_t)warp * NOUT + lane * 2;
    float2 t0 = *(const float2*)&Tx0[idx];
    float2 t2;
    t2.x = 2.0f * acc.x - t0.x;
    t2.y = 2.0f * acc.y - t0.y;
    *(float2*)&Tx2[idx] = t2;
    float ci_c = g_coe[ci];
    float2 o = *(const float2*)&out[idx];
    o.x = fmaf(ci_c, t2.x, o.x);
    o.y = fmaf(ci_c, t2.y, o.y);
    *(float2*)&out[idx] = o;
}

// ---------------------------------------------------------------------------
// Launch
// ---------------------------------------------------------------------------
extern "C" void kernel_launch(void* const* d_in, const int* in_sizes, int n_in,
                              void* d_out, int out_size) {
    const float* feature = (const float*)d_in[0];
    const float* W1      = (const float*)d_in[1];
    const float* b1      = (const float*)d_in[2];
    const float* W2      = (const float*)d_in[3];
    const float* b2      = (const float*)d_in[4];
    const float* temp    = (const float*)d_in[5];
    const int*   edge    = (const int*)d_in[6];

    const int n = NNODES;
    const int E = in_sizes[6] / 2;            // 3,200,000
    const int* row = edge;
    const int* col = edge + E;
    float* out = (float*)d_out;

    // scratch pointers
    void *p_hid, *p_bufA, *p_bufB, *p_bufC, *p_w1t, *p_w2t, *p_deg, *p_cursor;
    cudaGetSymbolAddress(&p_hid, g_hid);
    cudaGetSymbolAddress(&p_bufA, g_bufA);
    cudaGetSymbolAddress(&p_bufB, g_bufB);
    cudaGetSymbolAddress(&p_bufC, g_bufC);
    cudaGetSymbolAddress(&p_w1t, g_W1T);
    cudaGetSymbolAddress(&p_w2t, g_W2T);
    cudaGetSymbolAddress(&p_deg, g_deg);
    cudaGetSymbolAddress(&p_cursor, g_cursor);

    // 1. Chebyshev coefficients
    cheb_coeffs_kernel<<<1, 32>>>(temp);

    // 2. Transpose weights
    {
        dim3 blk(32, 32);
        dim3 g1(NFEAT / 32, NHID / 32);   // W1: 256x512 -> 512x256
        transpose_kernel<<<g1, blk>>>(W1, (float*)p_w1t, NHID, NFEAT);
        dim3 g2(NHID / 32, NOUT / 32);    // W2: 64x256 -> 256x64
        transpose_kernel<<<g2, blk>>>(W2, (float*)p_w2t, NOUT, NHID);
    }

    // 3. MLP
    {
        dim3 grid((n + 127) / 128, NHID / 128);
        sgemm1_relu_kernel<<<grid, 256>>>(feature, (const float*)p_w1t, b1, (float*)p_hid, n);
        dim3 grid2((n + 63) / 64, 1);
        sgemm2_kernel<<<grid2, 256>>>((const float*)p_hid, (const float*)p_w2t, b2,
                                      (float*)p_bufA, n);
    }

    // 4. Graph preprocessing -> CSR
    cudaMemsetAsync(p_deg, 0, n * sizeof(int), 0);
    cudaMemsetAsync(p_cursor, 0, n * sizeof(int), 0);
    degree_kernel<<<(E + 255) / 256, 256>>>(row, E);
    dinv_kernel<<<(n + 255) / 256, 256>>>(n);
    scan_kernel<<<1, 1024>>>(n);
    build_csr_kernel<<<(E + 255) / 256, 256>>>(row, col, E);

    // 5. Chebyshev propagation (10 SpMMs), one warp per node
    int pblocks = (n * 32 + 255) / 256;
    float* b0 = (float*)p_bufA;   // Tx0 = x
    float* b1p = (float*)p_bufB;  // Tx1
    float* b2p = (float*)p_bufC;  // Tx2
    prop_first_kernel<<<pblocks, 256>>>(b0, b1p, out, n);
    for (int i = 2; i <= KORD; i++) {
        prop_step_kernel<<<pblocks, 256>>>(b1p, b0, b2p, out, i, n);
        float* t = b0; b0 = b1p; b1p = b2p; b2p = t;
    }

    (void)n_in; (void)out_size;
}

// round 3
// speedup vs baseline: 1.3504x; 1.3504x over previous
#include <cuda_runtime.h>
#include <cuda_bf16.h>
#include <math.h>
#include <stdint.h>

// Problem constants (fixed by the dataset)
#define NNODES 100000
#define EHALF  1600000
#define NEDGE  (2*EHALF)     // 3,200,000 symmetrized directed edges
#define NFEAT  512
#define NHID   256
#define NOUT   64
#define KORD   10            // Chebyshev order

// ---------------------------------------------------------------------------
// Scratch (static device globals; allocation APIs are forbidden)
// ---------------------------------------------------------------------------
__device__ float g_bufA[(size_t)NNODES * NOUT];      // x / rotating Tx buffer
__device__ float g_bufB[(size_t)NNODES * NOUT];
__device__ float g_bufC[(size_t)NNODES * NOUT];
__device__ __nv_bfloat16 g_hidHi[(size_t)NNODES * NHID];  // hidden split-bf16
__device__ __nv_bfloat16 g_hidLo[(size_t)NNODES * NHID];
__device__ __nv_bfloat16 g_W1Hi[(size_t)NHID * NFEAT];    // W1 split [256,512]
__device__ __nv_bfloat16 g_W1Lo[(size_t)NHID * NFEAT];
__device__ __nv_bfloat16 g_W2Hi[(size_t)NOUT * NHID];     // W2 split [64,256]
__device__ __nv_bfloat16 g_W2Lo[(size_t)NOUT * NHID];
__device__ int   g_deg[NNODES];
__device__ float g_dinv[NNODES];
__device__ int   g_rowptr[NNODES + 1];
__device__ int   g_cursor[NNODES];
__device__ int   g_cols[NEDGE];
__device__ float g_norms[NEDGE];
__device__ float g_coe[KORD + 1];

// ---------------------------------------------------------------------------
// Base-target PTX helpers (NO 'a'-suffix features: mma.sync + ldmatrix only)
// ---------------------------------------------------------------------------
__device__ __forceinline__ uint32_t smem_u32(const void* p) {
    uint32_t a;
    asm("{ .reg .u64 t; cvta.to.shared.u64 t, %1; cvt.u32.u64 %0, t; }" : "=r"(a) : "l"(p));
    return a;
}

#define LDSM4(R, addr) \
    asm volatile("ldmatrix.sync.aligned.m8n8.x4.shared.b16 {%0,%1,%2,%3}, [%4];" \
        : "=r"((R)[0]), "=r"((R)[1]), "=r"((R)[2]), "=r"((R)[3]) : "r"(addr))

#define MMA16816(C, A, b0, b1) \
    asm volatile("mma.sync.aligned.m16n8k16.row.col.f32.bf16.bf16.f32 " \
        "{%0,%1,%2,%3},{%4,%5,%6,%7},{%8,%9},{%0,%1,%2,%3};" \
        : "+f"((C)[0]), "+f"((C)[1]), "+f"((C)[2]), "+f"((C)[3]) \
        : "r"((A)[0]), "r"((A)[1]), "r"((A)[2]), "r"((A)[3]), "r"(b0), "r"(b1))

__device__ __forceinline__ uint32_t pack_bf2(__nv_bfloat16 a, __nv_bfloat16 b) {
    uint32_t lo = (uint32_t)__bfloat16_as_ushort(a);
    uint32_t hi = (uint32_t)__bfloat16_as_ushort(b);
    return lo | (hi << 16);
}

// ---------------------------------------------------------------------------
// Split fp32 -> (bf16 hi, bf16 lo)
// ---------------------------------------------------------------------------
__global__ void split_kernel(const float* __restrict__ w, __nv_bfloat16* __restrict__ hi,
                             __nv_bfloat16* __restrict__ lo, int n) {
    int i = blockIdx.x * blockDim.x + threadIdx.x;
    if (i >= n) return;
    float x = w[i];
    __nv_bfloat16 h = __float2bfloat16(x);
    hi[i] = h;
    lo[i] = __float2bfloat16(x - __bfloat162float(h));
}

// ---------------------------------------------------------------------------
// Split-bf16 GEMM on mma.sync tensor cores.
//   D[M, NCOL] = A[M, KT] @ B[NCOL, KT]^T + bias   (3-term split, fp32 acc)
// BM=128, BK=64, 8 warps (2 x 4). GEMM1: BN=128 (NCOL=256, 2 y-blocks),
// A = fp32 converted in-flight, epilogue relu -> bf16 hi/lo pair.
// GEMM2: BN=64, A = bf16 hi/lo pair, epilogue +bias -> fp32.
// SMEM rows of 128B with seg^(row&7) swizzle -> conflict-free ldmatrix.x4.
// ---------------------------------------------------------------------------
template <int BN, int KT, int NCOL, bool IS_G1>
__global__ __launch_bounds__(256)
void gemm_mma_kernel(const float* __restrict__ Af32,
                     const __nv_bfloat16* __restrict__ Ahi,
                     const __nv_bfloat16* __restrict__ Alo,
                     const __nv_bfloat16* __restrict__ Bhi,
                     const __nv_bfloat16* __restrict__ Blo,
                     const float* __restrict__ bias,
                     __nv_bfloat16* __restrict__ outHi,
                     __nv_bfloat16* __restrict__ outLo,
                     float* __restrict__ outF,
                     int nrows) {
    constexpr int WN  = BN / 4;        // 32 or 16
    constexpr int NT  = WN / 8;        // n8 tiles per warp: 4 or 2
    constexpr int NP  = NT / 2;        // n16 ldmatrix pairs: 2 or 1
    constexpr int CH  = KT / 64;       // k chunks
    constexpr int BNB = BN * 128;      // bytes per B half per stage
    constexpr int BIT = BN / 32;       // B fetch iterations

    extern __shared__ char smem[];
    const uint32_t sb = smem_u32(smem);
    const int tid = threadIdx.x, lane = tid & 31, wid = tid >> 5;
    const int warpM = wid >> 2, warpN = wid & 3;
    const int m0 = blockIdx.x * 128, n0 = blockIdx.y * BN;
    const int s = tid & 7, rb = tid >> 3;   // fetch: seg 0..7, row base 0..31

    // SMEM map: A hi/lo (2 stages x 2 halves x 16KB) then B hi/lo
    //   Ah(st) = st*32768, Al(st) = +16384
    //   Bh(st) = 65536 + st*2*BNB, Bl(st) = +BNB
    float cacc[4][NT][4];
#pragma unroll
    for (int mt = 0; mt < 4; mt++)
#pragma unroll
        for (int nt = 0; nt < NT; nt++)
#pragma unroll
            for (int q = 0; q < 4; q++) cacc[mt][nt][q] = 0.0f;

    // prefetch registers
    float af[32];
    uint4 ahv[4], alv[4];
    uint4 bhv[BIT], blv[BIT];

    auto FETCH = [&](int c) {
        if (IS_G1) {
#pragma unroll
            for (int it = 0; it < 4; it++) {
                int g = m0 + rb + it * 32;
                if (g < nrows) {
                    const float4* p = (const float4*)(Af32 + (size_t)g * KT + c * 64 + s * 8);
                    float4 v0 = p[0], v1 = p[1];
                    af[it*8+0]=v0.x; af[it*8+1]=v0.y; af[it*8+2]=v0.z; af[it*8+3]=v0.w;
                    af[it*8+4]=v1.x; af[it*8+5]=v1.y; af[it*8+6]=v1.z; af[it*8+7]=v1.w;
                } else {
#pragma unroll
                    for (int j = 0; j < 8; j++) af[it*8+j] = 0.0f;
                }
            }
        } else {
#pragma unroll
            for (int it = 0; it < 4; it++) {
                int g = m0 + rb + it * 32;
                if (g < nrows) {
                    ahv[it] = *(const uint4*)(Ahi + (size_t)g * KT + c * 64 + s * 8);
                    alv[it] = *(const uint4*)(Alo + (size_t)g * KT + c * 64 + s * 8);
                } else {
                    ahv[it] = make_uint4(0,0,0,0);
                    alv[it] = make_uint4(0,0,0,0);
                }
            }
        }
#pragma unroll
        for (int it = 0; it < BIT; it++) {
            int r = rb + it * 32;
            bhv[it] = *(const uint4*)(Bhi + (size_t)(n0 + r) * KT + c * 64 + s * 8);
            blv[it] = *(const uint4*)(Blo + (size_t)(n0 + r) * KT + c * 64 + s * 8);
        }
    };

    auto STORE = [&](int st) {
        char* aH = smem + st * 32768;
        char* aL = aH + 16384;
#pragma unroll
        for (int it = 0; it < 4; it++) {
            int r = rb + it * 32;
            uint32_t off = (uint32_t)r * 128u + (uint32_t)((s ^ (r & 7)) << 4);
            if (IS_G1) {
                uint4 H, L;
                uint32_t hw[4], lw[4];
#pragma unroll
                for (int p = 0; p < 4; p++) {
                    float x0 = af[it*8 + 2*p], x1 = af[it*8 + 2*p + 1];
                    __nv_bfloat16 h0 = __float2bfloat16(x0), h1 = __float2bfloat16(x1);
                    __nv_bfloat16 l0 = __float2bfloat16(x0 - __bfloat162float(h0));
                    __nv_bfloat16 l1 = __float2bfloat16(x1 - __bfloat162float(h1));
                    hw[p] = pack_bf2(h0, h1);
                    lw[p] = pack_bf2(l0, l1);
                }
                H = make_uint4(hw[0], hw[1], hw[2], hw[3]);
                L = make_uint4(lw[0], lw[1], lw[2], lw[3]);
                *(uint4*)(aH + off) = H;
                *(uint4*)(aL + off) = L;
            } else {
                *(uint4*)(aH + off) = ahv[it];
                *(uint4*)(aL + off) = alv[it];
            }
        }
        char* bH = smem + 65536 + st * 2 * BNB;
        char* bL = bH + BNB;
#pragma unroll
        for (int it = 0; it < BIT; it++) {
            int r = rb + it * 32;
            uint32_t off = (uint32_t)r * 128u + (uint32_t)((s ^ (r & 7)) << 4);
            *(uint4*)(bH + off) = bhv[it];
            *(uint4*)(bL + off) = blv[it];
        }
    };

    auto COMPUTE = [&](int st) {
        const uint32_t aH = sb + st * 32768, aL = aH + 16384;
        const uint32_t bH = sb + 65536 + st * 2 * BNB, bL = bH + BNB;
        const int g = lane >> 3, r = lane & 7;
#pragma unroll
        for (int ks = 0; ks < 4; ks++) {
            uint32_t Ah[4][4], Al[4][4], Bh[NP][4], Bl[NP][4];
#pragma unroll
            for (int mt = 0; mt < 4; mt++) {
                int row = warpM * 64 + mt * 16 + (g & 1) * 8 + r;
                int seg = ks * 2 + (g >> 1);
                uint32_t off = (uint32_t)row * 128u + (uint32_t)((seg ^ (row & 7)) << 4);
                LDSM4(Ah[mt], aH + off);
                LDSM4(Al[mt], aL + off);
            }
#pragma unroll
            for (int pt = 0; pt < NP; pt++) {
                int row = warpN * WN + pt * 16 + (g >> 1) * 8 + r;
                int seg = ks * 2 + (g & 1);
                uint32_t off = (uint32_t)row * 128u + (uint32_t)((seg ^ (row & 7)) << 4);
                LDSM4(Bh[pt], bH + off);
                LDSM4(Bl[pt], bL + off);
            }
            // pass 1: Ah * Bh
#pragma unroll
            for (int mt = 0; mt < 4; mt++)
#pragma unroll
                for (int nt = 0; nt < NT; nt++) {
                    const uint32_t* b = &Bh[nt >> 1][(nt & 1) * 2];
                    MMA16816(cacc[mt][nt], Ah[mt], b[0], b[1]);
                }
            // pass 2: Ah * Bl
#pragma unroll
            for (int mt = 0; mt < 4; mt++)
#pragma unroll
                for (int nt = 0; nt < NT; nt++) {
                    const uint32_t* b = &Bl[nt >> 1][(nt & 1) * 2];
                    MMA16816(cacc[mt][nt], Ah[mt], b[0], b[1]);
                }
            // pass 3: Al * Bh
#pragma unroll
            for (int mt = 0; mt < 4; mt++)
#pragma unroll
                for (int nt = 0; nt < NT; nt++) {
                    const uint32_t* b = &Bh[nt >> 1][(nt & 1) * 2];
                    MMA16816(cacc[mt][nt], Al[mt], b[0], b[1]);
                }
        }
    };

    FETCH(0);
    STORE(0);
    __syncthreads();
    for (int c = 0; c < CH; c++) {
        if (c + 1 < CH) FETCH(c + 1);
        COMPUTE(c & 1);
        if (c + 1 < CH) STORE((c + 1) & 1);
        __syncthreads();
    }

    // ---- epilogue ----
    const int qr = lane >> 2, qc = (lane & 3) * 2;
#pragma unroll
    for (int mt = 0; mt < 4; mt++) {
        int row0 = m0 + warpM * 64 + mt * 16 + qr;
#pragma unroll
        for (int nt = 0; nt < NT; nt++) {
            int col = n0 + warpN * WN + nt * 8 + qc;
            float b0 = __ldg(bias + col), b1 = __ldg(bias + col + 1);
#pragma unroll
            for (int h = 0; h < 2; h++) {
                int row = row0 + h * 8;
                if (row >= nrows) continue;
                float x0 = cacc[mt][nt][h * 2 + 0] + b0;
                float x1 = cacc[mt][nt][h * 2 + 1] + b1;
                if (IS_G1) {
                    x0 = fmaxf(x0, 0.f);
                    x1 = fmaxf(x1, 0.f);
                    __nv_bfloat16 h0 = __float2bfloat16(x0), h1 = __float2bfloat16(x1);
                    __nv_bfloat16 l0 = __float2bfloat16(x0 - __bfloat162float(h0));
                    __nv_bfloat16 l1 = __float2bfloat16(x1 - __bfloat162float(h1));
                    *(uint32_t*)(outHi + (size_t)row * NCOL + col) = pack_bf2(h0, h1);
                    *(uint32_t*)(outLo + (size_t)row * NCOL + col) = pack_bf2(l0, l1);
                } else {
                    *(float2*)(outF + (size_t)row * NCOL + col) = make_float2(x0, x1);
                }
            }
        }
    }
}

// ---------------------------------------------------------------------------
// Chebyshev coefficients
// ---------------------------------------------------------------------------
__global__ void cheb_coeffs_kernel(const float* __restrict__ temp) {
    int i = threadIdx.x;
    if (i > KORD) return;
    const float PI = 3.14159265358979323846f;
    float s = 0.0f;
    for (int j = 0; j <= KORD; j++) {
        float t = fmaxf(temp[j], 0.0f);
        float theta = (KORD - j + 0.5f) * PI / (KORD + 1);
        s += t * cosf((float)i * theta);
    }
    float c = (2.0f / (KORD + 1)) * s;
    if (i == 0) c *= 0.5f;
    g_coe[i] = c;
}

// ---------------------------------------------------------------------------
// Graph preprocessing
// ---------------------------------------------------------------------------
__global__ void degree_kernel(const int* __restrict__ row, int nedge) {
    int e = blockIdx.x * blockDim.x + threadIdx.x;
    if (e >= nedge) return;
    atomicAdd(&g_deg[row[e]], 1);
}

__global__ void dinv_kernel(int n) {
    int i = blockIdx.x * blockDim.x + threadIdx.x;
    if (i >= n) return;
    int d = g_deg[i];
    g_dinv[i] = (d > 0) ? rsqrtf((float)d) : 0.0f;
}

__global__ void scan_kernel(int n) {
    __shared__ int sums[1024];
    int tid = threadIdx.x;
    int chunk = (n + 1023) / 1024;
    int start = tid * chunk;
    int end = min(start + chunk, n);
    int s = 0;
    for (int i = start; i < end; i++) s += g_deg[i];
    sums[tid] = s;
    __syncthreads();
    for (int off = 1; off < 1024; off <<= 1) {
        int v = 0;
        if (tid >= off) v = sums[tid - off];
        __syncthreads();
        if (tid >= off) sums[tid] += v;
        __syncthreads();
    }
    int prefix = (tid == 0) ? 0 : sums[tid - 1];
    for (int i = start; i < end; i++) {
        g_rowptr[i] = prefix;
        prefix += g_deg[i];
    }
    if (tid == 1023) g_rowptr[n] = prefix;
}

__global__ void build_csr_kernel(const int* __restrict__ row, const int* __restrict__ col,
                                 int nedge) {
    int e = blockIdx.x * blockDim.x + threadIdx.x;
    if (e >= nedge) return;
    int r = row[e];
    int c = col[e];
    int pos = g_rowptr[r] + atomicAdd(&g_cursor[r], 1);
    g_cols[pos] = c;
    g_norms[pos] = -g_dinv[r] * g_dinv[c];
}

// ---------------------------------------------------------------------------
// Propagation (CSR SpMM, one warp per node, lane owns float2 of 64 feats)
// ---------------------------------------------------------------------------
__device__ __forceinline__ float2 csr_gather(const float* __restrict__ v, int r, int lane) {
    int beg = g_rowptr[r];
    int end = g_rowptr[r + 1];
    float2 acc = make_float2(0.f, 0.f);
    for (int j = beg; j < end; j += 32) {
        int cnt = min(32, end - j);
        int   myc = 0;
        float myn = 0.f;
        if (lane < cnt) { myc = g_cols[j + lane]; myn = g_norms[j + lane]; }
        for (int t = 0; t < cnt; t++) {
            int   c = __shfl_sync(0xffffffffu, myc, t);
            float w = __shfl_sync(0xffffffffu, myn, t);
            float2 vv = *(const float2*)&v[(size_t)c * NOUT + lane * 2];
            acc.x = fmaf(w, vv.x, acc.x);
            acc.y = fmaf(w, vv.y, acc.y);
        }
    }
    return acc;
}

__global__ __launch_bounds__(256)
void prop_first_kernel(const float* __restrict__ x, float* __restrict__ Tx1,
                       float* __restrict__ out, int n) {
    int warp = (blockIdx.x * blockDim.x + threadIdx.x) >> 5;
    int lane = threadIdx.x & 31;
    if (warp >= n) return;
    float2 acc = csr_gather(x, warp, lane);
    size_t idx = (size_t)warp * NOUT + lane * 2;
    float c0 = g_coe[0];   // pre-halved
    float c1 = g_coe[1];
    float2 xv = *(const float2*)&x[idx];
    *(float2*)&Tx1[idx] = acc;
    float2 o;
    o.x = c0 * xv.x + c1 * acc.x;
    o.y = c0 * xv.y + c1 * acc.y;
    *(float2*)&out[idx] = o;
}

__global__ __launch_bounds__(256)
void prop_step_kernel(const float* __restrict__ Tx1, const float* __restrict__ Tx0,
                      float* __restrict__ Tx2, float* __restrict__ out, int ci, int n) {
    int warp = (blockIdx.x * blockDim.x + threadIdx.x) >> 5;
    int lane = threadIdx.x & 31;
    if (warp >= n) return;
    float2 acc = csr_gather(Tx1, warp, lane);
    size_t idx = (size_t)warp * NOUT + lane * 2;
    float2 t0 = *(const float2*)&Tx0[idx];
    float2 t2;
    t2.x = 2.0f * acc.x - t0.x;
    t2.y = 2.0f * acc.y - t0.y;
    *(float2*)&Tx2[idx] = t2;
    float ci_c = g_coe[ci];
    float2 o = *(const float2*)&out[idx];
    o.x = fmaf(ci_c, t2.x, o.x);
    o.y = fmaf(ci_c, t2.y, o.y);
    *(float2*)&out[idx] = o;
}

// ---------------------------------------------------------------------------
// Launch
// ---------------------------------------------------------------------------
extern "C" void kernel_launch(void* const* d_in, const int* in_sizes, int n_in,
                              void* d_out, int out_size) {
    const float* feature = (const float*)d_in[0];
    const float* W1      = (const float*)d_in[1];
    const float* b1      = (const float*)d_in[2];
    const float* W2      = (const float*)d_in[3];
    const float* b2      = (const float*)d_in[4];
    const float* temp    = (const float*)d_in[5];
    const int*   edge    = (const int*)d_in[6];

    const int n = NNODES;
    const int E = in_sizes[6] / 2;            // 3,200,000
    const int* row = edge;
    const int* col = edge + E;
    float* out = (float*)d_out;

    void *p_bufA, *p_bufB, *p_bufC, *p_deg, *p_cursor;
    void *p_hidHi, *p_hidLo, *p_w1h, *p_w1l, *p_w2h, *p_w2l;
    cudaGetSymbolAddress(&p_bufA, g_bufA);
    cudaGetSymbolAddress(&p_bufB, g_bufB);
    cudaGetSymbolAddress(&p_bufC, g_bufC);
    cudaGetSymbolAddress(&p_deg, g_deg);
    cudaGetSymbolAddress(&p_cursor, g_cursor);
    cudaGetSymbolAddress(&p_hidHi, g_hidHi);
    cudaGetSymbolAddress(&p_hidLo, g_hidLo);
    cudaGetSymbolAddress(&p_w1h, g_W1Hi);
    cudaGetSymbolAddress(&p_w1l, g_W1Lo);
    cudaGetSymbolAddress(&p_w2h, g_W2Hi);
    cudaGetSymbolAddress(&p_w2l, g_W2Lo);

    // 1. Chebyshev coefficients
    cheb_coeffs_kernel<<<1, 32>>>(temp);

    // 2. Split weights to bf16 hi/lo
    split_kernel<<<(NHID * NFEAT + 255) / 256, 256>>>(W1, (__nv_bfloat16*)p_w1h,
                                                      (__nv_bfloat16*)p_w1l, NHID * NFEAT);
    split_kernel<<<(NOUT * NHID + 255) / 256, 256>>>(W2, (__nv_bfloat16*)p_w2h,
                                                     (__nv_bfloat16*)p_w2l, NOUT * NHID);

    // 3. MLP on mma.sync tensor cores (split-bf16)
    {
        const int smem1 = 65536 + 4 * 128 * 128;   // 131072
        const int smem2 = 65536 + 4 * 64 * 128;    //  98304
        cudaFuncSetAttribute(gemm_mma_kernel<128, NFEAT, NHID, true>,
                             cudaFuncAttributeMaxDynamicSharedMemorySize, smem1);
        cudaFuncSetAttribute(gemm_mma_kernel<64, NHID, NOUT, false>,
                             cudaFuncAttributeMaxDynamicSharedMemorySize, smem2);
        dim3 grid1((n + 127) / 128, NHID / 128);   // 782 x 2
        gemm_mma_kernel<128, NFEAT, NHID, true><<<grid1, 256, smem1>>>(
            feature, nullptr, nullptr,
            (const __nv_bfloat16*)p_w1h, (const __nv_bfloat16*)p_w1l, b1,
            (__nv_bfloat16*)p_hidHi, (__nv_bfloat16*)p_hidLo, nullptr, n);
        dim3 grid2((n + 127) / 128, 1);            // 782 x 1
        gemm_mma_kernel<64, NHID, NOUT, false><<<grid2, 256, smem2>>>(
            nullptr, (const __nv_bfloat16*)p_hidHi, (const __nv_bfloat16*)p_hidLo,
            (const __nv_bfloat16*)p_w2h, (const __nv_bfloat16*)p_w2l, b2,
            nullptr, nullptr, (float*)p_bufA, n);
    }

    // 4. Graph preprocessing -> CSR
    cudaMemsetAsync(p_deg, 0, n * sizeof(int), 0);
    cudaMemsetAsync(p_cursor, 0, n * sizeof(int), 0);
    degree_kernel<<<(E + 255) / 256, 256>>>(row, E);
    dinv_kernel<<<(n + 255) / 256, 256>>>(n);
    scan_kernel<<<1, 1024>>>(n);
    build_csr_kernel<<<(E + 255) / 256, 256>>>(row, col, E);

    // 5. Chebyshev propagation (10 SpMMs), one warp per node
    int pblocks = (n * 32 + 255) / 256;
    float* b0 = (float*)p_bufA;   // Tx0 = x
    float* b1p = (float*)p_bufB;  // Tx1
    float* b2p = (float*)p_bufC;  // Tx2
    prop_first_kernel<<<pblocks, 256>>>(b0, b1p, out, n);
    for (int i = 2; i <= KORD; i++) {
        prop_step_kernel<<<pblocks, 256>>>(b1p, b0, b2p, out, i, n);
        float* t = b0; b0 = b1p; b1p = b2p; b2p = t;
    }

    (void)n_in; (void)out_size;
}

// round 4
// speedup vs baseline: 1.6207x; 1.2002x over previous
#include <cuda_runtime.h>
#include <cuda_bf16.h>
#include <cuda_fp16.h>
#include <math.h>
#include <stdint.h>

// Problem constants (fixed by the dataset)
#define NNODES 100000
#define EHALF  1600000
#define NEDGE  (2*EHALF)     // 3,200,000 symmetrized directed edges
#define NFEAT  512
#define NHID   256
#define NOUT   64
#define KORD   10            // Chebyshev order

// ---------------------------------------------------------------------------
// Scratch (static device globals; allocation APIs are forbidden)
// ---------------------------------------------------------------------------
__device__ float  g_xf[(size_t)NNODES * NOUT];            // x fp32 (GEMM2 out)
__device__ __half g_hA[(size_t)NNODES * NOUT];            // Tx rotating (fp16)
__device__ __half g_hB[(size_t)NNODES * NOUT];
__device__ __half g_hC[(size_t)NNODES * NOUT];
__device__ __nv_bfloat16 g_hidHi[(size_t)NNODES * NHID];  // hidden split-bf16
__device__ __nv_bfloat16 g_hidLo[(size_t)NNODES * NHID];
__device__ __nv_bfloat16 g_W1Hi[(size_t)NHID * NFEAT];    // W1 split [256,512]
__device__ __nv_bfloat16 g_W1Lo[(size_t)NHID * NFEAT];
__device__ __nv_bfloat16 g_W2Hi[(size_t)NOUT * NHID];     // W2 split [64,256]
__device__ __nv_bfloat16 g_W2Lo[(size_t)NOUT * NHID];
__device__ int   g_deg[NNODES];
__device__ float g_dinv[NNODES];
__device__ int   g_rowptr[NNODES + 1];
__device__ int   g_cursor[NNODES];
__device__ int   g_cols[NEDGE];
__device__ float g_norms[NEDGE];
__device__ float g_coe[KORD + 1];

// ---------------------------------------------------------------------------
// Base-target PTX helpers (mma.sync + ldmatrix + cp.async only)
// ---------------------------------------------------------------------------
__device__ __forceinline__ uint32_t smem_u32(const void* p) {
    uint32_t a;
    asm("{ .reg .u64 t; cvta.to.shared.u64 t, %1; cvt.u32.u64 %0, t; }" : "=r"(a) : "l"(p));
    return a;
}

#define LDSM4(R, addr) \
    asm volatile("ldmatrix.sync.aligned.m8n8.x4.shared.b16 {%0,%1,%2,%3}, [%4];" \
        : "=r"((R)[0]), "=r"((R)[1]), "=r"((R)[2]), "=r"((R)[3]) : "r"(addr))

#define MMA16816(C, A, b0, b1) \
    asm volatile("mma.sync.aligned.m16n8k16.row.col.f32.bf16.bf16.f32 " \
        "{%0,%1,%2,%3},{%4,%5,%6,%7},{%8,%9},{%0,%1,%2,%3};" \
        : "+f"((C)[0]), "+f"((C)[1]), "+f"((C)[2]), "+f"((C)[3]) \
        : "r"((A)[0]), "r"((A)[1]), "r"((A)[2]), "r"((A)[3]), "r"(b0), "r"(b1))

#define CP_ASYNC16(dst, src, zfill) \
    asm volatile("cp.async.cg.shared.global [%0], [%1], 16, %2;" \
        :: "r"((uint32_t)(dst)), "l"(src), "r"((uint32_t)(zfill)) : "memory")
#define CP_COMMIT() asm volatile("cp.async.commit_group;" ::: "memory")
#define CP_WAIT0()  asm volatile("cp.async.wait_group 0;" ::: "memory")

__device__ __forceinline__ uint32_t pack_bf2(__nv_bfloat16 a, __nv_bfloat16 b) {
    uint32_t lo = (uint32_t)__bfloat16_as_ushort(a);
    uint32_t hi = (uint32_t)__bfloat16_as_ushort(b);
    return lo | (hi << 16);
}

// ---------------------------------------------------------------------------
// Split fp32 -> (bf16 hi, bf16 lo)
// ---------------------------------------------------------------------------
__global__ void split_kernel(const float* __restrict__ w, __nv_bfloat16* __restrict__ hi,
                             __nv_bfloat16* __restrict__ lo, int n) {
    int i = blockIdx.x * blockDim.x + threadIdx.x;
    if (i >= n) return;
    float x = w[i];
    __nv_bfloat16 h = __float2bfloat16(x);
    hi[i] = h;
    lo[i] = __float2bfloat16(x - __bfloat162float(h));
}

// ---------------------------------------------------------------------------
// Split-bf16 GEMM on mma.sync tensor cores, cp.async pipelined.
//   D[M, NCOL] = A[M, KT] @ B[NCOL, KT]^T + bias   (3-term split, fp32 acc)
// BM=128, BK=64, 8 warps (2 x 4), 2 stages.
// GEMM1 (IS_G1): A fp32 converted in-flight (reg path), B via cp.async;
//   epilogue relu -> bf16 hi/lo pair.
// GEMM2: A hi/lo + B hi/lo all via cp.async; epilogue +bias -> fp32 + fp16.
// ---------------------------------------------------------------------------
template <int BN, int KT, int NCOL, bool IS_G1>
__global__ __launch_bounds__(256)
void gemm_mma_kernel(const float* __restrict__ Af32,
                     const __nv_bfloat16* __restrict__ Ahi,
                     const __nv_bfloat16* __restrict__ Alo,
                     const __nv_bfloat16* __restrict__ Bhi,
                     const __nv_bfloat16* __restrict__ Blo,
                     const float* __restrict__ bias,
                     __nv_bfloat16* __restrict__ outHi,
                     __nv_bfloat16* __restrict__ outLo,
                     float* __restrict__ outF,
                     __half* __restrict__ outH,
                     int nrows) {
    constexpr int WN  = BN / 4;        // 32 or 16
    constexpr int NT  = WN / 8;        // n8 tiles per warp: 4 or 2
    constexpr int NP  = NT / 2;        // n16 ldmatrix pairs: 2 or 1
    constexpr int CH  = KT / 64;       // k chunks
    constexpr int BNB = BN * 128;      // bytes per B half per stage
    constexpr int BIT = BN / 32;       // B fetch iterations

    extern __shared__ char smem[];
    const uint32_t sb = smem_u32(smem);
    const int tid = threadIdx.x, lane = tid & 31, wid = tid >> 5;
    const int warpM = wid >> 2, warpN = wid & 3;
    const int m0 = blockIdx.x * 128, n0 = blockIdx.y * BN;
    const int s = tid & 7, rb = tid >> 3;   // fetch: seg 0..7, row base 0..31

    float cacc[4][NT][4];
#pragma unroll
    for (int mt = 0; mt < 4; mt++)
#pragma unroll
        for (int nt = 0; nt < NT; nt++)
#pragma unroll
            for (int q = 0; q < 4; q++) cacc[mt][nt][q] = 0.0f;

    float af[32];   // GEMM1 A prefetch (fp32 before conversion)

    // Issue cp.async for B (and A when !IS_G1) for chunk c into stage st.
    auto ISSUE = [&](int c, int st) {
        const uint32_t bH = sb + 65536u + (uint32_t)st * 2u * BNB;
        const uint32_t bL = bH + BNB;
#pragma unroll
        for (int it = 0; it < BIT; it++) {
            int r = rb + it * 32;
            uint32_t off = (uint32_t)r * 128u + (uint32_t)((s ^ (r & 7)) << 4);
            const char* srcH = (const char*)(Bhi + (size_t)(n0 + r) * KT + c * 64 + s * 8);
            const char* srcL = (const char*)(Blo + (size_t)(n0 + r) * KT + c * 64 + s * 8);
            CP_ASYNC16(bH + off, srcH, 16);
            CP_ASYNC16(bL + off, srcL, 16);
        }
        if (!IS_G1) {
            const uint32_t aH = sb + (uint32_t)st * 32768u;
            const uint32_t aL = aH + 16384u;
#pragma unroll
            for (int it = 0; it < 4; it++) {
                int r = rb + it * 32;
                int g = m0 + r;
                uint32_t zf = (g < nrows) ? 16u : 0u;
                uint32_t off = (uint32_t)r * 128u + (uint32_t)((s ^ (r & 7)) << 4);
                const char* srcH = (const char*)(Ahi + (size_t)g * KT + c * 64 + s * 8);
                const char* srcL = (const char*)(Alo + (size_t)g * KT + c * 64 + s * 8);
                CP_ASYNC16(aH + off, srcH, zf);
                CP_ASYNC16(aL + off, srcL, zf);
            }
        }
    };

    auto FETCHA = [&](int c) {   // GEMM1 only: fp32 A into registers
        if (!IS_G1) return;
#pragma unroll
        for (int it = 0; it < 4; it++) {
            int g = m0 + rb + it * 32;
            if (g < nrows) {
                const float4* p = (const float4*)(Af32 + (size_t)g * KT + c * 64 + s * 8);
                float4 v0 = p[0], v1 = p[1];
                af[it*8+0]=v0.x; af[it*8+1]=v0.y; af[it*8+2]=v0.z; af[it*8+3]=v0.w;
                af[it*8+4]=v1.x; af[it*8+5]=v1.y; af[it*8+6]=v1.z; af[it*8+7]=v1.w;
            } else {
#pragma unroll
                for (int j = 0; j < 8; j++) af[it*8+j] = 0.0f;
            }
        }
    };

    auto STOREA = [&](int st) {  // GEMM1 only: convert + STS
        if (!IS_G1) return;
        char* aH = smem + st * 32768;
        char* aL = aH + 16384;
#pragma unroll
        for (int it = 0; it < 4; it++) {
            int r = rb + it * 32;
            uint32_t off = (uint32_t)r * 128u + (uint32_t)((s ^ (r & 7)) << 4);
            uint32_t hw[4], lw[4];
#pragma unroll
            for (int p = 0; p < 4; p++) {
                float x0 = af[it*8 + 2*p], x1 = af[it*8 + 2*p + 1];
                __nv_bfloat16 h0 = __float2bfloat16(x0), h1 = __float2bfloat16(x1);
                __nv_bfloat16 l0 = __float2bfloat16(x0 - __bfloat162float(h0));
                __nv_bfloat16 l1 = __float2bfloat16(x1 - __bfloat162float(h1));
                hw[p] = pack_bf2(h0, h1);
                lw[p] = pack_bf2(l0, l1);
            }
            *(uint4*)(aH + off) = make_uint4(hw[0], hw[1], hw[2], hw[3]);
            *(uint4*)(aL + off) = make_uint4(lw[0], lw[1], lw[2], lw[3]);
        }
    };

    auto COMPUTE = [&](int st) {
        const uint32_t aH = sb + st * 32768, aL = aH + 16384;
        const uint32_t bH = sb + 65536 + st * 2 * BNB, bL = bH + BNB;
        const int g = lane >> 3, r = lane & 7;
#pragma unroll
        for (int ks = 0; ks < 4; ks++) {
            uint32_t Ah[4][4], Al[4][4], Bh[NP][4], Bl[NP][4];
#pragma unroll
            for (int mt = 0; mt < 4; mt++) {
                int row = warpM * 64 + mt * 16 + (g & 1) * 8 + r;
                int seg = ks * 2 + (g >> 1);
                uint32_t off = (uint32_t)row * 128u + (uint32_t)((seg ^ (row & 7)) << 4);
                LDSM4(Ah[mt], aH + off);
                LDSM4(Al[mt], aL + off);
            }
#pragma unroll
            for (int pt = 0; pt < NP; pt++) {
                int row = warpN * WN + pt * 16 + (g >> 1) * 8 + r;
                int seg = ks * 2 + (g & 1);
                uint32_t off = (uint32_t)row * 128u + (uint32_t)((seg ^ (row & 7)) << 4);
                LDSM4(Bh[pt], bH + off);
                LDSM4(Bl[pt], bL + off);
            }
#pragma unroll
            for (int mt = 0; mt < 4; mt++)
#pragma unroll
                for (int nt = 0; nt < NT; nt++) {
                    const uint32_t* b = &Bh[nt >> 1][(nt & 1) * 2];
                    MMA16816(cacc[mt][nt], Ah[mt], b[0], b[1]);
                }
#pragma unroll
            for (int mt = 0; mt < 4; mt++)
#pragma unroll
                for (int nt = 0; nt < NT; nt++) {
                    const uint32_t* b = &Bl[nt >> 1][(nt & 1) * 2];
                    MMA16816(cacc[mt][nt], Ah[mt], b[0], b[1]);
                }
#pragma unroll
            for (int mt = 0; mt < 4; mt++)
#pragma unroll
                for (int nt = 0; nt < NT; nt++) {
                    const uint32_t* b = &Bh[nt >> 1][(nt & 1) * 2];
                    MMA16816(cacc[mt][nt], Al[mt], b[0], b[1]);
                }
        }
    };

    // Prologue: fill stage 0
    ISSUE(0, 0);
    CP_COMMIT();
    FETCHA(0);
    STOREA(0);
    CP_WAIT0();
    __syncthreads();

    for (int c = 0; c < CH; c++) {
        if (c + 1 < CH) {
            FETCHA(c + 1);
            ISSUE(c + 1, (c + 1) & 1);
            CP_COMMIT();
        }
        COMPUTE(c & 1);
        if (c + 1 < CH) {
            STOREA((c + 1) & 1);
            CP_WAIT0();
        }
        __syncthreads();
    }

    // ---- epilogue ----
    const int qr = lane >> 2, qc = (lane & 3) * 2;
#pragma unroll
    for (int mt = 0; mt < 4; mt++) {
        int row0 = m0 + warpM * 64 + mt * 16 + qr;
#pragma unroll
        for (int nt = 0; nt < NT; nt++) {
            int col = n0 + warpN * WN + nt * 8 + qc;
            float b0 = __ldg(bias + col), b1 = __ldg(bias + col + 1);
#pragma unroll
            for (int h = 0; h < 2; h++) {
                int row = row0 + h * 8;
                if (row >= nrows) continue;
                float x0 = cacc[mt][nt][h * 2 + 0] + b0;
                float x1 = cacc[mt][nt][h * 2 + 1] + b1;
                if (IS_G1) {
                    x0 = fmaxf(x0, 0.f);
                    x1 = fmaxf(x1, 0.f);
                    __nv_bfloat16 h0 = __float2bfloat16(x0), h1 = __float2bfloat16(x1);
                    __nv_bfloat16 l0 = __float2bfloat16(x0 - __bfloat162float(h0));
                    __nv_bfloat16 l1 = __float2bfloat16(x1 - __bfloat162float(h1));
                    *(uint32_t*)(outHi + (size_t)row * NCOL + col) = pack_bf2(h0, h1);
                    *(uint32_t*)(outLo + (size_t)row * NCOL + col) = pack_bf2(l0, l1);
                } else {
                    *(float2*)(outF + (size_t)row * NCOL + col) = make_float2(x0, x1);
                    *(__half2*)(outH + (size_t)row * NCOL + col) =
                        __floats2half2_rn(x0, x1);
                }
            }
        }
    }
}

// ---------------------------------------------------------------------------
// Chebyshev coefficients
// ---------------------------------------------------------------------------
__global__ void cheb_coeffs_kernel(const float* __restrict__ temp) {
    int i = threadIdx.x;
    if (i > KORD) return;
    const float PI = 3.14159265358979323846f;
    float s = 0.0f;
    for (int j = 0; j <= KORD; j++) {
        float t = fmaxf(temp[j], 0.0f);
        float theta = (KORD - j + 0.5f) * PI / (KORD + 1);
        s += t * cosf((float)i * theta);
    }
    float c = (2.0f / (KORD + 1)) * s;
    if (i == 0) c *= 0.5f;
    g_coe[i] = c;
}

// ---------------------------------------------------------------------------
// Graph preprocessing
// ---------------------------------------------------------------------------
__global__ void degree_kernel(const int* __restrict__ row, int nedge) {
    int e = blockIdx.x * blockDim.x + threadIdx.x;
    if (e >= nedge) return;
    atomicAdd(&g_deg[row[e]], 1);
}

__global__ void dinv_kernel(int n) {
    int i = blockIdx.x * blockDim.x + threadIdx.x;
    if (i >= n) return;
    int d = g_deg[i];
    g_dinv[i] = (d > 0) ? rsqrtf((float)d) : 0.0f;
}

__global__ void scan_kernel(int n) {
    __shared__ int sums[1024];
    int tid = threadIdx.x;
    int chunk = (n + 1023) / 1024;
    int start = tid * chunk;
    int end = min(start + chunk, n);
    int s = 0;
    for (int i = start; i < end; i++) s += g_deg[i];
    sums[tid] = s;
    __syncthreads();
    for (int off = 1; off < 1024; off <<= 1) {
        int v = 0;
        if (tid >= off) v = sums[tid - off];
        __syncthreads();
        if (tid >= off) sums[tid] += v;
        __syncthreads();
    }
    int prefix = (tid == 0) ? 0 : sums[tid - 1];
    for (int i = start; i < end; i++) {
        g_rowptr[i] = prefix;
        prefix += g_deg[i];
    }
    if (tid == 1023) g_rowptr[n] = prefix;
}

__global__ void build_csr_kernel(const int* __restrict__ row, const int* __restrict__ col,
                                 int nedge) {
    int e = blockIdx.x * blockDim.x + threadIdx.x;
    if (e >= nedge) return;
    int r = row[e];
    int c = col[e];
    int pos = g_rowptr[r] + atomicAdd(&g_cursor[r], 1);
    g_cols[pos] = c;
    g_norms[pos] = -g_dinv[r] * g_dinv[c];
}

// ---------------------------------------------------------------------------
// Propagation: CSR SpMM over fp16 state, fp32 math.
// One warp per node; lane owns a __half2 (2 of 64 feats) per neighbor row.
// ---------------------------------------------------------------------------
__device__ __forceinline__ float2 csr_gather_h(const __half* __restrict__ v,
                                               int r, int lane) {
    int beg = g_rowptr[r];
    int end = g_rowptr[r + 1];
    float2 acc = make_float2(0.f, 0.f);
    for (int j = beg; j < end; j += 32) {
        int cnt = min(32, end - j);
        int   myc = 0;
        float myn = 0.f;
        if (lane < cnt) { myc = g_cols[j + lane]; myn = g_norms[j + lane]; }
        for (int t = 0; t < cnt; t++) {
            int   c = __shfl_sync(0xffffffffu, myc, t);
            float w = __shfl_sync(0xffffffffu, myn, t);
            __half2 hv = *(const __half2*)(v + (size_t)c * NOUT + lane * 2);
            float2 f = __half22float2(hv);
            acc.x = fmaf(w, f.x, acc.x);
            acc.y = fmaf(w, f.y, acc.y);
        }
    }
    return acc;
}

// Tx1 = prop(x);  out = coe0h*x + coe1*Tx1   (x fp32 for the coe0 term)
__global__ __launch_bounds__(256)
void prop_first_kernel(const float* __restrict__ xf, const __half* __restrict__ xh,
                       __half* __restrict__ Tx1, float* __restrict__ out, int n) {
    int warp = (blockIdx.x * blockDim.x + threadIdx.x) >> 5;
    int lane = threadIdx.x & 31;
    if (warp >= n) return;
    float2 acc = csr_gather_h(xh, warp, lane);
    size_t idx = (size_t)warp * NOUT + lane * 2;
    float c0 = g_coe[0];   // pre-halved
    float c1 = g_coe[1];
    float2 xv = *(const float2*)&xf[idx];
    *(__half2*)&Tx1[idx] = __floats2half2_rn(acc.x, acc.y);
    float2 o;
    o.x = fmaf(c1, acc.x, c0 * xv.x);
    o.y = fmaf(c1, acc.y, c0 * xv.y);
    *(float2*)&out[idx] = o;
}

// Tx2 = 2*prop(Tx1) - Tx0;  out += coe[ci]*Tx2.  Optionally skip Tx2 store.
__global__ __launch_bounds__(256)
void prop_step_kernel(const __half* __restrict__ Tx1, const __half* __restrict__ Tx0,
                      __half* __restrict__ Tx2, float* __restrict__ out, int ci,
                      int store_tx2, int n) {
    int warp = (blockIdx.x * blockDim.x + threadIdx.x) >> 5;
    int lane = threadIdx.x & 31;
    if (warp >= n) return;
    float2 acc = csr_gather_h(Tx1, warp, lane);
    size_t idx = (size_t)warp * NOUT + lane * 2;
    float2 t0 = __half22float2(*(const __half2*)&Tx0[idx]);
    float2 t2;
    t2.x = 2.0f * acc.x - t0.x;
    t2.y = 2.0f * acc.y - t0.y;
    if (store_tx2)
        *(__half2*)&Tx2[idx] = __floats2half2_rn(t2.x, t2.y);
    float ci_c = g_coe[ci];
    float2 o = *(const float2*)&out[idx];
    o.x = fmaf(ci_c, t2.x, o.x);
    o.y = fmaf(ci_c, t2.y, o.y);
    *(float2*)&out[idx] = o;
}

// ---------------------------------------------------------------------------
// Launch
// ---------------------------------------------------------------------------
extern "C" void kernel_launch(void* const* d_in, const int* in_sizes, int n_in,
                              void* d_out, int out_size) {
    const float* feature = (const float*)d_in[0];
    const float* W1      = (const float*)d_in[1];
    const float* b1      = (const float*)d_in[2];
    const float* W2      = (const float*)d_in[3];
    const float* b2      = (const float*)d_in[4];
    const float* temp    = (const float*)d_in[5];
    const int*   edge    = (const int*)d_in[6];

    const int n = NNODES;
    const int E = in_sizes[6] / 2;            // 3,200,000
    const int* row = edge;
    const int* col = edge + E;
    float* out = (float*)d_out;

    void *p_xf, *p_hA, *p_hB, *p_hC, *p_deg, *p_cursor;
    void *p_hidHi, *p_hidLo, *p_w1h, *p_w1l, *p_w2h, *p_w2l;
    cudaGetSymbolAddress(&p_xf, g_xf);
    cudaGetSymbolAddress(&p_hA, g_hA);
    cudaGetSymbolAddress(&p_hB, g_hB);
    cudaGetSymbolAddress(&p_hC, g_hC);
    cudaGetSymbolAddress(&p_deg, g_deg);
    cudaGetSymbolAddress(&p_cursor, g_cursor);
    cudaGetSymbolAddress(&p_hidHi, g_hidHi);
    cudaGetSymbolAddress(&p_hidLo, g_hidLo);
    cudaGetSymbolAddress(&p_w1h, g_W1Hi);
    cudaGetSymbolAddress(&p_w1l, g_W1Lo);
    cudaGetSymbolAddress(&p_w2h, g_W2Hi);
    cudaGetSymbolAddress(&p_w2l, g_W2Lo);

    // 1. Chebyshev coefficients
    cheb_coeffs_kernel<<<1, 32>>>(temp);

    // 2. Split weights to bf16 hi/lo
    split_kernel<<<(NHID * NFEAT + 255) / 256, 256>>>(W1, (__nv_bfloat16*)p_w1h,
                                                      (__nv_bfloat16*)p_w1l, NHID * NFEAT);
    split_kernel<<<(NOUT * NHID + 255) / 256, 256>>>(W2, (__nv_bfloat16*)p_w2h,
                                                     (__nv_bfloat16*)p_w2l, NOUT * NHID);

    // 3. MLP on mma.sync tensor cores (split-bf16, cp.async pipelined)
    {
        const int smem1 = 65536 + 4 * 128 * 128;   // 131072
        const int smem2 = 65536 + 4 * 64 * 128;    //  98304
        cudaFuncSetAttribute(gemm_mma_kernel<128, NFEAT, NHID, true>,
                             cudaFuncAttributeMaxDynamicSharedMemorySize, smem1);
        cudaFuncSetAttribute(gemm_mma_kernel<64, NHID, NOUT, false>,
                             cudaFuncAttributeMaxDynamicSharedMemorySize, smem2);
        dim3 grid1((n + 127) / 128, NHID / 128);   // 782 x 2
        gemm_mma_kernel<128, NFEAT, NHID, true><<<grid1, 256, smem1>>>(
            feature, nullptr, nullptr,
            (const __nv_bfloat16*)p_w1h, (const __nv_bfloat16*)p_w1l, b1,
            (__nv_bfloat16*)p_hidHi, (__nv_bfloat16*)p_hidLo, nullptr, nullptr, n);
        dim3 grid2((n + 127) / 128, 1);            // 782 x 1
        gemm_mma_kernel<64, NHID, NOUT, false><<<grid2, 256, smem2>>>(
            nullptr, (const __nv_bfloat16*)p_hidHi, (const __nv_bfloat16*)p_hidLo,
            (const __nv_bfloat16*)p_w2h, (const __nv_bfloat16*)p_w2l, b2,
            nullptr, nullptr, (float*)p_xf, (__half*)p_hA, n);
    }

    // 4. Graph preprocessing -> CSR
    cudaMemsetAsync(p_deg, 0, n * sizeof(int), 0);
    cudaMemsetAsync(p_cursor, 0, n * sizeof(int), 0);
    degree_kernel<<<(E + 255) / 256, 256>>>(row, E);
    dinv_kernel<<<(n + 255) / 256, 256>>>(n);
    scan_kernel<<<1, 1024>>>(n);
    build_csr_kernel<<<(E + 255) / 256, 256>>>(row, col, E);

    // 5. Chebyshev propagation (10 SpMMs over fp16 state), one warp per node
    int pblocks = (n * 32 + 255) / 256;
    __half* b0 = (__half*)p_hA;   // Tx0 = x (fp16)
    __half* b1p = (__half*)p_hB;  // Tx1
    __half* b2p = (__half*)p_hC;  // Tx2
    prop_first_kernel<<<pblocks, 256>>>((const float*)p_xf, b0, b1p, out, n);
    for (int i = 2; i <= KORD; i++) {
        prop_step_kernel<<<pblocks, 256>>>(b1p, b0, b2p, out, i,
                                           (i < KORD) ? 1 : 0, n);
        __half* t = b0; b0 = b1p; b1p = b2p; b2p = t;
    }

    (void)n_in; (void)out_size;
}

// round 5
// speedup vs baseline: 1.9797x; 1.2215x over previous
#include <cuda_runtime.h>
#include <cuda_bf16.h>
#include <cuda_fp16.h>
#include <math.h>
#include <stdint.h>

// Problem constants (fixed by the dataset)
#define NNODES 100000
#define EHALF  1600000
#define NEDGE  (2*EHALF)     // 3,200,000 symmetrized directed edges
#define NFEAT  512
#define NHID   256
#define NOUT   64
#define KORD   10            // Chebyshev order

// ---------------------------------------------------------------------------
// Scratch (static device globals; allocation APIs are forbidden)
// ---------------------------------------------------------------------------
__device__ float  g_xf[(size_t)NNODES * NOUT];            // x fp32 (GEMM2 out)
__device__ __half g_hA[(size_t)NNODES * NOUT];            // Tx rotating (fp16)
__device__ __half g_hB[(size_t)NNODES * NOUT];
__device__ __half g_hC[(size_t)NNODES * NOUT];
__device__ __nv_bfloat16 g_hidHi[(size_t)NNODES * NHID];  // hidden split-bf16
__device__ __nv_bfloat16 g_hidLo[(size_t)NNODES * NHID];
__device__ __nv_bfloat16 g_W1Hi[(size_t)NHID * NFEAT];    // W1 split [256,512]
__device__ __nv_bfloat16 g_W1Lo[(size_t)NHID * NFEAT];
__device__ __nv_bfloat16 g_W2Hi[(size_t)NOUT * NHID];     // W2 split [64,256]
__device__ __nv_bfloat16 g_W2Lo[(size_t)NOUT * NHID];
__device__ int   g_deg[NNODES];
__device__ float g_dinv[NNODES];
__device__ int   g_rowptr[NNODES + 1];
__device__ int   g_cursor[NNODES];
__device__ int   g_cols[NEDGE];
__device__ float g_norms[NEDGE];
__device__ float g_coe[KORD + 1];

// ---------------------------------------------------------------------------
// Base-target PTX helpers (mma.sync + ldmatrix + cp.async only)
// ---------------------------------------------------------------------------
__device__ __forceinline__ uint32_t smem_u32(const void* p) {
    uint32_t a;
    asm("{ .reg .u64 t; cvta.to.shared.u64 t, %1; cvt.u32.u64 %0, t; }" : "=r"(a) : "l"(p));
    return a;
}

#define LDSM4(R, addr) \
    asm volatile("ldmatrix.sync.aligned.m8n8.x4.shared.b16 {%0,%1,%2,%3}, [%4];" \
        : "=r"((R)[0]), "=r"((R)[1]), "=r"((R)[2]), "=r"((R)[3]) : "r"(addr))

#define MMA16816(C, A, b0, b1) \
    asm volatile("mma.sync.aligned.m16n8k16.row.col.f32.bf16.bf16.f32 " \
        "{%0,%1,%2,%3},{%4,%5,%6,%7},{%8,%9},{%0,%1,%2,%3};" \
        : "+f"((C)[0]), "+f"((C)[1]), "+f"((C)[2]), "+f"((C)[3]) \
        : "r"((A)[0]), "r"((A)[1]), "r"((A)[2]), "r"((A)[3]), "r"(b0), "r"(b1))

#define CP_ASYNC16(dst, src, zfill) \
    asm volatile("cp.async.cg.shared.global [%0], [%1], 16, %2;" \
        :: "r"((uint32_t)(dst)), "l"(src), "r"((uint32_t)(zfill)) : "memory")
#define CP_COMMIT() asm volatile("cp.async.commit_group;" ::: "memory")
#define CP_WAIT0()  asm volatile("cp.async.wait_group 0;" ::: "memory")
#define CP_WAIT1()  asm volatile("cp.async.wait_group 1;" ::: "memory")

__device__ __forceinline__ uint32_t pack_bf2(__nv_bfloat16 a, __nv_bfloat16 b) {
    uint32_t lo = (uint32_t)__bfloat16_as_ushort(a);
    uint32_t hi = (uint32_t)__bfloat16_as_ushort(b);
    return lo | (hi << 16);
}

// ---------------------------------------------------------------------------
// Split fp32 -> (bf16 hi, bf16 lo)
// ---------------------------------------------------------------------------
__global__ void split_kernel(const float* __restrict__ w, __nv_bfloat16* __restrict__ hi,
                             __nv_bfloat16* __restrict__ lo, int n) {
    int i = blockIdx.x * blockDim.x + threadIdx.x;
    if (i >= n) return;
    float x = w[i];
    __nv_bfloat16 h = __float2bfloat16(x);
    hi[i] = h;
    lo[i] = __float2bfloat16(x - __bfloat162float(h));
}

// ---------------------------------------------------------------------------
// Split-bf16 GEMM on mma.sync tensor cores.
//   D[M, NCOL] = A[M, KT] @ B[NCOL, KT]^T + bias   (3-term split, fp32 acc)
// BM=64, BK=64, 8 warps (2 x 4), A double-stage, B single-stage (64KB smem
// for GEMM1) -> 2 CTAs/SM. Grid: x = n-blocks, y = m-blocks so co-scheduled
// CTAs share A rows in L2.
// GEMM1 (IS_G1): A fp32 converted in-flight (reg path), B via cp.async;
//   epilogue relu -> bf16 hi/lo pair.
// GEMM2: A hi/lo + B hi/lo all via cp.async; epilogue +bias -> fp32 + fp16.
// ---------------------------------------------------------------------------
template <int BN, int KT, int NCOL, bool IS_G1>
__global__ __launch_bounds__(256, 2)
void gemm_mma_kernel(const float* __restrict__ Af32,
                     const __nv_bfloat16* __restrict__ Ahi,
                     const __nv_bfloat16* __restrict__ Alo,
                     const __nv_bfloat16* __restrict__ Bhi,
                     const __nv_bfloat16* __restrict__ Blo,
                     const float* __restrict__ bias,
                     __nv_bfloat16* __restrict__ outHi,
                     __nv_bfloat16* __restrict__ outLo,
                     float* __restrict__ outF,
                     __half* __restrict__ outH,
                     int nrows) {
    constexpr int WN  = BN / 4;        // 32 or 16
    constexpr int NT  = WN / 8;        // n8 tiles per warp: 4 or 2
    constexpr int NP  = NT / 2;        // n16 ldmatrix pairs: 2 or 1
    constexpr int CH  = KT / 64;       // k chunks
    constexpr int BNB = BN * 128;      // bytes per B half
    constexpr int BIT = BN / 32;       // B fetch iterations
    // SMEM: A stage st half h at st*16384 + h*8192 (64 rows x 128B);
    //       B at 32768 (hi), 32768+BNB (lo)
    constexpr uint32_t BOFF = 32768u;

    extern __shared__ char smem[];
    const uint32_t sb = smem_u32(smem);
    const int tid = threadIdx.x, lane = tid & 31, wid = tid >> 5;
    const int warpM = wid >> 2, warpN = wid & 3;
    const int m0 = blockIdx.y * 64, n0 = blockIdx.x * BN;
    const int s = tid & 7, rb = tid >> 3;   // fetch: seg 0..7, row base 0..31

    float cacc[2][NT][4];
#pragma unroll
    for (int mt = 0; mt < 2; mt++)
#pragma unroll
        for (int nt = 0; nt < NT; nt++)
#pragma unroll
            for (int q = 0; q < 4; q++) cacc[mt][nt][q] = 0.0f;

    float af[16];   // GEMM1 A prefetch (fp32), rows {rb, rb+32}, cols s*8..+7

    auto ISSUE_B = [&](int c) {
#pragma unroll
        for (int it = 0; it < BIT; it++) {
            int r = rb + it * 32;
            uint32_t off = (uint32_t)r * 128u + (uint32_t)((s ^ (r & 7)) << 4);
            const char* srcH = (const char*)(Bhi + (size_t)(n0 + r) * KT + c * 64 + s * 8);
            const char* srcL = (const char*)(Blo + (size_t)(n0 + r) * KT + c * 64 + s * 8);
            CP_ASYNC16(sb + BOFF + off, srcH, 16);
            CP_ASYNC16(sb + BOFF + BNB + off, srcL, 16);
        }
    };

    auto ISSUE_A = [&](int c, int st) {   // GEMM2 only
        const uint32_t aH = sb + (uint32_t)st * 16384u;
        const uint32_t aL = aH + 8192u;
#pragma unroll
        for (int it = 0; it < 2; it++) {
            int r = rb + it * 32;
            int g = m0 + r;
            uint32_t zf = (g < nrows) ? 16u : 0u;
            uint32_t off = (uint32_t)r * 128u + (uint32_t)((s ^ (r & 7)) << 4);
            const char* srcH = (const char*)(Ahi + (size_t)g * KT + c * 64 + s * 8);
            const char* srcL = (const char*)(Alo + (size_t)g * KT + c * 64 + s * 8);
            CP_ASYNC16(aH + off, srcH, zf);
            CP_ASYNC16(aL + off, srcL, zf);
        }
    };

    auto FETCHA = [&](int c) {   // GEMM1 only: fp32 A into registers
#pragma unroll
        for (int it = 0; it < 2; it++) {
            int g = m0 + rb + it * 32;
            if (g < nrows) {
                const float4* p = (const float4*)(Af32 + (size_t)g * KT + c * 64 + s * 8);
                float4 v0 = p[0], v1 = p[1];
                af[it*8+0]=v0.x; af[it*8+1]=v0.y; af[it*8+2]=v0.z; af[it*8+3]=v0.w;
                af[it*8+4]=v1.x; af[it*8+5]=v1.y; af[it*8+6]=v1.z; af[it*8+7]=v1.w;
            } else {
#pragma unroll
                for (int j = 0; j < 8; j++) af[it*8+j] = 0.0f;
            }
        }
    };

    auto STOREA = [&](int st) {  // GEMM1 only: convert + STS
        char* aH = smem + st * 16384;
        char* aL = aH + 8192;
#pragma unroll
        for (int it = 0; it < 2; it++) {
            int r = rb + it * 32;
            uint32_t off = (uint32_t)r * 128u + (uint32_t)((s ^ (r & 7)) << 4);
            uint32_t hw[4], lw[4];
#pragma unroll
            for (int p = 0; p < 4; p++) {
                float x0 = af[it*8 + 2*p], x1 = af[it*8 + 2*p + 1];
                __nv_bfloat16 h0 = __float2bfloat16(x0), h1 = __float2bfloat16(x1);
                __nv_bfloat16 l0 = __float2bfloat16(x0 - __bfloat162float(h0));
                __nv_bfloat16 l1 = __float2bfloat16(x1 - __bfloat162float(h1));
                hw[p] = pack_bf2(h0, h1);
                lw[p] = pack_bf2(l0, l1);
            }
            *(uint4*)(aH + off) = make_uint4(hw[0], hw[1], hw[2], hw[3]);
            *(uint4*)(aL + off) = make_uint4(lw[0], lw[1], lw[2], lw[3]);
        }
    };

    auto COMPUTE = [&](int st) {
        const uint32_t aH = sb + st * 16384, aL = aH + 8192;
        const uint32_t bH = sb + BOFF, bL = bH + BNB;
        const int g = lane >> 3, r = lane & 7;
#pragma unroll
        for (int ks = 0; ks < 4; ks++) {
            uint32_t Ah[2][4], Al[2][4], Bh[NP][4], Bl[NP][4];
#pragma unroll
            for (int mt = 0; mt < 2; mt++) {
                int row = warpM * 32 + mt * 16 + (g & 1) * 8 + r;
                int seg = ks * 2 + (g >> 1);
                uint32_t off = (uint32_t)row * 128u + (uint32_t)((seg ^ (row & 7)) << 4);
                LDSM4(Ah[mt], aH + off);
                LDSM4(Al[mt], aL + off);
            }
#pragma unroll
            for (int pt = 0; pt < NP; pt++) {
                int row = warpN * WN + pt * 16 + (g >> 1) * 8 + r;
                int seg = ks * 2 + (g & 1);
                uint32_t off = (uint32_t)row * 128u + (uint32_t)((seg ^ (row & 7)) << 4);
                LDSM4(Bh[pt], bH + off);
                LDSM4(Bl[pt], bL + off);
            }
#pragma unroll
            for (int mt = 0; mt < 2; mt++)
#pragma unroll
                for (int nt = 0; nt < NT; nt++) {
                    const uint32_t* b = &Bh[nt >> 1][(nt & 1) * 2];
                    MMA16816(cacc[mt][nt], Ah[mt], b[0], b[1]);
                }
#pragma unroll
            for (int mt = 0; mt < 2; mt++)
#pragma unroll
                for (int nt = 0; nt < NT; nt++) {
                    const uint32_t* b = &Bl[nt >> 1][(nt & 1) * 2];
                    MMA16816(cacc[mt][nt], Ah[mt], b[0], b[1]);
                }
#pragma unroll
            for (int mt = 0; mt < 2; mt++)
#pragma unroll
                for (int nt = 0; nt < NT; nt++) {
                    const uint32_t* b = &Bh[nt >> 1][(nt & 1) * 2];
                    MMA16816(cacc[mt][nt], Al[mt], b[0], b[1]);
                }
        }
    };

    // Prologue
    if (IS_G1) {
        FETCHA(0);
        STOREA(0);
        ISSUE_B(0);
        CP_COMMIT();
    } else {
        ISSUE_A(0, 0);
        ISSUE_B(0);
        CP_COMMIT();
    }

    for (int c = 0; c < CH; c++) {
        if (IS_G1) {
            if (c + 1 < CH) FETCHA(c + 1);
            CP_WAIT0();
            __syncthreads();
            COMPUTE(c & 1);
            if (c + 1 < CH) STOREA((c + 1) & 1);
            __syncthreads();
            if (c + 1 < CH) { ISSUE_B(c + 1); CP_COMMIT(); }
        } else {
            if (c + 1 < CH) { ISSUE_A(c + 1, (c + 1) & 1); CP_COMMIT(); CP_WAIT1(); }
            else            { CP_WAIT0(); }
            __syncthreads();
            COMPUTE(c & 1);
            __syncthreads();
            if (c + 1 < CH) { ISSUE_B(c + 1); CP_COMMIT(); }
        }
    }

    // ---- epilogue ----
    const int qr = lane >> 2, qc = (lane & 3) * 2;
#pragma unroll
    for (int mt = 0; mt < 2; mt++) {
        int row0 = m0 + warpM * 32 + mt * 16 + qr;
#pragma unroll
        for (int nt = 0; nt < NT; nt++) {
            int col = n0 + warpN * WN + nt * 8 + qc;
            float b0 = __ldg(bias + col), b1 = __ldg(bias + col + 1);
#pragma unroll
            for (int h = 0; h < 2; h++) {
                int row = row0 + h * 8;
                if (row >= nrows) continue;
                float x0 = cacc[mt][nt][h * 2 + 0] + b0;
                float x1 = cacc[mt][nt][h * 2 + 1] + b1;
                if (IS_G1) {
                    x0 = fmaxf(x0, 0.f);
                    x1 = fmaxf(x1, 0.f);
                    __nv_bfloat16 h0 = __float2bfloat16(x0), h1 = __float2bfloat16(x1);
                    __nv_bfloat16 l0 = __float2bfloat16(x0 - __bfloat162float(h0));
                    __nv_bfloat16 l1 = __float2bfloat16(x1 - __bfloat162float(h1));
                    *(uint32_t*)(outHi + (size_t)row * NCOL + col) = pack_bf2(h0, h1);
                    *(uint32_t*)(outLo + (size_t)row * NCOL + col) = pack_bf2(l0, l1);
                } else {
                    *(float2*)(outF + (size_t)row * NCOL + col) = make_float2(x0, x1);
                    *(__half2*)(outH + (size_t)row * NCOL + col) =
                        __floats2half2_rn(x0, x1);
                }
            }
        }
    }
}

// ---------------------------------------------------------------------------
// Chebyshev coefficients
// ---------------------------------------------------------------------------
__global__ void cheb_coeffs_kernel(const float* __restrict__ temp) {
    int i = threadIdx.x;
    if (i > KORD) return;
    const float PI = 3.14159265358979323846f;
    float s = 0.0f;
    for (int j = 0; j <= KORD; j++) {
        float t = fmaxf(temp[j], 0.0f);
        float theta = (KORD - j + 0.5f) * PI / (KORD + 1);
        s += t * cosf((float)i * theta);
    }
    float c = (2.0f / (KORD + 1)) * s;
    if (i == 0) c *= 0.5f;
    g_coe[i] = c;
}

// ---------------------------------------------------------------------------
// Graph preprocessing
// ---------------------------------------------------------------------------
__global__ void degree_kernel(const int* __restrict__ row, int nedge) {
    int e = blockIdx.x * blockDim.x + threadIdx.x;
    if (e >= nedge) return;
    atomicAdd(&g_deg[row[e]], 1);
}

__global__ void dinv_kernel(int n) {
    int i = blockIdx.x * blockDim.x + threadIdx.x;
    if (i >= n) return;
    int d = g_deg[i];
    g_dinv[i] = (d > 0) ? rsqrtf((float)d) : 0.0f;
}

__global__ void scan_kernel(int n) {
    __shared__ int sums[1024];
    int tid = threadIdx.x;
    int chunk = (n + 1023) / 1024;
    int start = tid * chunk;
    int end = min(start + chunk, n);
    int s = 0;
    for (int i = start; i < end; i++) s += g_deg[i];
    sums[tid] = s;
    __syncthreads();
    for (int off = 1; off < 1024; off <<= 1) {
        int v = 0;
        if (tid >= off) v = sums[tid - off];
        __syncthreads();
        if (tid >= off) sums[tid] += v;
        __syncthreads();
    }
    int prefix = (tid == 0) ? 0 : sums[tid - 1];
    for (int i = start; i < end; i++) {
        g_rowptr[i] = prefix;
        prefix += g_deg[i];
    }
    if (tid == 1023) g_rowptr[n] = prefix;
}

__global__ void build_csr_kernel(const int* __restrict__ row, const int* __restrict__ col,
                                 int nedge) {
    int e = blockIdx.x * blockDim.x + threadIdx.x;
    if (e >= nedge) return;
    int r = row[e];
    int c = col[e];
    int pos = g_rowptr[r] + atomicAdd(&g_cursor[r], 1);
    g_cols[pos] = c;
    g_norms[pos] = -g_dinv[r] * g_dinv[c];
}

// ---------------------------------------------------------------------------
// Propagation: CSR SpMM over fp16 state, fp32 math.
// 4 nodes per warp; each 8-lane group handles one node, lane owns 8 feats
// (one uint4 of fp16). Per neighbor: one LDG.128 per group, (c,w) broadcast
// via shfl within the group.
// ---------------------------------------------------------------------------
__device__ __forceinline__ void csr_gather8(const __half* __restrict__ v,
                                            int beg, int end, int lane,
                                            float* __restrict__ acc) {
    const int lane8 = lane & 7;
    const int grpBase = lane & 24;     // (lane>>3)*8
    for (int j = beg; __any_sync(0xffffffffu, j < end); j += 8) {
        int   myc = -1;
        float myn = 0.f;
        int idx = j + lane8;
        if (idx < end && j < end) { myc = g_cols[idx]; myn = g_norms[idx]; }
#pragma unroll
        for (int t = 0; t < 8; t++) {
            int   c = __shfl_sync(0xffffffffu, myc, grpBase + t);
            float w = __shfl_sync(0xffffffffu, myn, grpBase + t);
            if (c >= 0) {
                uint4 hv = *(const uint4*)(v + ((size_t)c << 6) + (lane8 << 3));
                const __half2* hp = (const __half2*)&hv;
                float2 f0 = __half22float2(hp[0]);
                float2 f1 = __half22float2(hp[1]);
                float2 f2 = __half22float2(hp[2]);
                float2 f3 = __half22float2(hp[3]);
                acc[0] = fmaf(w, f0.x, acc[0]);
                acc[1] = fmaf(w, f0.y, acc[1]);
                acc[2] = fmaf(w, f1.x, acc[2]);
                acc[3] = fmaf(w, f1.y, acc[3]);
                acc[4] = fmaf(w, f2.x, acc[4]);
                acc[5] = fmaf(w, f2.y, acc[5]);
                acc[6] = fmaf(w, f3.x, acc[6]);
                acc[7] = fmaf(w, f3.y, acc[7]);
            }
        }
    }
}

__device__ __forceinline__ uint4 pack_h8(const float* a) {
    uint4 r;
    *(__half2*)&r.x = __floats2half2_rn(a[0], a[1]);
    *(__half2*)&r.y = __floats2half2_rn(a[2], a[3]);
    *(__half2*)&r.z = __floats2half2_rn(a[4], a[5]);
    *(__half2*)&r.w = __floats2half2_rn(a[6], a[7]);
    return r;
}

// Tx1 = prop(x);  out = coe0h*x + coe1*Tx1   (x fp32 for the coe0 term)
__global__ __launch_bounds__(256)
void prop_first_kernel(const float* __restrict__ xf, const __half* __restrict__ xh,
                       __half* __restrict__ Tx1, float* __restrict__ out, int n) {
    int gw = (blockIdx.x * blockDim.x + threadIdx.x) >> 5;
    int lane = threadIdx.x & 31;
    int node = gw * 4 + (lane >> 3);
    bool ok = node < n;
    int beg = 0, end = 0;
    if (ok) { beg = g_rowptr[node]; end = g_rowptr[node + 1]; }
    float acc[8] = {0.f, 0.f, 0.f, 0.f, 0.f, 0.f, 0.f, 0.f};
    csr_gather8(xh, beg, end, lane, acc);
    if (!ok) return;
    size_t fb = ((size_t)node << 6) + ((lane & 7) << 3);
    float c0 = g_coe[0];   // pre-halved
    float c1 = g_coe[1];
    *(uint4*)(Tx1 + fb) = pack_h8(acc);
    float4 x0 = *(const float4*)(xf + fb);
    float4 x1 = *(const float4*)(xf + fb + 4);
    float4 o0, o1;
    o0.x = fmaf(c1, acc[0], c0 * x0.x);
    o0.y = fmaf(c1, acc[1], c0 * x0.y);
    o0.z = fmaf(c1, acc[2], c0 * x0.z);
    o0.w = fmaf(c1, acc[3], c0 * x0.w);
    o1.x = fmaf(c1, acc[4], c0 * x1.x);
    o1.y = fmaf(c1, acc[5], c0 * x1.y);
    o1.z = fmaf(c1, acc[6], c0 * x1.z);
    o1.w = fmaf(c1, acc[7], c0 * x1.w);
    *(float4*)(out + fb) = o0;
    *(float4*)(out + fb + 4) = o1;
}

// Tx2 = 2*prop(Tx1) - Tx0;  out += coe[ci]*Tx2.  Optionally skip Tx2 store.
__global__ __launch_bounds__(256)
void prop_step_kernel(const __half* __restrict__ Tx1, const __half* __restrict__ Tx0,
                      __half* __restrict__ Tx2, float* __restrict__ out, int ci,
                      int store_tx2, int n) {
    int gw = (blockIdx.x * blockDim.x + threadIdx.x) >> 5;
    int lane = threadIdx.x & 31;
    int node = gw * 4 + (lane >> 3);
    bool ok = node < n;
    int beg = 0, end = 0;
    if (ok) { beg = g_rowptr[node]; end = g_rowptr[node + 1]; }
    float acc[8] = {0.f, 0.f, 0.f, 0.f, 0.f, 0.f, 0.f, 0.f};
    csr_gather8(Tx1, beg, end, lane, acc);
    if (!ok) return;
    size_t fb = ((size_t)node << 6) + ((lane & 7) << 3);
    uint4 t0v = *(const uint4*)(Tx0 + fb);
    const __half2* t0p = (const __half2*)&t0v;
    float t2[8];
    {
        float2 a = __half22float2(t0p[0]), b = __half22float2(t0p[1]);
        float2 c = __half22float2(t0p[2]), d = __half22float2(t0p[3]);
        t2[0] = 2.f * acc[0] - a.x;  t2[1] = 2.f * acc[1] - a.y;
        t2[2] = 2.f * acc[2] - b.x;  t2[3] = 2.f * acc[3] - b.y;
        t2[4] = 2.f * acc[4] - c.x;  t2[5] = 2.f * acc[5] - c.y;
        t2[6] = 2.f * acc[6] - d.x;  t2[7] = 2.f * acc[7] - d.y;
    }
    if (store_tx2)
        *(uint4*)(Tx2 + fb) = pack_h8(t2);
    float cc = g_coe[ci];
    float4 o0 = *(const float4*)(out + fb);
    float4 o1 = *(const float4*)(out + fb + 4);
    o0.x = fmaf(cc, t2[0], o0.x);
    o0.y = fmaf(cc, t2[1], o0.y);
    o0.z = fmaf(cc, t2[2], o0.z);
    o0.w = fmaf(cc, t2[3], o0.w);
    o1.x = fmaf(cc, t2[4], o1.x);
    o1.y = fmaf(cc, t2[5], o1.y);
    o1.z = fmaf(cc, t2[6], o1.z);
    o1.w = fmaf(cc, t2[7], o1.w);
    *(float4*)(out + fb) = o0;
    *(float4*)(out + fb + 4) = o1;
}

// ---------------------------------------------------------------------------
// Launch
// ---------------------------------------------------------------------------
extern "C" void kernel_launch(void* const* d_in, const int* in_sizes, int n_in,
                              void* d_out, int out_size) {
    const float* feature = (const float*)d_in[0];
    const float* W1      = (const float*)d_in[1];
    const float* b1      = (const float*)d_in[2];
    const float* W2      = (const float*)d_in[3];
    const float* b2      = (const float*)d_in[4];
    const float* temp    = (const float*)d_in[5];
    const int*   edge    = (const int*)d_in[6];

    const int n = NNODES;
    const int E = in_sizes[6] / 2;            // 3,200,000
    const int* row = edge;
    const int* col = edge + E;
    float* out = (float*)d_out;

    void *p_xf, *p_hA, *p_hB, *p_hC, *p_deg, *p_cursor;
    void *p_hidHi, *p_hidLo, *p_w1h, *p_w1l, *p_w2h, *p_w2l;
    cudaGetSymbolAddress(&p_xf, g_xf);
    cudaGetSymbolAddress(&p_hA, g_hA);
    cudaGetSymbolAddress(&p_hB, g_hB);
    cudaGetSymbolAddress(&p_hC, g_hC);
    cudaGetSymbolAddress(&p_deg, g_deg);
    cudaGetSymbolAddress(&p_cursor, g_cursor);
    cudaGetSymbolAddress(&p_hidHi, g_hidHi);
    cudaGetSymbolAddress(&p_hidLo, g_hidLo);
    cudaGetSymbolAddress(&p_w1h, g_W1Hi);
    cudaGetSymbolAddress(&p_w1l, g_W1Lo);
    cudaGetSymbolAddress(&p_w2h, g_W2Hi);
    cudaGetSymbolAddress(&p_w2l, g_W2Lo);

    // 1. Chebyshev coefficients
    cheb_coeffs_kernel<<<1, 32>>>(temp);

    // 2. Split weights to bf16 hi/lo
    split_kernel<<<(NHID * NFEAT + 255) / 256, 256>>>(W1, (__nv_bfloat16*)p_w1h,
                                                      (__nv_bfloat16*)p_w1l, NHID * NFEAT);
    split_kernel<<<(NOUT * NHID + 255) / 256, 256>>>(W2, (__nv_bfloat16*)p_w2h,
                                                     (__nv_bfloat16*)p_w2l, NOUT * NHID);

    // 3. MLP on mma.sync tensor cores (split-bf16), 2 CTAs/SM
    {
        const int mblocks = (n + 63) / 64;         // 1563
        const int smem1 = 32768 + 2 * 128 * 128;   // 65536
        const int smem2 = 32768 + 2 * 64 * 128;    // 49152
        cudaFuncSetAttribute(gemm_mma_kernel<128, NFEAT, NHID, true>,
                             cudaFuncAttributeMaxDynamicSharedMemorySize, smem1);
        cudaFuncSetAttribute(gemm_mma_kernel<64, NHID, NOUT, false>,
                             cudaFuncAttributeMaxDynamicSharedMemorySize, smem2);
        dim3 grid1(NHID / 128, mblocks);           // x = n-blocks (L2 A reuse)
        gemm_mma_kernel<128, NFEAT, NHID, true><<<grid1, 256, smem1>>>(
            feature, nullptr, nullptr,
            (const __nv_bfloat16*)p_w1h, (const __nv_bfloat16*)p_w1l, b1,
            (__nv_bfloat16*)p_hidHi, (__nv_bfloat16*)p_hidLo, nullptr, nullptr, n);
        dim3 grid2(1, mblocks);
        gemm_mma_kernel<64, NHID, NOUT, false><<<grid2, 256, smem2>>>(
            nullptr, (const __nv_bfloat16*)p_hidHi, (const __nv_bfloat16*)p_hidLo,
            (const __nv_bfloat16*)p_w2h, (const __nv_bfloat16*)p_w2l, b2,
            nullptr, nullptr, (float*)p_xf, (__half*)p_hA, n);
    }

    // 4. Graph preprocessing -> CSR
    cudaMemsetAsync(p_deg, 0, n * sizeof(int), 0);
    cudaMemsetAsync(p_cursor, 0, n * sizeof(int), 0);
    degree_kernel<<<(E + 255) / 256, 256>>>(row, E);
    dinv_kernel<<<(n + 255) / 256, 256>>>(n);
    scan_kernel<<<1, 1024>>>(n);
    build_csr_kernel<<<(E + 255) / 256, 256>>>(row, col, E);

    // 5. Chebyshev propagation (10 SpMMs over fp16 state), 4 nodes/warp
    int nwarps = (n + 3) / 4;                      // 25000
    int pblocks = (nwarps + 7) / 8;                // 3125
    __half* b0 = (__half*)p_hA;   // Tx0 = x (fp16)
    __half* b1p = (__half*)p_hB;  // Tx1
    __half* b2p = (__half*)p_hC;  // Tx2
    prop_first_kernel<<<pblocks, 256>>>((const float*)p_xf, b0, b1p, out, n);
    for (int i = 2; i <= KORD; i++) {
        prop_step_kernel<<<pblocks, 256>>>(b1p, b0, b2p, out, i,
                                           (i < KORD) ? 1 : 0, n);
        __half* t = b0; b0 = b1p; b1p = b2p; b2p = t;
    }

    (void)n_in; (void)out_size;
}

// round 6
// speedup vs baseline: 2.0838x; 1.0526x over previous
#include <cuda_runtime.h>
#include <cuda_bf16.h>
#include <cuda_fp16.h>
#include <math.h>
#include <stdint.h>

// Problem constants (fixed by the dataset)
#define NNODES 100000
#define EHALF  1600000
#define NEDGE  (2*EHALF)     // 3,200,000 symmetrized directed edges
#define NFEAT  512
#define NHID   256
#define NOUT   64
#define KORD   10            // Chebyshev order
#define SZNO   ((size_t)NNODES * NOUT)

// ---------------------------------------------------------------------------
// Scratch (static device globals; allocation APIs are forbidden)
// ---------------------------------------------------------------------------
__device__ float  g_xf[SZNO];                 // x fp32 (GEMM2 out)
__device__ __half g_hx[SZNO];                 // x fp16
__device__ __half g_hT[(size_t)KORD * SZNO];  // Tx1..Tx10 (fp16), 128MB
__device__ __nv_bfloat16 g_hidHi[(size_t)NNODES * NHID];  // hidden split-bf16
__device__ __nv_bfloat16 g_hidLo[(size_t)NNODES * NHID];
__device__ __nv_bfloat16 g_W1Hi[(size_t)NHID * NFEAT];
__device__ __nv_bfloat16 g_W1Lo[(size_t)NHID * NFEAT];
__device__ __nv_bfloat16 g_W2Hi[(size_t)NOUT * NHID];
__device__ __nv_bfloat16 g_W2Lo[(size_t)NOUT * NHID];
__device__ int   g_deg[NNODES];
__device__ float g_dinv[NNODES];
__device__ int   g_rowptr[NNODES + 1];
__device__ int   g_cursor[NNODES];
__device__ int2  g_cn[NEDGE];                 // packed (col, norm-as-int)
__device__ float g_coe[KORD + 1];

// ---------------------------------------------------------------------------
// Base-target PTX helpers (mma.sync + ldmatrix + cp.async only)
// ---------------------------------------------------------------------------
__device__ __forceinline__ uint32_t smem_u32(const void* p) {
    uint32_t a;
    asm("{ .reg .u64 t; cvta.to.shared.u64 t, %1; cvt.u32.u64 %0, t; }" : "=r"(a) : "l"(p));
    return a;
}

#define LDSM4(R, addr) \
    asm volatile("ldmatrix.sync.aligned.m8n8.x4.shared.b16 {%0,%1,%2,%3}, [%4];" \
        : "=r"((R)[0]), "=r"((R)[1]), "=r"((R)[2]), "=r"((R)[3]) : "r"(addr))

#define MMA16816(C, A, b0, b1) \
    asm volatile("mma.sync.aligned.m16n8k16.row.col.f32.bf16.bf16.f32 " \
        "{%0,%1,%2,%3},{%4,%5,%6,%7},{%8,%9},{%0,%1,%2,%3};" \
        : "+f"((C)[0]), "+f"((C)[1]), "+f"((C)[2]), "+f"((C)[3]) \
        : "r"((A)[0]), "r"((A)[1]), "r"((A)[2]), "r"((A)[3]), "r"(b0), "r"(b1))

#define CP_ASYNC16(dst, src, zfill) \
    asm volatile("cp.async.cg.shared.global [%0], [%1], 16, %2;" \
        :: "r"((uint32_t)(dst)), "l"(src), "r"((uint32_t)(zfill)) : "memory")
#define CP_COMMIT() asm volatile("cp.async.commit_group;" ::: "memory")
#define CP_WAIT0()  asm volatile("cp.async.wait_group 0;" ::: "memory")
#define CP_WAIT1()  asm volatile("cp.async.wait_group 1;" ::: "memory")

__device__ __forceinline__ uint32_t pack_bf2(__nv_bfloat16 a, __nv_bfloat16 b) {
    uint32_t lo = (uint32_t)__bfloat16_as_ushort(a);
    uint32_t hi = (uint32_t)__bfloat16_as_ushort(b);
    return lo | (hi << 16);
}

// ---------------------------------------------------------------------------
// Split fp32 -> (bf16 hi, bf16 lo)
// ---------------------------------------------------------------------------
__global__ void split_kernel(const float* __restrict__ w, __nv_bfloat16* __restrict__ hi,
                             __nv_bfloat16* __restrict__ lo, int n) {
    int i = blockIdx.x * blockDim.x + threadIdx.x;
    if (i >= n) return;
    float x = w[i];
    __nv_bfloat16 h = __float2bfloat16(x);
    hi[i] = h;
    lo[i] = __float2bfloat16(x - __bfloat162float(h));
}

// ---------------------------------------------------------------------------
// Split-bf16 GEMM on mma.sync tensor cores.
//   D[M, NCOL] = A[M, KT] @ B[NCOL, KT]^T + bias   (3-term split, fp32 acc)
// BM=64, BK=64, 8 warps (2 x 4). A and B both double-staged -> every COMPUTE
// has its operands resident; 2 CTAs/SM (96KB smem GEMM1, 64KB GEMM2).
// GEMM1 (IS_G1): A fp32 converted in-flight (reg path), B via cp.async;
//   epilogue relu -> bf16 hi/lo pair.
// GEMM2: A hi/lo + B hi/lo all via cp.async; epilogue +bias -> fp32 + fp16.
// ---------------------------------------------------------------------------
template <int BN, int KT, int NCOL, bool IS_G1>
__global__ __launch_bounds__(256, 2)
void gemm_mma_kernel(const float* __restrict__ Af32,
                     const __nv_bfloat16* __restrict__ Ahi,
                     const __nv_bfloat16* __restrict__ Alo,
                     const __nv_bfloat16* __restrict__ Bhi,
                     const __nv_bfloat16* __restrict__ Blo,
                     const float* __restrict__ bias,
                     __nv_bfloat16* __restrict__ outHi,
                     __nv_bfloat16* __restrict__ outLo,
                     float* __restrict__ outF,
                     __half* __restrict__ outH,
                     int nrows) {
    constexpr int WN  = BN / 4;        // 32 or 16
    constexpr int NT  = WN / 8;        // n8 tiles per warp: 4 or 2
    constexpr int NP  = NT / 2;        // n16 ldmatrix pairs: 2 or 1
    constexpr int CH  = KT / 64;       // k chunks
    constexpr int BNB = BN * 128;      // bytes per B half per stage
    constexpr int BIT = BN / 32;       // B fetch iterations
    constexpr uint32_t BOFF = 32768u;  // A: 2 stages x (8KB hi + 8KB lo)

    extern __shared__ char smem[];
    const uint32_t sb = smem_u32(smem);
    const int tid = threadIdx.x, lane = tid & 31, wid = tid >> 5;
    const int warpM = wid >> 2, warpN = wid & 3;
    const int m0 = blockIdx.y * 64, n0 = blockIdx.x * BN;
    const int s = tid & 7, rb = tid >> 3;   // fetch: seg 0..7, row base 0..31

    float cacc[2][NT][4];
#pragma unroll
    for (int mt = 0; mt < 2; mt++)
#pragma unroll
        for (int nt = 0; nt < NT; nt++)
#pragma unroll
            for (int q = 0; q < 4; q++) cacc[mt][nt][q] = 0.0f;

    float af[16];   // GEMM1 A prefetch (fp32), rows {rb, rb+32}, cols s*8..+7

    auto ISSUE_B = [&](int c, int st) {
        const uint32_t bH = sb + BOFF + (uint32_t)st * 2u * BNB;
        const uint32_t bL = bH + BNB;
#pragma unroll
        for (int it = 0; it < BIT; it++) {
            int r = rb + it * 32;
            uint32_t off = (uint32_t)r * 128u + (uint32_t)((s ^ (r & 7)) << 4);
            const char* srcH = (const char*)(Bhi + (size_t)(n0 + r) * KT + c * 64 + s * 8);
            const char* srcL = (const char*)(Blo + (size_t)(n0 + r) * KT + c * 64 + s * 8);
            CP_ASYNC16(bH + off, srcH, 16);
            CP_ASYNC16(bL + off, srcL, 16);
        }
    };

    auto ISSUE_A = [&](int c, int st) {   // GEMM2 only
        const uint32_t aH = sb + (uint32_t)st * 16384u;
        const uint32_t aL = aH + 8192u;
#pragma unroll
        for (int it = 0; it < 2; it++) {
            int r = rb + it * 32;
            int g = m0 + r;
            uint32_t zf = (g < nrows) ? 16u : 0u;
            uint32_t off = (uint32_t)r * 128u + (uint32_t)((s ^ (r & 7)) << 4);
            const char* srcH = (const char*)(Ahi + (size_t)g * KT + c * 64 + s * 8);
            const char* srcL = (const char*)(Alo + (size_t)g * KT + c * 64 + s * 8);
            CP_ASYNC16(aH + off, srcH, zf);
            CP_ASYNC16(aL + off, srcL, zf);
        }
    };

    auto FETCHA = [&](int c) {   // GEMM1 only: fp32 A into registers
#pragma unroll
        for (int it = 0; it < 2; it++) {
            int g = m0 + rb + it * 32;
            if (g < nrows) {
                const float4* p = (const float4*)(Af32 + (size_t)g * KT + c * 64 + s * 8);
                float4 v0 = p[0], v1 = p[1];
                af[it*8+0]=v0.x; af[it*8+1]=v0.y; af[it*8+2]=v0.z; af[it*8+3]=v0.w;
                af[it*8+4]=v1.x; af[it*8+5]=v1.y; af[it*8+6]=v1.z; af[it*8+7]=v1.w;
            } else {
#pragma unroll
                for (int j = 0; j < 8; j++) af[it*8+j] = 0.0f;
            }
        }
    };

    auto STOREA = [&](int st) {  // GEMM1 only: convert + STS
        char* aH = smem + st * 16384;
        char* aL = aH + 8192;
#pragma unroll
        for (int it = 0; it < 2; it++) {
            int r = rb + it * 32;
            uint32_t off = (uint32_t)r * 128u + (uint32_t)((s ^ (r & 7)) << 4);
            uint32_t hw[4], lw[4];
#pragma unroll
            for (int p = 0; p < 4; p++) {
                float x0 = af[it*8 + 2*p], x1 = af[it*8 + 2*p + 1];
                __nv_bfloat16 h0 = __float2bfloat16(x0), h1 = __float2bfloat16(x1);
                __nv_bfloat16 l0 = __float2bfloat16(x0 - __bfloat162float(h0));
                __nv_bfloat16 l1 = __float2bfloat16(x1 - __bfloat162float(h1));
                hw[p] = pack_bf2(h0, h1);
                lw[p] = pack_bf2(l0, l1);
            }
            *(uint4*)(aH + off) = make_uint4(hw[0], hw[1], hw[2], hw[3]);
            *(uint4*)(aL + off) = make_uint4(lw[0], lw[1], lw[2], lw[3]);
        }
    };

    auto COMPUTE = [&](int st) {
        const uint32_t aH = sb + st * 16384, aL = aH + 8192;
        const uint32_t bH = sb + BOFF + (uint32_t)st * 2u * BNB, bL = bH + BNB;
        const int g = lane >> 3, r = lane & 7;
#pragma unroll
        for (int ks = 0; ks < 4; ks++) {
            uint32_t Ah[2][4], Al[2][4], Bh[NP][4], Bl[NP][4];
#pragma unroll
            for (int mt = 0; mt < 2; mt++) {
                int row = warpM * 32 + mt * 16 + (g & 1) * 8 + r;
                int seg = ks * 2 + (g >> 1);
                uint32_t off = (uint32_t)row * 128u + (uint32_t)((seg ^ (row & 7)) << 4);
                LDSM4(Ah[mt], aH + off);
                LDSM4(Al[mt], aL + off);
            }
#pragma unroll
            for (int pt = 0; pt < NP; pt++) {
                int row = warpN * WN + pt * 16 + (g >> 1) * 8 + r;
                int seg = ks * 2 + (g & 1);
                uint32_t off = (uint32_t)row * 128u + (uint32_t)((seg ^ (row & 7)) << 4);
                LDSM4(Bh[pt], bH + off);
                LDSM4(Bl[pt], bL + off);
            }
#pragma unroll
            for (int mt = 0; mt < 2; mt++)
#pragma unroll
                for (int nt = 0; nt < NT; nt++) {
                    const uint32_t* b = &Bh[nt >> 1][(nt & 1) * 2];
                    MMA16816(cacc[mt][nt], Ah[mt], b[0], b[1]);
                }
#pragma unroll
            for (int mt = 0; mt < 2; mt++)
#pragma unroll
                for (int nt = 0; nt < NT; nt++) {
                    const uint32_t* b = &Bl[nt >> 1][(nt & 1) * 2];
                    MMA16816(cacc[mt][nt], Ah[mt], b[0], b[1]);
                }
#pragma unroll
            for (int mt = 0; mt < 2; mt++)
#pragma unroll
                for (int nt = 0; nt < NT; nt++) {
                    const uint32_t* b = &Bh[nt >> 1][(nt & 1) * 2];
                    MMA16816(cacc[mt][nt], Al[mt], b[0], b[1]);
                }
        }
    };

    // Prologue: fill both stages
    if (IS_G1) {
        FETCHA(0); STOREA(0);
        ISSUE_B(0, 0); CP_COMMIT();
        ISSUE_B(1, 1); CP_COMMIT();
        FETCHA(1);
    } else {
        ISSUE_A(0, 0); ISSUE_B(0, 0); CP_COMMIT();
        ISSUE_A(1, 1); ISSUE_B(1, 1); CP_COMMIT();
    }

    for (int c = 0; c < CH; c++) {
        if (c + 1 < CH) { CP_WAIT1(); } else { CP_WAIT0(); }
        __syncthreads();
        COMPUTE(c & 1);
        if (IS_G1 && c + 1 < CH) STOREA((c + 1) & 1);
        __syncthreads();
        if (c + 2 < CH) {
            if (IS_G1) {
                ISSUE_B(c + 2, c & 1); CP_COMMIT();
                FETCHA(c + 2);
            } else {
                ISSUE_A(c + 2, c & 1); ISSUE_B(c + 2, c & 1); CP_COMMIT();
            }
        }
    }

    // ---- epilogue ----
    const int qr = lane >> 2, qc = (lane & 3) * 2;
#pragma unroll
    for (int mt = 0; mt < 2; mt++) {
        int row0 = m0 + warpM * 32 + mt * 16 + qr;
#pragma unroll
        for (int nt = 0; nt < NT; nt++) {
            int col = n0 + warpN * WN + nt * 8 + qc;
            float b0 = __ldg(bias + col), b1 = __ldg(bias + col + 1);
#pragma unroll
            for (int h = 0; h < 2; h++) {
                int row = row0 + h * 8;
                if (row >= nrows) continue;
                float x0 = cacc[mt][nt][h * 2 + 0] + b0;
                float x1 = cacc[mt][nt][h * 2 + 1] + b1;
                if (IS_G1) {
                    x0 = fmaxf(x0, 0.f);
                    x1 = fmaxf(x1, 0.f);
                    __nv_bfloat16 h0 = __float2bfloat16(x0), h1 = __float2bfloat16(x1);
                    __nv_bfloat16 l0 = __float2bfloat16(x0 - __bfloat162float(h0));
                    __nv_bfloat16 l1 = __float2bfloat16(x1 - __bfloat162float(h1));
                    *(uint32_t*)(outHi + (size_t)row * NCOL + col) = pack_bf2(h0, h1);
                    *(uint32_t*)(outLo + (size_t)row * NCOL + col) = pack_bf2(l0, l1);
                } else {
                    *(float2*)(outF + (size_t)row * NCOL + col) = make_float2(x0, x1);
                    *(__half2*)(outH + (size_t)row * NCOL + col) =
                        __floats2half2_rn(x0, x1);
                }
            }
        }
    }
}

// ---------------------------------------------------------------------------
// Chebyshev coefficients
// ---------------------------------------------------------------------------
__global__ void cheb_coeffs_kernel(const float* __restrict__ temp) {
    int i = threadIdx.x;
    if (i > KORD) return;
    const float PI = 3.14159265358979323846f;
    float s = 0.0f;
    for (int j = 0; j <= KORD; j++) {
        float t = fmaxf(temp[j], 0.0f);
        float theta = (KORD - j + 0.5f) * PI / (KORD + 1);
        s += t * cosf((float)i * theta);
    }
    float c = (2.0f / (KORD + 1)) * s;
    if (i == 0) c *= 0.5f;
    g_coe[i] = c;
}

// ---------------------------------------------------------------------------
// Graph preprocessing
// ---------------------------------------------------------------------------
__global__ void degree_kernel(const int* __restrict__ row, int nedge) {
    int e = blockIdx.x * blockDim.x + threadIdx.x;
    if (e >= nedge) return;
    atomicAdd(&g_deg[row[e]], 1);
}

__global__ void dinv_kernel(int n) {
    int i = blockIdx.x * blockDim.x + threadIdx.x;
    if (i >= n) return;
    int d = g_deg[i];
    g_dinv[i] = (d > 0) ? rsqrtf((float)d) : 0.0f;
}

__global__ void scan_kernel(int n) {
    __shared__ int sums[1024];
    int tid = threadIdx.x;
    int chunk = (n + 1023) / 1024;
    int start = tid * chunk;
    int end = min(start + chunk, n);
    int s = 0;
    for (int i = start; i < end; i++) s += g_deg[i];
    sums[tid] = s;
    __syncthreads();
    for (int off = 1; off < 1024; off <<= 1) {
        int v = 0;
        if (tid >= off) v = sums[tid - off];
        __syncthreads();
        if (tid >= off) sums[tid] += v;
        __syncthreads();
    }
    int prefix = (tid == 0) ? 0 : sums[tid - 1];
    for (int i = start; i < end; i++) {
        g_rowptr[i] = prefix;
        prefix += g_deg[i];
    }
    if (tid == 1023) g_rowptr[n] = prefix;
}

__global__ void build_csr_kernel(const int* __restrict__ row, const int* __restrict__ col,
                                 int nedge) {
    int e = blockIdx.x * blockDim.x + threadIdx.x;
    if (e >= nedge) return;
    int r = row[e];
    int c = col[e];
    int pos = g_rowptr[r] + atomicAdd(&g_cursor[r], 1);
    float w = -g_dinv[r] * g_dinv[c];
    g_cn[pos] = make_int2(c, __float_as_int(w));
}

// ---------------------------------------------------------------------------
// Propagation: CSR SpMM over fp16 state, fp32 math, no out accumulation
// (deferred to combine_kernel). 4 nodes/warp, 8 lanes/node, lane owns 8 feats.
// ---------------------------------------------------------------------------
__device__ __forceinline__ void csr_gather8(const __half* __restrict__ v,
                                            int beg, int end, int lane,
                                            float* __restrict__ acc) {
    const int lane8 = lane & 7;
    const int grpBase = lane & 24;     // (lane>>3)*8
    for (int j = beg; __any_sync(0xffffffffu, j < end); j += 8) {
        int   myc = -1;
        float myn = 0.f;
        int idx = j + lane8;
        if (idx < end && j < end) {
            int2 cw = g_cn[idx];
            myc = cw.x;
            myn = __int_as_float(cw.y);
        }
#pragma unroll
        for (int t = 0; t < 8; t++) {
            int   c = __shfl_sync(0xffffffffu, myc, grpBase + t);
            float w = __shfl_sync(0xffffffffu, myn, grpBase + t);
            if (c >= 0) {
                uint4 hv = *(const uint4*)(v + ((size_t)c << 6) + (lane8 << 3));
                const __half2* hp = (const __half2*)&hv;
                float2 f0 = __half22float2(hp[0]);
                float2 f1 = __half22float2(hp[1]);
                float2 f2 = __half22float2(hp[2]);
                float2 f3 = __half22float2(hp[3]);
                acc[0] = fmaf(w, f0.x, acc[0]);
                acc[1] = fmaf(w, f0.y, acc[1]);
                acc[2] = fmaf(w, f1.x, acc[2]);
                acc[3] = fmaf(w, f1.y, acc[3]);
                acc[4] = fmaf(w, f2.x, acc[4]);
                acc[5] = fmaf(w, f2.y, acc[5]);
                acc[6] = fmaf(w, f3.x, acc[6]);
                acc[7] = fmaf(w, f3.y, acc[7]);
            }
        }
    }
}

__device__ __forceinline__ uint4 pack_h8(const float* a) {
    uint4 r;
    *(__half2*)&r.x = __floats2half2_rn(a[0], a[1]);
    *(__half2*)&r.y = __floats2half2_rn(a[2], a[3]);
    *(__half2*)&r.z = __floats2half2_rn(a[4], a[5]);
    *(__half2*)&r.w = __floats2half2_rn(a[6], a[7]);
    return r;
}

// Tx1 = prop(x)
__global__ __launch_bounds__(256)
void prop_first_kernel(const __half* __restrict__ xh, __half* __restrict__ Tx1, int n) {
    int gw = (blockIdx.x * blockDim.x + threadIdx.x) >> 5;
    int lane = threadIdx.x & 31;
    int node = gw * 4 + (lane >> 3);
    bool ok = node < n;
    int beg = 0, end = 0;
    if (ok) { beg = g_rowptr[node]; end = g_rowptr[node + 1]; }
    float acc[8] = {0.f, 0.f, 0.f, 0.f, 0.f, 0.f, 0.f, 0.f};
    csr_gather8(xh, beg, end, lane, acc);
    if (!ok) return;
    size_t fb = ((size_t)node << 6) + ((lane & 7) << 3);
    *(uint4*)(Tx1 + fb) = pack_h8(acc);
}

// Tx2 = 2*prop(Tx1) - Tx0
__global__ __launch_bounds__(256)
void prop_step_kernel(const __half* __restrict__ Tx1, const __half* __restrict__ Tx0,
                      __half* __restrict__ Tx2, int n) {
    int gw = (blockIdx.x * blockDim.x + threadIdx.x) >> 5;
    int lane = threadIdx.x & 31;
    int node = gw * 4 + (lane >> 3);
    bool ok = node < n;
    int beg = 0, end = 0;
    if (ok) { beg = g_rowptr[node]; end = g_rowptr[node + 1]; }
    float acc[8] = {0.f, 0.f, 0.f, 0.f, 0.f, 0.f, 0.f, 0.f};
    csr_gather8(Tx1, beg, end, lane, acc);
    if (!ok) return;
    size_t fb = ((size_t)node << 6) + ((lane & 7) << 3);
    uint4 t0v = *(const uint4*)(Tx0 + fb);
    const __half2* t0p = (const __half2*)&t0v;
    float t2[8];
    {
        float2 a = __half22float2(t0p[0]), b = __half22float2(t0p[1]);
        float2 c = __half22float2(t0p[2]), d = __half22float2(t0p[3]);
        t2[0] = 2.f * acc[0] - a.x;  t2[1] = 2.f * acc[1] - a.y;
        t2[2] = 2.f * acc[2] - b.x;  t2[3] = 2.f * acc[3] - b.y;
        t2[4] = 2.f * acc[4] - c.x;  t2[5] = 2.f * acc[5] - c.y;
        t2[6] = 2.f * acc[6] - d.x;  t2[7] = 2.f * acc[7] - d.y;
    }
    *(uint4*)(Tx2 + fb) = pack_h8(t2);
}

// out = coe0h*x + sum_{i=1..K} coe[i]*Tx_i   (single pass, 8 elems/thread)
__global__ __launch_bounds__(256)
void combine_kernel(const float* __restrict__ xf, const __half* __restrict__ hT,
                    float* __restrict__ out, int total8) {
    int i = blockIdx.x * blockDim.x + threadIdx.x;
    if (i >= total8) return;
    size_t base = (size_t)i << 3;
    float c0 = g_coe[0];   // pre-halved
    float4 x0 = *(const float4*)(xf + base);
    float4 x1 = *(const float4*)(xf + base + 4);
    float acc[8];
    acc[0] = c0 * x0.x;  acc[1] = c0 * x0.y;
    acc[2] = c0 * x0.z;  acc[3] = c0 * x0.w;
    acc[4] = c0 * x1.x;  acc[5] = c0 * x1.y;
    acc[6] = c0 * x1.z;  acc[7] = c0 * x1.w;
#pragma unroll
    for (int k = 1; k <= KORD; k++) {
        float ck = g_coe[k];
        uint4 v = *(const uint4*)(hT + (size_t)(k - 1) * SZNO + base);
        const __half2* hp = (const __half2*)&v;
        float2 f0 = __half22float2(hp[0]);
        float2 f1 = __half22float2(hp[1]);
        float2 f2 = __half22float2(hp[2]);
        float2 f3 = __half22float2(hp[3]);
        acc[0] = fmaf(ck, f0.x, acc[0]);
        acc[1] = fmaf(ck, f0.y, acc[1]);
        acc[2] = fmaf(ck, f1.x, acc[2]);
        acc[3] = fmaf(ck, f1.y, acc[3]);
        acc[4] = fmaf(ck, f2.x, acc[4]);
        acc[5] = fmaf(ck, f2.y, acc[5]);
        acc[6] = fmaf(ck, f3.x, acc[6]);
        acc[7] = fmaf(ck, f3.y, acc[7]);
    }
    *(float4*)(out + base) = make_float4(acc[0], acc[1], acc[2], acc[3]);
    *(float4*)(out + base + 4) = make_float4(acc[4], acc[5], acc[6], acc[7]);
}

// ---------------------------------------------------------------------------
// Launch
// ---------------------------------------------------------------------------
extern "C" void kernel_launch(void* const* d_in, const int* in_sizes, int n_in,
                              void* d_out, int out_size) {
    const float* feature = (const float*)d_in[0];
    const float* W1      = (const float*)d_in[1];
    const float* b1      = (const float*)d_in[2];
    const float* W2      = (const float*)d_in[3];
    const float* b2      = (const float*)d_in[4];
    const float* temp    = (const float*)d_in[5];
    const int*   edge    = (const int*)d_in[6];

    const int n = NNODES;
    const int E = in_sizes[6] / 2;            // 3,200,000
    const int* row = edge;
    const int* col = edge + E;
    float* out = (float*)d_out;

    void *p_xf, *p_hx, *p_hT, *p_deg, *p_cursor;
    void *p_hidHi, *p_hidLo, *p_w1h, *p_w1l, *p_w2h, *p_w2l;
    cudaGetSymbolAddress(&p_xf, g_xf);
    cudaGetSymbolAddress(&p_hx, g_hx);
    cudaGetSymbolAddress(&p_hT, g_hT);
    cudaGetSymbolAddress(&p_deg, g_deg);
    cudaGetSymbolAddress(&p_cursor, g_cursor);
    cudaGetSymbolAddress(&p_hidHi, g_hidHi);
    cudaGetSymbolAddress(&p_hidLo, g_hidLo);
    cudaGetSymbolAddress(&p_w1h, g_W1Hi);
    cudaGetSymbolAddress(&p_w1l, g_W1Lo);
    cudaGetSymbolAddress(&p_w2h, g_W2Hi);
    cudaGetSymbolAddress(&p_w2l, g_W2Lo);

    // 1. Chebyshev coefficients
    cheb_coeffs_kernel<<<1, 32>>>(temp);

    // 2. Split weights to bf16 hi/lo
    split_kernel<<<(NHID * NFEAT + 255) / 256, 256>>>(W1, (__nv_bfloat16*)p_w1h,
                                                      (__nv_bfloat16*)p_w1l, NHID * NFEAT);
    split_kernel<<<(NOUT * NHID + 255) / 256, 256>>>(W2, (__nv_bfloat16*)p_w2h,
                                                     (__nv_bfloat16*)p_w2l, NOUT * NHID);

    // 3. MLP on mma.sync tensor cores (split-bf16), 2 CTAs/SM, 2-stage A+B
    {
        const int mblocks = (n + 63) / 64;                 // 1563
        const int smem1 = 32768 + 2 * 2 * 128 * 128;       // 98304
        const int smem2 = 32768 + 2 * 2 * 64 * 128;        // 65536
        cudaFuncSetAttribute(gemm_mma_kernel<128, NFEAT, NHID, true>,
                             cudaFuncAttributeMaxDynamicSharedMemorySize, smem1);
        cudaFuncSetAttribute(gemm_mma_kernel<64, NHID, NOUT, false>,
                             cudaFuncAttributeMaxDynamicSharedMemorySize, smem2);
        dim3 grid1(NHID / 128, mblocks);
        gemm_mma_kernel<128, NFEAT, NHID, true><<<grid1, 256, smem1>>>(
            feature, nullptr, nullptr,
            (const __nv_bfloat16*)p_w1h, (const __nv_bfloat16*)p_w1l, b1,
            (__nv_bfloat16*)p_hidHi, (__nv_bfloat16*)p_hidLo, nullptr, nullptr, n);
        dim3 grid2(1, mblocks);
        gemm_mma_kernel<64, NHID, NOUT, false><<<grid2, 256, smem2>>>(
            nullptr, (const __nv_bfloat16*)p_hidHi, (const __nv_bfloat16*)p_hidLo,
            (const __nv_bfloat16*)p_w2h, (const __nv_bfloat16*)p_w2l, b2,
            nullptr, nullptr, (float*)p_xf, (__half*)p_hx, n);
    }

    // 4. Graph preprocessing -> CSR (packed col+weight)
    cudaMemsetAsync(p_deg, 0, n * sizeof(int), 0);
    cudaMemsetAsync(p_cursor, 0, n * sizeof(int), 0);
    degree_kernel<<<(E + 255) / 256, 256>>>(row, E);
    dinv_kernel<<<(n + 255) / 256, 256>>>(n);
    scan_kernel<<<1, 1024>>>(n);
    build_csr_kernel<<<(E + 255) / 256, 256>>>(row, col, E);

    // 5. Chebyshev propagation: Tx_i -> g_hT[(i-1)], no out accumulation
    int nwarps = (n + 3) / 4;                      // 25000
    int pblocks = (nwarps + 7) / 8;                // 3125
    __half* hx = (__half*)p_hx;
    __half* hT = (__half*)p_hT;
    prop_first_kernel<<<pblocks, 256>>>(hx, hT, n);                       // Tx1
    {
        // Tx2 = 2*prop(Tx1) - x
        prop_step_kernel<<<pblocks, 256>>>(hT, hx, hT + SZNO, n);
        for (int i = 3; i <= KORD; i++) {
            prop_step_kernel<<<pblocks, 256>>>(hT + (size_t)(i - 2) * SZNO,
                                               hT + (size_t)(i - 3) * SZNO,
                                               hT + (size_t)(i - 1) * SZNO, n);
        }
    }

    // 6. Final combine: out = coe0h*x + sum coe[i]*Tx_i
    int total8 = (int)(SZNO / 8);                  // 800,000
    combine_kernel<<<(total8 + 255) / 256, 256>>>((const float*)p_xf, hT, out, total8);

    (void)n_in; (void)out_size;
}

// round 7
// speedup vs baseline: 2.4320x; 1.1671x over previous
#include <cuda_runtime.h>
#include <cuda_fp16.h>
#include <math.h>
#include <stdint.h>

// Problem constants (fixed by the dataset)
#define NNODES 100000
#define EHALF  1600000
#define NEDGE  (2*EHALF)     // 3,200,000 symmetrized directed edges
#define NFEAT  512
#define NHID   256
#define NOUT   64
#define KORD   10            // Chebyshev order
#define SZNO   ((size_t)NNODES * NOUT)

// ---------------------------------------------------------------------------
// Scratch (static device globals; allocation APIs are forbidden)
// ---------------------------------------------------------------------------
__device__ float  g_xf[SZNO];                 // x fp32 (GEMM2 out)
__device__ __half g_hx[SZNO];                 // x fp16
__device__ __half g_hT[(size_t)KORD * SZNO];  // Tx1..Tx10 (fp16), 128MB
__device__ __half g_hidH[(size_t)NNODES * NHID];   // hidden fp16
__device__ __half g_W1h[(size_t)NHID * NFEAT];     // W1 fp16 [256,512]
__device__ __half g_W2h[(size_t)NOUT * NHID];      // W2 fp16 [64,256]
__device__ int   g_deg[NNODES];
__device__ float g_dinv[NNODES];
__device__ int   g_rowptr[NNODES + 1];
__device__ int   g_cursor[NNODES];
__device__ int2  g_cn[NEDGE];                 // packed (col, norm-as-int)
__device__ float g_coe[KORD + 1];

// ---------------------------------------------------------------------------
// Base-target PTX helpers (mma.sync + ldmatrix + cp.async only)
// ---------------------------------------------------------------------------
__device__ __forceinline__ uint32_t smem_u32(const void* p) {
    uint32_t a;
    asm("{ .reg .u64 t; cvta.to.shared.u64 t, %1; cvt.u32.u64 %0, t; }" : "=r"(a) : "l"(p));
    return a;
}

#define LDSM4(R, addr) \
    asm volatile("ldmatrix.sync.aligned.m8n8.x4.shared.b16 {%0,%1,%2,%3}, [%4];" \
        : "=r"((R)[0]), "=r"((R)[1]), "=r"((R)[2]), "=r"((R)[3]) : "r"(addr))

#define MMA16816F16(C, A, b0, b1) \
    asm volatile("mma.sync.aligned.m16n8k16.row.col.f32.f16.f16.f32 " \
        "{%0,%1,%2,%3},{%4,%5,%6,%7},{%8,%9},{%0,%1,%2,%3};" \
        : "+f"((C)[0]), "+f"((C)[1]), "+f"((C)[2]), "+f"((C)[3]) \
        : "r"((A)[0]), "r"((A)[1]), "r"((A)[2]), "r"((A)[3]), "r"(b0), "r"(b1))

#define CP_ASYNC16(dst, src, zfill) \
    asm volatile("cp.async.cg.shared.global [%0], [%1], 16, %2;" \
        :: "r"((uint32_t)(dst)), "l"(src), "r"((uint32_t)(zfill)) : "memory")
#define CP_COMMIT() asm volatile("cp.async.commit_group;" ::: "memory")
#define CP_WAIT0()  asm volatile("cp.async.wait_group 0;" ::: "memory")
#define CP_WAIT1()  asm volatile("cp.async.wait_group 1;" ::: "memory")

__device__ __forceinline__ uint32_t h2u(__half2 v) {
    return *(uint32_t*)&v;
}

// ---------------------------------------------------------------------------
// fp32 -> fp16 convert
// ---------------------------------------------------------------------------
__global__ void tohalf_kernel(const float* __restrict__ w, __half* __restrict__ h, int n) {
    int i = blockIdx.x * blockDim.x + threadIdx.x;
    if (i >= n) return;
    h[i] = __float2half(w[i]);
}

// ---------------------------------------------------------------------------
// Single-pass fp16 GEMM on mma.sync tensor cores.
//   D[M, NCOL] = A[M, KT] @ B[NCOL, KT]^T + bias   (fp16 in, fp32 acc)
// BM=64, BK=64, 8 warps (2 x 4). B 3-stage, A 2-stage(G1, STS path) or
// 3-stage(G2, cp.async). ONE __syncthreads per k-chunk.
// GEMM1 (IS_G1): A fp32 -> fp16 in-flight; epilogue relu -> fp16 hidden.
// GEMM2: A fp16 via cp.async; epilogue +bias -> fp32 + fp16.
// ---------------------------------------------------------------------------
template <int BN, int KT, int NCOL, bool IS_G1>
__global__ __launch_bounds__(256, 2)
void gemm_mma_kernel(const float* __restrict__ Af32,
                     const __half* __restrict__ Ah16,
                     const __half* __restrict__ Bh16,
                     const float* __restrict__ bias,
                     __half* __restrict__ outHid,
                     float* __restrict__ outF,
                     __half* __restrict__ outHx,
                     int nrows) {
    constexpr int WN  = BN / 4;            // 32 or 16
    constexpr int NT  = WN / 8;            // n8 tiles per warp: 4 or 2
    constexpr int NP  = NT / 2;            // n16 ldmatrix pairs: 2 or 1
    constexpr int CH  = KT / 64;           // k chunks
    constexpr int BIT = BN / 32;           // B fetch iterations
    constexpr uint32_t ASZ = 8192;         // 64 rows x 128B
    constexpr int ASTG = IS_G1 ? 2 : 3;
    constexpr uint32_t BSZ = (uint32_t)BN * 128u;
    constexpr uint32_t BOFF = ASTG * ASZ;

    extern __shared__ char smem[];
    const uint32_t sb = smem_u32(smem);
    const int tid = threadIdx.x, lane = tid & 31, wid = tid >> 5;
    const int warpM = wid >> 2, warpN = wid & 3;
    const int m0 = blockIdx.y * 64, n0 = blockIdx.x * BN;
    const int s = tid & 7, rb = tid >> 3;  // fetch: seg 0..7, row base 0..31

    float cacc[2][NT][4];
#pragma unroll
    for (int mt = 0; mt < 2; mt++)
#pragma unroll
        for (int nt = 0; nt < NT; nt++)
#pragma unroll
            for (int q = 0; q < 4; q++) cacc[mt][nt][q] = 0.0f;

    float af[16];   // GEMM1 A prefetch (fp32), rows {rb, rb+32}, cols s*8..+7

    auto ISSUE_B = [&](int c, int st) {
        const uint32_t bB = sb + BOFF + (uint32_t)st * BSZ;
#pragma unroll
        for (int it = 0; it < BIT; it++) {
            int r = rb + it * 32;
            uint32_t off = (uint32_t)r * 128u + (uint32_t)((s ^ (r & 7)) << 4);
            const char* src = (const char*)(Bh16 + (size_t)(n0 + r) * KT + c * 64 + s * 8);
            CP_ASYNC16(bB + off, src, 16);
        }
    };

    auto ISSUE_A = [&](int c, int st) {   // GEMM2 only
        const uint32_t aB = sb + (uint32_t)st * ASZ;
#pragma unroll
        for (int it = 0; it < 2; it++) {
            int r = rb + it * 32;
            int g = m0 + r;
            uint32_t zf = (g < nrows) ? 16u : 0u;
            uint32_t off = (uint32_t)r * 128u + (uint32_t)((s ^ (r & 7)) << 4);
            const char* src = (const char*)(Ah16 + (size_t)g * KT + c * 64 + s * 8);
            CP_ASYNC16(aB + off, src, zf);
        }
    };

    auto FETCHA = [&](int c) {   // GEMM1 only: fp32 A into registers
#pragma unroll
        for (int it = 0; it < 2; it++) {
            int g = m0 + rb + it * 32;
            if (g < nrows) {
                const float4* p = (const float4*)(Af32 + (size_t)g * KT + c * 64 + s * 8);
                float4 v0 = p[0], v1 = p[1];
                af[it*8+0]=v0.x; af[it*8+1]=v0.y; af[it*8+2]=v0.z; af[it*8+3]=v0.w;
                af[it*8+4]=v1.x; af[it*8+5]=v1.y; af[it*8+6]=v1.z; af[it*8+7]=v1.w;
            } else {
#pragma unroll
                for (int j = 0; j < 8; j++) af[it*8+j] = 0.0f;
            }
        }
    };

    auto STOREA = [&](int st) {  // GEMM1 only: fp32 -> fp16 + STS.128
        char* aB = smem + st * ASZ;
#pragma unroll
        for (int it = 0; it < 2; it++) {
            int r = rb + it * 32;
            uint32_t off = (uint32_t)r * 128u + (uint32_t)((s ^ (r & 7)) << 4);
            uint4 v;
            v.x = h2u(__floats2half2_rn(af[it*8+0], af[it*8+1]));
            v.y = h2u(__floats2half2_rn(af[it*8+2], af[it*8+3]));
            v.z = h2u(__floats2half2_rn(af[it*8+4], af[it*8+5]));
            v.w = h2u(__floats2half2_rn(af[it*8+6], af[it*8+7]));
            *(uint4*)(aB + off) = v;
        }
    };

    auto COMPUTE = [&](int c) {
        const int ast = IS_G1 ? (c & 1) : (c % 3);
        const int bst = c % 3;
        const uint32_t aB = sb + (uint32_t)ast * ASZ;
        const uint32_t bB = sb + BOFF + (uint32_t)bst * BSZ;
        const int g = lane >> 3, r = lane & 7;
#pragma unroll
        for (int ks = 0; ks < 4; ks++) {
            uint32_t Afr[2][4], Bfr[NP][4];
#pragma unroll
            for (int mt = 0; mt < 2; mt++) {
                int row = warpM * 32 + mt * 16 + (g & 1) * 8 + r;
                int seg = ks * 2 + (g >> 1);
                uint32_t off = (uint32_t)row * 128u + (uint32_t)((seg ^ (row & 7)) << 4);
                LDSM4(Afr[mt], aB + off);
            }
#pragma unroll
            for (int pt = 0; pt < NP; pt++) {
                int row = warpN * WN + pt * 16 + (g >> 1) * 8 + r;
                int seg = ks * 2 + (g & 1);
                uint32_t off = (uint32_t)row * 128u + (uint32_t)((seg ^ (row & 7)) << 4);
                LDSM4(Bfr[pt], bB + off);
            }
#pragma unroll
            for (int mt = 0; mt < 2; mt++)
#pragma unroll
                for (int nt = 0; nt < NT; nt++) {
                    const uint32_t* b = &Bfr[nt >> 1][(nt & 1) * 2];
                    MMA16816F16(cacc[mt][nt], Afr[mt], b[0], b[1]);
                }
        }
    };

    // Prologue: fill stages 0 and 1 (groups 0, 1)
    if (IS_G1) { FETCHA(0); STOREA(0); FETCHA(1); }
    else       { ISSUE_A(0, 0); }
    ISSUE_B(0, 0); CP_COMMIT();
    if (!IS_G1) ISSUE_A(1, 1);
    ISSUE_B(1, 1); CP_COMMIT();

    for (int c = 0; c < CH; c++) {
        if (c + 1 < CH) { CP_WAIT1(); } else { CP_WAIT0(); }
        __syncthreads();                    // the ONLY barrier per chunk
        if (c + 2 < CH) {
            if (!IS_G1) ISSUE_A(c + 2, (c + 2) % 3);
            ISSUE_B(c + 2, (c + 2) % 3);
            CP_COMMIT();
        }
        if (IS_G1) {
            if (c + 1 < CH) STOREA((c + 1) & 1);
            if (c + 2 < CH) FETCHA(c + 2);
        }
        COMPUTE(c);
    }

    // ---- epilogue ----
    const int qr = lane >> 2, qc = (lane & 3) * 2;
#pragma unroll
    for (int mt = 0; mt < 2; mt++) {
        int row0 = m0 + warpM * 32 + mt * 16 + qr;
#pragma unroll
        for (int nt = 0; nt < NT; nt++) {
            int col = n0 + warpN * WN + nt * 8 + qc;
            float b0 = __ldg(bias + col), b1 = __ldg(bias + col + 1);
#pragma unroll
            for (int h = 0; h < 2; h++) {
                int row = row0 + h * 8;
                if (row >= nrows) continue;
                float x0 = cacc[mt][nt][h * 2 + 0] + b0;
                float x1 = cacc[mt][nt][h * 2 + 1] + b1;
                if (IS_G1) {
                    x0 = fmaxf(x0, 0.f);
                    x1 = fmaxf(x1, 0.f);
                    *(uint32_t*)(outHid + (size_t)row * NCOL + col) =
                        h2u(__floats2half2_rn(x0, x1));
                } else {
                    *(float2*)(outF + (size_t)row * NCOL + col) = make_float2(x0, x1);
                    *(uint32_t*)(outHx + (size_t)row * NCOL + col) =
                        h2u(__floats2half2_rn(x0, x1));
                }
            }
        }
    }
}

// ---------------------------------------------------------------------------
// Chebyshev coefficients
// ---------------------------------------------------------------------------
__global__ void cheb_coeffs_kernel(const float* __restrict__ temp) {
    int i = threadIdx.x;
    if (i > KORD) return;
    const float PI = 3.14159265358979323846f;
    float s = 0.0f;
    for (int j = 0; j <= KORD; j++) {
        float t = fmaxf(temp[j], 0.0f);
        float theta = (KORD - j + 0.5f) * PI / (KORD + 1);
        s += t * cosf((float)i * theta);
    }
    float c = (2.0f / (KORD + 1)) * s;
    if (i == 0) c *= 0.5f;
    g_coe[i] = c;
}

// ---------------------------------------------------------------------------
// Graph preprocessing
// ---------------------------------------------------------------------------
__global__ void degree_kernel(const int* __restrict__ row, int nedge) {
    int e = blockIdx.x * blockDim.x + threadIdx.x;
    if (e >= nedge) return;
    atomicAdd(&g_deg[row[e]], 1);
}

__global__ void dinv_kernel(int n) {
    int i = blockIdx.x * blockDim.x + threadIdx.x;
    if (i >= n) return;
    int d = g_deg[i];
    g_dinv[i] = (d > 0) ? rsqrtf((float)d) : 0.0f;
}

__global__ void scan_kernel(int n) {
    __shared__ int sums[1024];
    int tid = threadIdx.x;
    int chunk = (n + 1023) / 1024;
    int start = tid * chunk;
    int end = min(start + chunk, n);
    int s = 0;
    for (int i = start; i < end; i++) s += g_deg[i];
    sums[tid] = s;
    __syncthreads();
    for (int off = 1; off < 1024; off <<= 1) {
        int v = 0;
        if (tid >= off) v = sums[tid - off];
        __syncthreads();
        if (tid >= off) sums[tid] += v;
        __syncthreads();
    }
    int prefix = (tid == 0) ? 0 : sums[tid - 1];
    for (int i = start; i < end; i++) {
        g_rowptr[i] = prefix;
        prefix += g_deg[i];
    }
    if (tid == 1023) g_rowptr[n] = prefix;
}

__global__ void build_csr_kernel(const int* __restrict__ row, const int* __restrict__ col,
                                 int nedge) {
    int e = blockIdx.x * blockDim.x + threadIdx.x;
    if (e >= nedge) return;
    int r = row[e];
    int c = col[e];
    int pos = g_rowptr[r] + atomicAdd(&g_cursor[r], 1);
    float w = -g_dinv[r] * g_dinv[c];
    g_cn[pos] = make_int2(c, __float_as_int(w));
}

// ---------------------------------------------------------------------------
// Propagation: CSR SpMM over fp16 state, fp32 math, no out accumulation
// (deferred to combine_kernel). 4 nodes/warp, 8 lanes/node, lane owns 8 feats.
// ---------------------------------------------------------------------------
__device__ __forceinline__ void csr_gather8(const __half* __restrict__ v,
                                            int beg, int end, int lane,
                                            float* __restrict__ acc) {
    const int lane8 = lane & 7;
    const int grpBase = lane & 24;     // (lane>>3)*8
    for (int j = beg; __any_sync(0xffffffffu, j < end); j += 8) {
        int   myc = -1;
        float myn = 0.f;
        int idx = j + lane8;
        if (idx < end && j < end) {
            int2 cw = g_cn[idx];
            myc = cw.x;
            myn = __int_as_float(cw.y);
        }
#pragma unroll
        for (int t = 0; t < 8; t++) {
            int   c = __shfl_sync(0xffffffffu, myc, grpBase + t);
            float w = __shfl_sync(0xffffffffu, myn, grpBase + t);
            if (c >= 0) {
                uint4 hv = *(const uint4*)(v + ((size_t)c << 6) + (lane8 << 3));
                const __half2* hp = (const __half2*)&hv;
                float2 f0 = __half22float2(hp[0]);
                float2 f1 = __half22float2(hp[1]);
                float2 f2 = __half22float2(hp[2]);
                float2 f3 = __half22float2(hp[3]);
                acc[0] = fmaf(w, f0.x, acc[0]);
                acc[1] = fmaf(w, f0.y, acc[1]);
                acc[2] = fmaf(w, f1.x, acc[2]);
                acc[3] = fmaf(w, f1.y, acc[3]);
                acc[4] = fmaf(w, f2.x, acc[4]);
                acc[5] = fmaf(w, f2.y, acc[5]);
                acc[6] = fmaf(w, f3.x, acc[6]);
                acc[7] = fmaf(w, f3.y, acc[7]);
            }
        }
    }
}

__device__ __forceinline__ uint4 pack_h8(const float* a) {
    uint4 r;
    *(__half2*)&r.x = __floats2half2_rn(a[0], a[1]);
    *(__half2*)&r.y = __floats2half2_rn(a[2], a[3]);
    *(__half2*)&r.z = __floats2half2_rn(a[4], a[5]);
    *(__half2*)&r.w = __floats2half2_rn(a[6], a[7]);
    return r;
}

// Tx1 = prop(x)
__global__ __launch_bounds__(256)
void prop_first_kernel(const __half* __restrict__ xh, __half* __restrict__ Tx1, int n) {
    int gw = (blockIdx.x * blockDim.x + threadIdx.x) >> 5;
    int lane = threadIdx.x & 31;
    int node = gw * 4 + (lane >> 3);
    bool ok = node < n;
    int beg = 0, end = 0;
    if (ok) { beg = g_rowptr[node]; end = g_rowptr[node + 1]; }
    float acc[8] = {0.f, 0.f, 0.f, 0.f, 0.f, 0.f, 0.f, 0.f};
    csr_gather8(xh, beg, end, lane, acc);
    if (!ok) return;
    size_t fb = ((size_t)node << 6) + ((lane & 7) << 3);
    *(uint4*)(Tx1 + fb) = pack_h8(acc);
}

// Tx2 = 2*prop(Tx1) - Tx0
__global__ __launch_bounds__(256)
void prop_step_kernel(const __half* __restrict__ Tx1, const __half* __restrict__ Tx0,
                      __half* __restrict__ Tx2, int n) {
    int gw = (blockIdx.x * blockDim.x + threadIdx.x) >> 5;
    int lane = threadIdx.x & 31;
    int node = gw * 4 + (lane >> 3);
    bool ok = node < n;
    int beg = 0, end = 0;
    if (ok) { beg = g_rowptr[node]; end = g_rowptr[node + 1]; }
    float acc[8] = {0.f, 0.f, 0.f, 0.f, 0.f, 0.f, 0.f, 0.f};
    csr_gather8(Tx1, beg, end, lane, acc);
    if (!ok) return;
    size_t fb = ((size_t)node << 6) + ((lane & 7) << 3);
    uint4 t0v = *(const uint4*)(Tx0 + fb);
    const __half2* t0p = (const __half2*)&t0v;
    float t2[8];
    {
        float2 a = __half22float2(t0p[0]), b = __half22float2(t0p[1]);
        float2 c = __half22float2(t0p[2]), d = __half22float2(t0p[3]);
        t2[0] = 2.f * acc[0] - a.x;  t2[1] = 2.f * acc[1] - a.y;
        t2[2] = 2.f * acc[2] - b.x;  t2[3] = 2.f * acc[3] - b.y;
        t2[4] = 2.f * acc[4] - c.x;  t2[5] = 2.f * acc[5] - c.y;
        t2[6] = 2.f * acc[6] - d.x;  t2[7] = 2.f * acc[7] - d.y;
    }
    *(uint4*)(Tx2 + fb) = pack_h8(t2);
}

// out = coe0h*x + sum_{i=1..K} coe[i]*Tx_i   (single pass, 8 elems/thread)
__global__ __launch_bounds__(256)
void combine_kernel(const float* __restrict__ xf, const __half* __restrict__ hT,
                    float* __restrict__ out, int total8) {
    int i = blockIdx.x * blockDim.x + threadIdx.x;
    if (i >= total8) return;
    size_t base = (size_t)i << 3;
    float c0 = g_coe[0];   // pre-halved
    float4 x0 = *(const float4*)(xf + base);
    float4 x1 = *(const float4*)(xf + base + 4);
    float acc[8];
    acc[0] = c0 * x0.x;  acc[1] = c0 * x0.y;
    acc[2] = c0 * x0.z;  acc[3] = c0 * x0.w;
    acc[4] = c0 * x1.x;  acc[5] = c0 * x1.y;
    acc[6] = c0 * x1.z;  acc[7] = c0 * x1.w;
#pragma unroll
    for (int k = 1; k <= KORD; k++) {
        float ck = g_coe[k];
        uint4 v = *(const uint4*)(hT + (size_t)(k - 1) * SZNO + base);
        const __half2* hp = (const __half2*)&v;
        float2 f0 = __half22float2(hp[0]);
        float2 f1 = __half22float2(hp[1]);
        float2 f2 = __half22float2(hp[2]);
        float2 f3 = __half22float2(hp[3]);
        acc[0] = fmaf(ck, f0.x, acc[0]);
        acc[1] = fmaf(ck, f0.y, acc[1]);
        acc[2] = fmaf(ck, f1.x, acc[2]);
        acc[3] = fmaf(ck, f1.y, acc[3]);
        acc[4] = fmaf(ck, f2.x, acc[4]);
        acc[5] = fmaf(ck, f2.y, acc[5]);
        acc[6] = fmaf(ck, f3.x, acc[6]);
        acc[7] = fmaf(ck, f3.y, acc[7]);
    }
    *(float4*)(out + base) = make_float4(acc[0], acc[1], acc[2], acc[3]);
    *(float4*)(out + base + 4) = make_float4(acc[4], acc[5], acc[6], acc[7]);
}

// ---------------------------------------------------------------------------
// Launch
// ---------------------------------------------------------------------------
extern "C" void kernel_launch(void* const* d_in, const int* in_sizes, int n_in,
                              void* d_out, int out_size) {
    const float* feature = (const float*)d_in[0];
    const float* W1      = (const float*)d_in[1];
    const float* b1      = (const float*)d_in[2];
    const float* W2      = (const float*)d_in[3];
    const float* b2      = (const float*)d_in[4];
    const float* temp    = (const float*)d_in[5];
    const int*   edge    = (const int*)d_in[6];

    const int n = NNODES;
    const int E = in_sizes[6] / 2;            // 3,200,000
    const int* row = edge;
    const int* col = edge + E;
    float* out = (float*)d_out;

    void *p_xf, *p_hx, *p_hT, *p_deg, *p_cursor, *p_hidH, *p_w1h, *p_w2h;
    cudaGetSymbolAddress(&p_xf, g_xf);
    cudaGetSymbolAddress(&p_hx, g_hx);
    cudaGetSymbolAddress(&p_hT, g_hT);
    cudaGetSymbolAddress(&p_deg, g_deg);
    cudaGetSymbolAddress(&p_cursor, g_cursor);
    cudaGetSymbolAddress(&p_hidH, g_hidH);
    cudaGetSymbolAddress(&p_w1h, g_W1h);
    cudaGetSymbolAddress(&p_w2h, g_W2h);

    // 1. Chebyshev coefficients
    cheb_coeffs_kernel<<<1, 32>>>(temp);

    // 2. Weights -> fp16
    tohalf_kernel<<<(NHID * NFEAT + 255) / 256, 256>>>(W1, (__half*)p_w1h, NHID * NFEAT);
    tohalf_kernel<<<(NOUT * NHID + 255) / 256, 256>>>(W2, (__half*)p_w2h, NOUT * NHID);

    // 3. MLP: single-pass fp16 mma.sync, 2 CTAs/SM, 1 sync per chunk
    {
        const int mblocks = (n + 63) / 64;                 // 1563
        const int smem1 = 2 * 8192 + 3 * 128 * 128;        // 65536
        const int smem2 = 3 * 8192 + 3 * 64 * 128;         // 49152
        cudaFuncSetAttribute(gemm_mma_kernel<128, NFEAT, NHID, true>,
                             cudaFuncAttributeMaxDynamicSharedMemorySize, smem1);
        cudaFuncSetAttribute(gemm_mma_kernel<64, NHID, NOUT, false>,
                             cudaFuncAttributeMaxDynamicSharedMemorySize, smem2);
        dim3 grid1(NHID / 128, mblocks);
        gemm_mma_kernel<128, NFEAT, NHID, true><<<grid1, 256, smem1>>>(
            feature, nullptr, (const __half*)p_w1h, b1,
            (__half*)p_hidH, nullptr, nullptr, n);
        dim3 grid2(1, mblocks);
        gemm_mma_kernel<64, NHID, NOUT, false><<<grid2, 256, smem2>>>(
            nullptr, (const __half*)p_hidH, (const __half*)p_w2h, b2,
            nullptr, (float*)p_xf, (__half*)p_hx, n);
    }

    // 4. Graph preprocessing -> CSR (packed col+weight)
    cudaMemsetAsync(p_deg, 0, n * sizeof(int), 0);
    cudaMemsetAsync(p_cursor, 0, n * sizeof(int), 0);
    degree_kernel<<<(E + 255) / 256, 256>>>(row, E);
    dinv_kernel<<<(n + 255) / 256, 256>>>(n);
    scan_kernel<<<1, 1024>>>(n);
    build_csr_kernel<<<(E + 255) / 256, 256>>>(row, col, E);

    // 5. Chebyshev propagation: Tx_i -> g_hT[(i-1)], no out accumulation
    int nwarps = (n + 3) / 4;                      // 25000
    int pblocks = (nwarps + 7) / 8;                // 3125
    __half* hx = (__half*)p_hx;
    __half* hT = (__half*)p_hT;
    prop_first_kernel<<<pblocks, 256>>>(hx, hT, n);                       // Tx1
    prop_step_kernel<<<pblocks, 256>>>(hT, hx, hT + SZNO, n);             // Tx2
    for (int i = 3; i <= KORD; i++) {
        prop_step_kernel<<<pblocks, 256>>>(hT + (size_t)(i - 2) * SZNO,
                                           hT + (size_t)(i - 3) * SZNO,
                                           hT + (size_t)(i - 1) * SZNO, n);
    }

    // 6. Final combine: out = coe0h*x + sum coe[i]*Tx_i
    int total8 = (int)(SZNO / 8);                  // 800,000
    combine_kernel<<<(total8 + 255) / 256, 256>>>((const float*)p_xf, hT, out, total8);

    (void)n_in; (void)out_size;
}

// round 8
// speedup vs baseline: 2.5094x; 1.0318x over previous
#include <cuda_runtime.h>
#include <cuda_fp16.h>
#include <math.h>
#include <stdint.h>

// Problem constants (fixed by the dataset)
#define NNODES 100000
#define EHALF  1600000
#define NEDGE  (2*EHALF)     // 3,200,000 symmetrized directed edges
#define NFEAT  512
#define NHID   256
#define NOUT   64
#define KORD   10            // Chebyshev order
#define SZNO   ((size_t)NNODES * NOUT)

// ---------------------------------------------------------------------------
// Scratch (static device globals; allocation APIs are forbidden)
// ---------------------------------------------------------------------------
__device__ float  g_xf[SZNO];                 // x fp32 (GEMM2 out)
__device__ __half g_hx[SZNO];                 // x fp16
__device__ __half g_hT[(size_t)KORD * SZNO];  // Tx1..Tx10 (fp16)
__device__ __half g_hidH[(size_t)NNODES * NHID];   // hidden fp16
__device__ __half g_W1h[(size_t)NHID * NFEAT];     // W1 fp16 [256,512]
__device__ __half g_W2h[(size_t)NOUT * NHID];      // W2 fp16 [64,256]
__device__ int   g_deg[NNODES];
__device__ float g_dinv[NNODES];
__device__ int   g_rowptr[NNODES + 1];
__device__ int   g_cursor[NNODES];
__device__ int2  g_cn[NEDGE];                 // packed (col, norm-as-int)
__device__ float g_coe[KORD + 1];

// ---------------------------------------------------------------------------
// Base-target PTX helpers (mma.sync + ldmatrix + cp.async only)
// ---------------------------------------------------------------------------
__device__ __forceinline__ uint32_t smem_u32(const void* p) {
    uint32_t a;
    asm("{ .reg .u64 t; cvta.to.shared.u64 t, %1; cvt.u32.u64 %0, t; }" : "=r"(a) : "l"(p));
    return a;
}

#define LDSM4(R, addr) \
    asm volatile("ldmatrix.sync.aligned.m8n8.x4.shared.b16 {%0,%1,%2,%3}, [%4];" \
        : "=r"((R)[0]), "=r"((R)[1]), "=r"((R)[2]), "=r"((R)[3]) : "r"(addr))

#define MMA16816F16(C, A, b0, b1) \
    asm volatile("mma.sync.aligned.m16n8k16.row.col.f32.f16.f16.f32 " \
        "{%0,%1,%2,%3},{%4,%5,%6,%7},{%8,%9},{%0,%1,%2,%3};" \
        : "+f"((C)[0]), "+f"((C)[1]), "+f"((C)[2]), "+f"((C)[3]) \
        : "r"((A)[0]), "r"((A)[1]), "r"((A)[2]), "r"((A)[3]), "r"(b0), "r"(b1))

#define CP_ASYNC16(dst, src, zfill) \
    asm volatile("cp.async.cg.shared.global [%0], [%1], 16, %2;" \
        :: "r"((uint32_t)(dst)), "l"(src), "r"((uint32_t)(zfill)) : "memory")
#define CP_COMMIT() asm volatile("cp.async.commit_group;" ::: "memory")
#define CP_WAIT0()  asm volatile("cp.async.wait_group 0;" ::: "memory")
#define CP_WAIT1()  asm volatile("cp.async.wait_group 1;" ::: "memory")
#define CP_WAIT2()  asm volatile("cp.async.wait_group 2;" ::: "memory")

__device__ __forceinline__ uint32_t h2u(__half2 v) {
    return *(uint32_t*)&v;
}

// ---------------------------------------------------------------------------
// fp32 -> fp16 convert
// ---------------------------------------------------------------------------
__global__ void tohalf_kernel(const float* __restrict__ w, __half* __restrict__ h, int n) {
    int i = blockIdx.x * blockDim.x + threadIdx.x;
    if (i >= n) return;
    h[i] = __float2half(w[i]);
}

// ---------------------------------------------------------------------------
// GEMM1: hidden[N,256] = relu(feature[N,512] @ W1h[256,512]^T + b1), fp16 out.
// BM=64, BN=128, BK=64, 8 warps. A loaded as RAW fp32 via 3-stage cp.async
// (2 chunks of A in flight during compute) then converted fp32->fp16 in smem.
// B (weights) 3-stage cp.async from L2. 2 CTAs/SM (112KB smem).
// ---------------------------------------------------------------------------
__global__ __launch_bounds__(256, 2)
void gemm1_kernel(const float* __restrict__ Af32, const __half* __restrict__ Bh16,
                  const float* __restrict__ bias, __half* __restrict__ outHid,
                  int nrows) {
    constexpr int KT = NFEAT;              // 512
    constexpr int BN = 128;
    constexpr int NCOL = NHID;             // 256
    constexpr int CH = KT / 64;            // 8
    constexpr uint32_t A32OFF = 0;         // 3 x 16384 (fp32, 64 rows x 256B)
    constexpr uint32_t A16OFF = 49152;     // 2 x 8192  (fp16, 64 rows x 128B)
    constexpr uint32_t BOFF2  = 65536;     // 3 x 16384 (fp16, 128 rows x 128B)

    extern __shared__ char smem[];
    const uint32_t sb = smem_u32(smem);
    const int tid = threadIdx.x, lane = tid & 31, wid = tid >> 5;
    const int warpM = wid >> 2, warpN = wid & 3;
    const int m0 = blockIdx.y * 64, n0 = blockIdx.x * BN;
    const int s = tid & 7,  rb = tid >> 3;    // B fetch: 8 segs x 32-row groups
    const int s2 = tid & 15, rb2 = tid >> 4;  // A fetch: 16 segs x 16-row groups

    float cacc[2][4][4];
#pragma unroll
    for (int mt = 0; mt < 2; mt++)
#pragma unroll
        for (int nt = 0; nt < 4; nt++)
#pragma unroll
            for (int q = 0; q < 4; q++) cacc[mt][nt][q] = 0.0f;

    auto ISSUE_A32 = [&](int c, int st) {
        const uint32_t aB = sb + A32OFF + (uint32_t)st * 16384u;
#pragma unroll
        for (int it = 0; it < 4; it++) {
            int r = rb2 + it * 16;
            int g = m0 + r;
            uint32_t zf = (g < nrows) ? 16u : 0u;
            const char* src = (const char*)(Af32 + (size_t)g * KT + c * 64 + s2 * 4);
            CP_ASYNC16(aB + (uint32_t)r * 256u + (uint32_t)s2 * 16u, src, zf);
        }
    };

    auto ISSUE_B = [&](int c, int st) {
        const uint32_t bB = sb + BOFF2 + (uint32_t)st * 16384u;
#pragma unroll
        for (int it = 0; it < 4; it++) {
            int r = rb + it * 32;
            uint32_t off = (uint32_t)r * 128u + (uint32_t)((s ^ (r & 7)) << 4);
            const char* src = (const char*)(Bh16 + (size_t)(n0 + r) * KT + c * 64 + s * 8);
            CP_ASYNC16(bB + off, src, 16);
        }
    };

    auto CONVERT = [&](int k) {            // A32 stage k%3 -> A16 stage k&1
        const char* a32 = smem + A32OFF + (k % 3) * 16384;
        char* a16 = smem + A16OFF + (k & 1) * 8192;
        const int seg = s2 >> 1, sub = (s2 & 1) * 8;
#pragma unroll
        for (int it = 0; it < 4; it++) {
            int r = rb2 + it * 16;
            float4 v = *(const float4*)(a32 + r * 256 + s2 * 16);
            uint2 hv;
            hv.x = h2u(__floats2half2_rn(v.x, v.y));
            hv.y = h2u(__floats2half2_rn(v.z, v.w));
            *(uint2*)(a16 + r * 128 + ((seg ^ (r & 7)) << 4) + sub) = hv;
        }
    };

    auto COMPUTE = [&](int c) {
        const uint32_t aB = sb + A16OFF + (uint32_t)(c & 1) * 8192u;
        const uint32_t bB = sb + BOFF2 + (uint32_t)(c % 3) * 16384u;
        const int g = lane >> 3, r = lane & 7;
#pragma unroll
        for (int ks = 0; ks < 4; ks++) {
            uint32_t Afr[2][4], Bfr[2][4];
#pragma unroll
            for (int mt = 0; mt < 2; mt++) {
                int row = warpM * 32 + mt * 16 + (g & 1) * 8 + r;
                int seg = ks * 2 + (g >> 1);
                uint32_t off = (uint32_t)row * 128u + (uint32_t)((seg ^ (row & 7)) << 4);
                LDSM4(Afr[mt], aB + off);
            }
#pragma unroll
            for (int pt = 0; pt < 2; pt++) {
                int row = warpN * 32 + pt * 16 + (g >> 1) * 8 + r;
                int seg = ks * 2 + (g & 1);
                uint32_t off = (uint32_t)row * 128u + (uint32_t)((seg ^ (row & 7)) << 4);
                LDSM4(Bfr[pt], bB + off);
            }
#pragma unroll
            for (int mt = 0; mt < 2; mt++)
#pragma unroll
                for (int nt = 0; nt < 4; nt++) {
                    const uint32_t* b = &Bfr[nt >> 1][(nt & 1) * 2];
                    MMA16816F16(cacc[mt][nt], Afr[mt], b[0], b[1]);
                }
        }
    };

    // Prologue: 3 groups (A32 0..2, B 0..1)
    ISSUE_A32(0, 0); CP_COMMIT();
    ISSUE_A32(1, 1); ISSUE_B(0, 0); CP_COMMIT();
    ISSUE_A32(2, 2); ISSUE_B(1, 1); CP_COMMIT();
    CP_WAIT2();
    __syncthreads();
    CONVERT(0);

    for (int c = 0; c < CH; c++) {
        CP_WAIT1();
        __syncthreads();
        if (c + 3 < CH) ISSUE_A32(c + 3, (c + 3) % 3);
        if (c + 2 < CH) ISSUE_B(c + 2, (c + 2) % 3);
        CP_COMMIT();                      // commit every iter (empty OK)
        if (c + 1 < CH) CONVERT(c + 1);
        COMPUTE(c);
    }

    // Epilogue: relu + bias -> fp16
    const int qr = lane >> 2, qc = (lane & 3) * 2;
#pragma unroll
    for (int mt = 0; mt < 2; mt++) {
        int row0 = m0 + warpM * 32 + mt * 16 + qr;
#pragma unroll
        for (int nt = 0; nt < 4; nt++) {
            int col = n0 + warpN * 32 + nt * 8 + qc;
            float b0 = __ldg(bias + col), b1 = __ldg(bias + col + 1);
#pragma unroll
            for (int h = 0; h < 2; h++) {
                int row = row0 + h * 8;
                if (row >= nrows) continue;
                float x0 = fmaxf(cacc[mt][nt][h * 2 + 0] + b0, 0.f);
                float x1 = fmaxf(cacc[mt][nt][h * 2 + 1] + b1, 0.f);
                *(uint32_t*)(outHid + (size_t)row * NCOL + col) =
                    h2u(__floats2half2_rn(x0, x1));
            }
        }
    }
}

// ---------------------------------------------------------------------------
// GEMM2: x[N,64] = hidden[N,256] @ W2h[64,256]^T + b2  -> fp32 + fp16.
// BM=64, BN=64, 8 warps, A+B fp16 via 3-stage cp.async (2 chunks in flight).
// ---------------------------------------------------------------------------
__global__ __launch_bounds__(256, 2)
void gemm2_kernel(const __half* __restrict__ Ah16, const __half* __restrict__ Bh16,
                  const float* __restrict__ bias, float* __restrict__ outF,
                  __half* __restrict__ outHx, int nrows) {
    constexpr int KT = NHID;               // 256
    constexpr int BN = 64;
    constexpr int NCOL = NOUT;             // 64
    constexpr int CH = KT / 64;            // 4
    constexpr uint32_t ASZ = 8192, BSZ = 8192;
    constexpr uint32_t BOFF2 = 3 * ASZ;    // 24576

    extern __shared__ char smem[];
    const uint32_t sb = smem_u32(smem);
    const int tid = threadIdx.x, lane = tid & 31, wid = tid >> 5;
    const int warpM = wid >> 2, warpN = wid & 3;
    const int m0 = blockIdx.y * 64, n0 = 0;
    const int s = tid & 7, rb = tid >> 3;

    float cacc[2][2][4];
#pragma unroll
    for (int mt = 0; mt < 2; mt++)
#pragma unroll
        for (int nt = 0; nt < 2; nt++)
#pragma unroll
            for (int q = 0; q < 4; q++) cacc[mt][nt][q] = 0.0f;

    auto ISSUE_A = [&](int c, int st) {
        const uint32_t aB = sb + (uint32_t)st * ASZ;
#pragma unroll
        for (int it = 0; it < 2; it++) {
            int r = rb + it * 32;
            int g = m0 + r;
            uint32_t zf = (g < nrows) ? 16u : 0u;
            uint32_t off = (uint32_t)r * 128u + (uint32_t)((s ^ (r & 7)) << 4);
            const char* src = (const char*)(Ah16 + (size_t)g * KT + c * 64 + s * 8);
            CP_ASYNC16(aB + off, src, zf);
        }
    };

    auto ISSUE_B = [&](int c, int st) {
        const uint32_t bB = sb + BOFF2 + (uint32_t)st * BSZ;
#pragma unroll
        for (int it = 0; it < 2; it++) {
            int r = rb + it * 32;
            uint32_t off = (uint32_t)r * 128u + (uint32_t)((s ^ (r & 7)) << 4);
            const char* src = (const char*)(Bh16 + (size_t)(n0 + r) * KT + c * 64 + s * 8);
            CP_ASYNC16(bB + off, src, 16);
        }
    };

    auto COMPUTE = [&](int c) {
        const uint32_t aB = sb + (uint32_t)(c % 3) * ASZ;
        const uint32_t bB = sb + BOFF2 + (uint32_t)(c % 3) * BSZ;
        const int g = lane >> 3, r = lane & 7;
#pragma unroll
        for (int ks = 0; ks < 4; ks++) {
            uint32_t Afr[2][4], Bfr[1][4];
#pragma unroll
            for (int mt = 0; mt < 2; mt++) {
                int row = warpM * 32 + mt * 16 + (g & 1) * 8 + r;
                int seg = ks * 2 + (g >> 1);
                uint32_t off = (uint32_t)row * 128u + (uint32_t)((seg ^ (row & 7)) << 4);
                LDSM4(Afr[mt], aB + off);
            }
            {
                int row = warpN * 16 + (g >> 1) * 8 + r;
                int seg = ks * 2 + (g & 1);
                uint32_t off = (uint32_t)row * 128u + (uint32_t)((seg ^ (row & 7)) << 4);
                LDSM4(Bfr[0], bB + off);
            }
#pragma unroll
            for (int mt = 0; mt < 2; mt++)
#pragma unroll
                for (int nt = 0; nt < 2; nt++) {
                    const uint32_t* b = &Bfr[0][nt * 2];
                    MMA16816F16(cacc[mt][nt], Afr[mt], b[0], b[1]);
                }
        }
    };

    ISSUE_A(0, 0); ISSUE_B(0, 0); CP_COMMIT();
    ISSUE_A(1, 1); ISSUE_B(1, 1); CP_COMMIT();

    for (int c = 0; c < CH; c++) {
        CP_WAIT1();
        __syncthreads();
        if (c + 2 < CH) { ISSUE_A(c + 2, (c + 2) % 3); ISSUE_B(c + 2, (c + 2) % 3); }
        CP_COMMIT();
        COMPUTE(c);
    }

    const int qr = lane >> 2, qc = (lane & 3) * 2;
#pragma unroll
    for (int mt = 0; mt < 2; mt++) {
        int row0 = m0 + warpM * 32 + mt * 16 + qr;
#pragma unroll
        for (int nt = 0; nt < 2; nt++) {
            int col = warpN * 16 + nt * 8 + qc;
            float b0 = __ldg(bias + col), b1 = __ldg(bias + col + 1);
#pragma unroll
            for (int h = 0; h < 2; h++) {
                int row = row0 + h * 8;
                if (row >= nrows) continue;
                float x0 = cacc[mt][nt][h * 2 + 0] + b0;
                float x1 = cacc[mt][nt][h * 2 + 1] + b1;
                *(float2*)(outF + (size_t)row * NCOL + col) = make_float2(x0, x1);
                *(uint32_t*)(outHx + (size_t)row * NCOL + col) =
                    h2u(__floats2half2_rn(x0, x1));
            }
        }
    }
}

// ---------------------------------------------------------------------------
// Chebyshev coefficients
// ---------------------------------------------------------------------------
__global__ void cheb_coeffs_kernel(const float* __restrict__ temp) {
    int i = threadIdx.x;
    if (i > KORD) return;
    const float PI = 3.14159265358979323846f;
    float s = 0.0f;
    for (int j = 0; j <= KORD; j++) {
        float t = fmaxf(temp[j], 0.0f);
        float theta = (KORD - j + 0.5f) * PI / (KORD + 1);
        s += t * cosf((float)i * theta);
    }
    float c = (2.0f / (KORD + 1)) * s;
    if (i == 0) c *= 0.5f;
    g_coe[i] = c;
}

// ---------------------------------------------------------------------------
// Graph preprocessing
// ---------------------------------------------------------------------------
__global__ void degree_kernel(const int* __restrict__ row, int nedge) {
    int e = blockIdx.x * blockDim.x + threadIdx.x;
    if (e >= nedge) return;
    atomicAdd(&g_deg[row[e]], 1);
}

__global__ void dinv_kernel(int n) {
    int i = blockIdx.x * blockDim.x + threadIdx.x;
    if (i >= n) return;
    int d = g_deg[i];
    g_dinv[i] = (d > 0) ? rsqrtf((float)d) : 0.0f;
}

__global__ void scan_kernel(int n) {
    __shared__ int sums[1024];
    int tid = threadIdx.x;
    int chunk = (n + 1023) / 1024;
    int start = tid * chunk;
    int end = min(start + chunk, n);
    int s = 0;
    for (int i = start; i < end; i++) s += g_deg[i];
    sums[tid] = s;
    __syncthreads();
    for (int off = 1; off < 1024; off <<= 1) {
        int v = 0;
        if (tid >= off) v = sums[tid - off];
        __syncthreads();
        if (tid >= off) sums[tid] += v;
        __syncthreads();
    }
    int prefix = (tid == 0) ? 0 : sums[tid - 1];
    for (int i = start; i < end; i++) {
        g_rowptr[i] = prefix;
        prefix += g_deg[i];
    }
    if (tid == 1023) g_rowptr[n] = prefix;
}

__global__ void build_csr_kernel(const int* __restrict__ row, const int* __restrict__ col,
                                 int nedge) {
    int e = blockIdx.x * blockDim.x + threadIdx.x;
    if (e >= nedge) return;
    int r = row[e];
    int c = col[e];
    int pos = g_rowptr[r] + atomicAdd(&g_cursor[r], 1);
    float w = -g_dinv[r] * g_dinv[c];
    g_cn[pos] = make_int2(c, __float_as_int(w));
}

// ---------------------------------------------------------------------------
// Propagation: CSR SpMM over fp16 state, fp32 math.
// 4 nodes/warp, 8 lanes/node, lane owns 8 feats (one uint4 of fp16).
// ---------------------------------------------------------------------------
__device__ __forceinline__ void csr_gather8(const __half* __restrict__ v,
                                            int beg, int end, int lane,
                                            float* __restrict__ acc) {
    const int lane8 = lane & 7;
    const int grpBase = lane & 24;     // (lane>>3)*8
    for (int j = beg; __any_sync(0xffffffffu, j < end); j += 8) {
        int   myc = -1;
        float myn = 0.f;
        int idx = j + lane8;
        if (idx < end && j < end) {
            int2 cw = g_cn[idx];
            myc = cw.x;
            myn = __int_as_float(cw.y);
        }
#pragma unroll
        for (int t = 0; t < 8; t++) {
            int   c = __shfl_sync(0xffffffffu, myc, grpBase + t);
            float w = __shfl_sync(0xffffffffu, myn, grpBase + t);
            if (c >= 0) {
                uint4 hv = *(const uint4*)(v + ((size_t)c << 6) + (lane8 << 3));
                const __half2* hp = (const __half2*)&hv;
                float2 f0 = __half22float2(hp[0]);
                float2 f1 = __half22float2(hp[1]);
                float2 f2 = __half22float2(hp[2]);
                float2 f3 = __half22float2(hp[3]);
                acc[0] = fmaf(w, f0.x, acc[0]);
                acc[1] = fmaf(w, f0.y, acc[1]);
                acc[2] = fmaf(w, f1.x, acc[2]);
                acc[3] = fmaf(w, f1.y, acc[3]);
                acc[4] = fmaf(w, f2.x, acc[4]);
                acc[5] = fmaf(w, f2.y, acc[5]);
                acc[6] = fmaf(w, f3.x, acc[6]);
                acc[7] = fmaf(w, f3.y, acc[7]);
            }
        }
    }
}

__device__ __forceinline__ uint4 pack_h8(const float* a) {
    uint4 r;
    *(__half2*)&r.x = __floats2half2_rn(a[0], a[1]);
    *(__half2*)&r.y = __floats2half2_rn(a[2], a[3]);
    *(__half2*)&r.z = __floats2half2_rn(a[4], a[5]);
    *(__half2*)&r.w = __floats2half2_rn(a[6], a[7]);
    return r;
}

// Tx1 = prop(x)
__global__ __launch_bounds__(256)
void prop_first_kernel(const __half* __restrict__ xh, __half* __restrict__ Tx1, int n) {
    int gw = (blockIdx.x * blockDim.x + threadIdx.x) >> 5;
    int lane = threadIdx.x & 31;
    int node = gw * 4 + (lane >> 3);
    bool ok = node < n;
    int beg = 0, end = 0;
    if (ok) { beg = g_rowptr[node]; end = g_rowptr[node + 1]; }
    float acc[8] = {0.f, 0.f, 0.f, 0.f, 0.f, 0.f, 0.f, 0.f};
    csr_gather8(xh, beg, end, lane, acc);
    if (!ok) return;
    size_t fb = ((size_t)node << 6) + ((lane & 7) << 3);
    *(uint4*)(Tx1 + fb) = pack_h8(acc);
}

// Tx2 = 2*prop(Tx1) - Tx0
__global__ __launch_bounds__(256)
void prop_step_kernel(const __half* __restrict__ Tx1, const __half* __restrict__ Tx0,
                      __half* __restrict__ Tx2, int n) {
    int gw = (blockIdx.x * blockDim.x + threadIdx.x) >> 5;
    int lane = threadIdx.x & 31;
    int node = gw * 4 + (lane >> 3);
    bool ok = node < n;
    int beg = 0, end = 0;
    if (ok) { beg = g_rowptr[node]; end = g_rowptr[node + 1]; }
    float acc[8] = {0.f, 0.f, 0.f, 0.f, 0.f, 0.f, 0.f, 0.f};
    csr_gather8(Tx1, beg, end, lane, acc);
    if (!ok) return;
    size_t fb = ((size_t)node << 6) + ((lane & 7) << 3);
    uint4 t0v = *(const uint4*)(Tx0 + fb);
    const __half2* t0p = (const __half2*)&t0v;
    float t2[8];
    {
        float2 a = __half22float2(t0p[0]), b = __half22float2(t0p[1]);
        float2 c = __half22float2(t0p[2]), d = __half22float2(t0p[3]);
        t2[0] = 2.f * acc[0] - a.x;  t2[1] = 2.f * acc[1] - a.y;
        t2[2] = 2.f * acc[2] - b.x;  t2[3] = 2.f * acc[3] - b.y;
        t2[4] = 2.f * acc[4] - c.x;  t2[5] = 2.f * acc[5] - c.y;
        t2[6] = 2.f * acc[6] - d.x;  t2[7] = 2.f * acc[7] - d.y;
    }
    *(uint4*)(Tx2 + fb) = pack_h8(t2);
}

// Last step fused with the final combine:
// t2 = 2*prop(Tx9) - Tx8 (kept in regs);
// out = coe0h*x + sum_{k=1..9} coe[k]*Tx_k + coe[10]*t2
__global__ __launch_bounds__(256)
void prop_last_kernel(const __half* __restrict__ Tx9, const __half* __restrict__ Tx8,
                      const __half* __restrict__ hT, const float* __restrict__ xf,
                      float* __restrict__ out, int n) {
    int gw = (blockIdx.x * blockDim.x + threadIdx.x) >> 5;
    int lane = threadIdx.x & 31;
    int node = gw * 4 + (lane >> 3);
    bool ok = node < n;
    int beg = 0, end = 0;
    if (ok) { beg = g_rowptr[node]; end = g_rowptr[node + 1]; }
    float acc[8] = {0.f, 0.f, 0.f, 0.f, 0.f, 0.f, 0.f, 0.f};
    csr_gather8(Tx9, beg, end, lane, acc);
    if (!ok) return;
    size_t fb = ((size_t)node << 6) + ((lane & 7) << 3);

    float t2[8];
    {
        uint4 t0v = *(const uint4*)(Tx8 + fb);
        const __half2* t0p = (const __half2*)&t0v;
        float2 a = __half22float2(t0p[0]), b = __half22float2(t0p[1]);
        float2 c = __half22float2(t0p[2]), d = __half22float2(t0p[3]);
        t2[0] = 2.f * acc[0] - a.x;  t2[1] = 2.f * acc[1] - a.y;
        t2[2] = 2.f * acc[2] - b.x;  t2[3] = 2.f * acc[3] - b.y;
        t2[4] = 2.f * acc[4] - c.x;  t2[5] = 2.f * acc[5] - c.y;
        t2[6] = 2.f * acc[6] - d.x;  t2[7] = 2.f * acc[7] - d.y;
    }

    float res[8];
    {
        float c0 = g_coe[0];   // pre-halved
        float4 x0 = *(const float4*)(xf + fb);
        float4 x1 = *(const float4*)(xf + fb + 4);
        res[0] = c0 * x0.x;  res[1] = c0 * x0.y;
        res[2] = c0 * x0.z;  res[3] = c0 * x0.w;
        res[4] = c0 * x1.x;  res[5] = c0 * x1.y;
        res[6] = c0 * x1.z;  res[7] = c0 * x1.w;
    }
#pragma unroll
    for (int k = 1; k <= KORD - 1; k++) {
        float ck = g_coe[k];
        uint4 v = *(const uint4*)(hT + (size_t)(k - 1) * SZNO + fb);
        const __half2* hp = (const __half2*)&v;
        float2 f0 = __half22float2(hp[0]);
        float2 f1 = __half22float2(hp[1]);
        float2 f2 = __half22float2(hp[2]);
        float2 f3 = __half22float2(hp[3]);
        res[0] = fmaf(ck, f0.x, res[0]);
        res[1] = fmaf(ck, f0.y, res[1]);
        res[2] = fmaf(ck, f1.x, res[2]);
        res[3] = fmaf(ck, f1.y, res[3]);
        res[4] = fmaf(ck, f2.x, res[4]);
        res[5] = fmaf(ck, f2.y, res[5]);
        res[6] = fmaf(ck, f3.x, res[6]);
        res[7] = fmaf(ck, f3.y, res[7]);
    }
    float cK = g_coe[KORD];
#pragma unroll
    for (int q = 0; q < 8; q++) res[q] = fmaf(cK, t2[q], res[q]);

    *(float4*)(out + fb) = make_float4(res[0], res[1], res[2], res[3]);
    *(float4*)(out + fb + 4) = make_float4(res[4], res[5], res[6], res[7]);
}

// ---------------------------------------------------------------------------
// Launch
// ---------------------------------------------------------------------------
extern "C" void kernel_launch(void* const* d_in, const int* in_sizes, int n_in,
                              void* d_out, int out_size) {
    const float* feature = (const float*)d_in[0];
    const float* W1      = (const float*)d_in[1];
    const float* b1      = (const float*)d_in[2];
    const float* W2      = (const float*)d_in[3];
    const float* b2      = (const float*)d_in[4];
    const float* temp    = (const float*)d_in[5];
    const int*   edge    = (const int*)d_in[6];

    const int n = NNODES;
    const int E = in_sizes[6] / 2;            // 3,200,000
    const int* row = edge;
    const int* col = edge + E;
    float* out = (float*)d_out;

    void *p_xf, *p_hx, *p_hT, *p_deg, *p_cursor, *p_hidH, *p_w1h, *p_w2h;
    cudaGetSymbolAddress(&p_xf, g_xf);
    cudaGetSymbolAddress(&p_hx, g_hx);
    cudaGetSymbolAddress(&p_hT, g_hT);
    cudaGetSymbolAddress(&p_deg, g_deg);
    cudaGetSymbolAddress(&p_cursor, g_cursor);
    cudaGetSymbolAddress(&p_hidH, g_hidH);
    cudaGetSymbolAddress(&p_w1h, g_W1h);
    cudaGetSymbolAddress(&p_w2h, g_W2h);

    // 1. Chebyshev coefficients
    cheb_coeffs_kernel<<<1, 32>>>(temp);

    // 2. Weights -> fp16
    tohalf_kernel<<<(NHID * NFEAT + 255) / 256, 256>>>(W1, (__half*)p_w1h, NHID * NFEAT);
    tohalf_kernel<<<(NOUT * NHID + 255) / 256, 256>>>(W2, (__half*)p_w2h, NOUT * NHID);

    // 3. MLP on mma.sync tensor cores
    {
        const int mblocks = (n + 63) / 64;                 // 1563
        const int smem1 = 3 * 16384 + 2 * 8192 + 3 * 16384;   // 114688
        const int smem2 = 3 * 8192 + 3 * 8192;                 // 49152
        cudaFuncSetAttribute(gemm1_kernel,
                             cudaFuncAttributeMaxDynamicSharedMemorySize, smem1);
        cudaFuncSetAttribute(gemm2_kernel,
                             cudaFuncAttributeMaxDynamicSharedMemorySize, smem2);
        dim3 grid1(NHID / 128, mblocks);
        gemm1_kernel<<<grid1, 256, smem1>>>(feature, (const __half*)p_w1h, b1,
                                            (__half*)p_hidH, n);
        dim3 grid2(1, mblocks);
        gemm2_kernel<<<grid2, 256, smem2>>>((const __half*)p_hidH, (const __half*)p_w2h,
                                            b2, (float*)p_xf, (__half*)p_hx, n);
    }

    // 4. Graph preprocessing -> CSR (packed col+weight)
    cudaMemsetAsync(p_deg, 0, n * sizeof(int), 0);
    cudaMemsetAsync(p_cursor, 0, n * sizeof(int), 0);
    degree_kernel<<<(E + 255) / 256, 256>>>(row, E);
    dinv_kernel<<<(n + 255) / 256, 256>>>(n);
    scan_kernel<<<1, 1024>>>(n);
    build_csr_kernel<<<(E + 255) / 256, 256>>>(row, col, E);

    // 5. Chebyshev propagation: Tx_i -> g_hT[(i-1)]; last step fused w/ combine
    int nwarps = (n + 3) / 4;                      // 25000
    int pblocks = (nwarps + 7) / 8;                // 3125
    __half* hx = (__half*)p_hx;
    __half* hT = (__half*)p_hT;
    prop_first_kernel<<<pblocks, 256>>>(hx, hT, n);                       // Tx1
    prop_step_kernel<<<pblocks, 256>>>(hT, hx, hT + SZNO, n);             // Tx2
    for (int i = 3; i <= KORD - 1; i++) {
        prop_step_kernel<<<pblocks, 256>>>(hT + (size_t)(i - 2) * SZNO,
                                           hT + (size_t)(i - 3) * SZNO,
                                           hT + (size_t)(i - 1) * SZNO, n);
    }
    // step 10 + combine fused
    prop_last_kernel<<<pblocks, 256>>>(hT + (size_t)(KORD - 2) * SZNO,
                                       hT + (size_t)(KORD - 3) * SZNO,
                                       hT, (const float*)p_xf, out, n);

    (void)n_in; (void)out_size;
}

// round 9
// speedup vs baseline: 2.6242x; 1.0457x over previous
#include <cuda_runtime.h>
#include <cuda_fp16.h>
#include <math.h>
#include <stdint.h>

// Problem constants (fixed by the dataset)
#define NNODES 100000
#define EHALF  1600000
#define NEDGE  (2*EHALF)     // 3,200,000 symmetrized directed edges
#define NFEAT  512
#define NHID   256
#define NOUT   64
#define KORD   10            // Chebyshev order
#define SZNO   ((size_t)NNODES * NOUT)

// ---------------------------------------------------------------------------
// Scratch (static device globals; allocation APIs are forbidden)
// ---------------------------------------------------------------------------
__device__ float  g_xf[SZNO];                 // x fp32 (GEMM2 out, unscaled)
__device__ __half g_s0[SZNO];                 // s0 = dinv * x (fp16)
__device__ __half g_sT[(size_t)KORD * SZNO];  // s1..s10 (scaled Tx, fp16)
__device__ __half g_hidH[(size_t)NNODES * NHID];   // hidden fp16
__device__ __half g_W1h[(size_t)NHID * NFEAT];     // W1 fp16 [256,512]
__device__ __half g_W2h[(size_t)NOUT * NHID];      // W2 fp16 [64,256]
__device__ int   g_deg[NNODES];
__device__ float g_dinv[NNODES];              // deg^-1/2 (0 if deg==0)
__device__ float g_d2[NNODES];                // dinv^2
__device__ float g_sqd[NNODES];               // sqrt(deg) = 1/dinv (0 if deg==0)
__device__ int   g_rowptr[NNODES + 1];
__device__ int   g_cursor[NNODES];
__device__ int   g_col[NEDGE];                // CSR columns only (no weights!)
__device__ float g_coe[KORD + 1];

// ---------------------------------------------------------------------------
// Base-target PTX helpers (mma.sync + ldmatrix + cp.async only)
// ---------------------------------------------------------------------------
__device__ __forceinline__ uint32_t smem_u32(const void* p) {
    uint32_t a;
    asm("{ .reg .u64 t; cvta.to.shared.u64 t, %1; cvt.u32.u64 %0, t; }" : "=r"(a) : "l"(p));
    return a;
}

#define LDSM4(R, addr) \
    asm volatile("ldmatrix.sync.aligned.m8n8.x4.shared.b16 {%0,%1,%2,%3}, [%4];" \
        : "=r"((R)[0]), "=r"((R)[1]), "=r"((R)[2]), "=r"((R)[3]) : "r"(addr))

#define MMA16816F16(C, A, b0, b1) \
    asm volatile("mma.sync.aligned.m16n8k16.row.col.f32.f16.f16.f32 " \
        "{%0,%1,%2,%3},{%4,%5,%6,%7},{%8,%9},{%0,%1,%2,%3};" \
        : "+f"((C)[0]), "+f"((C)[1]), "+f"((C)[2]), "+f"((C)[3]) \
        : "r"((A)[0]), "r"((A)[1]), "r"((A)[2]), "r"((A)[3]), "r"(b0), "r"(b1))

#define CP_ASYNC16(dst, src, zfill) \
    asm volatile("cp.async.cg.shared.global [%0], [%1], 16, %2;" \
        :: "r"((uint32_t)(dst)), "l"(src), "r"((uint32_t)(zfill)) : "memory")
#define CP_COMMIT() asm volatile("cp.async.commit_group;" ::: "memory")
#define CP_WAIT0()  asm volatile("cp.async.wait_group 0;" ::: "memory")
#define CP_WAIT1()  asm volatile("cp.async.wait_group 1;" ::: "memory")
#define CP_WAIT2()  asm volatile("cp.async.wait_group 2;" ::: "memory")

__device__ __forceinline__ uint32_t h2u(__half2 v) {
    return *(uint32_t*)&v;
}

// ---------------------------------------------------------------------------
// fp32 -> fp16 convert
// ---------------------------------------------------------------------------
__global__ void tohalf_kernel(const float* __restrict__ w, __half* __restrict__ h, int n) {
    int i = blockIdx.x * blockDim.x + threadIdx.x;
    if (i >= n) return;
    h[i] = __float2half(w[i]);
}

// ---------------------------------------------------------------------------
// GEMM1: hidden[N,256] = relu(feature[N,512] @ W1h[256,512]^T + b1), fp16 out.
// BM=64, BN=128, BK=64, 8 warps. A raw fp32 via 3-stage cp.async, converted
// fp32->fp16 in smem. B 3-stage cp.async. 2 CTAs/SM.
// ---------------------------------------------------------------------------
__global__ __launch_bounds__(256, 2)
void gemm1_kernel(const float* __restrict__ Af32, const __half* __restrict__ Bh16,
                  const float* __restrict__ bias, __half* __restrict__ outHid,
                  int nrows) {
    constexpr int KT = NFEAT;              // 512
    constexpr int NCOL = NHID;             // 256
    constexpr int CH = KT / 64;            // 8
    constexpr uint32_t A32OFF = 0;         // 3 x 16384
    constexpr uint32_t A16OFF = 49152;     // 2 x 8192
    constexpr uint32_t BOFF2  = 65536;     // 3 x 16384

    extern __shared__ char smem[];
    const uint32_t sb = smem_u32(smem);
    const int tid = threadIdx.x, lane = tid & 31, wid = tid >> 5;
    const int warpM = wid >> 2, warpN = wid & 3;
    const int m0 = blockIdx.y * 64, n0 = blockIdx.x * 128;
    const int s = tid & 7,  rb = tid >> 3;
    const int s2 = tid & 15, rb2 = tid >> 4;

    float cacc[2][4][4];
#pragma unroll
    for (int mt = 0; mt < 2; mt++)
#pragma unroll
        for (int nt = 0; nt < 4; nt++)
#pragma unroll
            for (int q = 0; q < 4; q++) cacc[mt][nt][q] = 0.0f;

    auto ISSUE_A32 = [&](int c, int st) {
        const uint32_t aB = sb + A32OFF + (uint32_t)st * 16384u;
#pragma unroll
        for (int it = 0; it < 4; it++) {
            int r = rb2 + it * 16;
            int g = m0 + r;
            uint32_t zf = (g < nrows) ? 16u : 0u;
            const char* src = (const char*)(Af32 + (size_t)g * KT + c * 64 + s2 * 4);
            CP_ASYNC16(aB + (uint32_t)r * 256u + (uint32_t)s2 * 16u, src, zf);
        }
    };

    auto ISSUE_B = [&](int c, int st) {
        const uint32_t bB = sb + BOFF2 + (uint32_t)st * 16384u;
#pragma unroll
        for (int it = 0; it < 4; it++) {
            int r = rb + it * 32;
            uint32_t off = (uint32_t)r * 128u + (uint32_t)((s ^ (r & 7)) << 4);
            const char* src = (const char*)(Bh16 + (size_t)(n0 + r) * KT + c * 64 + s * 8);
            CP_ASYNC16(bB + off, src, 16);
        }
    };

    auto CONVERT = [&](int k) {
        const char* a32 = smem + A32OFF + (k % 3) * 16384;
        char* a16 = smem + A16OFF + (k & 1) * 8192;
        const int seg = s2 >> 1, sub = (s2 & 1) * 8;
#pragma unroll
        for (int it = 0; it < 4; it++) {
            int r = rb2 + it * 16;
            float4 v = *(const float4*)(a32 + r * 256 + s2 * 16);
            uint2 hv;
            hv.x = h2u(__floats2half2_rn(v.x, v.y));
            hv.y = h2u(__floats2half2_rn(v.z, v.w));
            *(uint2*)(a16 + r * 128 + ((seg ^ (r & 7)) << 4) + sub) = hv;
        }
    };

    auto COMPUTE = [&](int c) {
        const uint32_t aB = sb + A16OFF + (uint32_t)(c & 1) * 8192u;
        const uint32_t bB = sb + BOFF2 + (uint32_t)(c % 3) * 16384u;
        const int g = lane >> 3, r = lane & 7;
#pragma unroll
        for (int ks = 0; ks < 4; ks++) {
            uint32_t Afr[2][4], Bfr[2][4];
#pragma unroll
            for (int mt = 0; mt < 2; mt++) {
                int row = warpM * 32 + mt * 16 + (g & 1) * 8 + r;
                int seg = ks * 2 + (g >> 1);
                uint32_t off = (uint32_t)row * 128u + (uint32_t)((seg ^ (row & 7)) << 4);
                LDSM4(Afr[mt], aB + off);
            }
#pragma unroll
            for (int pt = 0; pt < 2; pt++) {
                int row = warpN * 32 + pt * 16 + (g >> 1) * 8 + r;
                int seg = ks * 2 + (g & 1);
                uint32_t off = (uint32_t)row * 128u + (uint32_t)((seg ^ (row & 7)) << 4);
                LDSM4(Bfr[pt], bB + off);
            }
#pragma unroll
            for (int mt = 0; mt < 2; mt++)
#pragma unroll
                for (int nt = 0; nt < 4; nt++) {
                    const uint32_t* b = &Bfr[nt >> 1][(nt & 1) * 2];
                    MMA16816F16(cacc[mt][nt], Afr[mt], b[0], b[1]);
                }
        }
    };

    ISSUE_A32(0, 0); CP_COMMIT();
    ISSUE_A32(1, 1); ISSUE_B(0, 0); CP_COMMIT();
    ISSUE_A32(2, 2); ISSUE_B(1, 1); CP_COMMIT();
    CP_WAIT2();
    __syncthreads();
    CONVERT(0);

    for (int c = 0; c < CH; c++) {
        CP_WAIT1();
        __syncthreads();
        if (c + 3 < CH) ISSUE_A32(c + 3, (c + 3) % 3);
        if (c + 2 < CH) ISSUE_B(c + 2, (c + 2) % 3);
        CP_COMMIT();
        if (c + 1 < CH) CONVERT(c + 1);
        COMPUTE(c);
    }

    const int qr = lane >> 2, qc = (lane & 3) * 2;
#pragma unroll
    for (int mt = 0; mt < 2; mt++) {
        int row0 = m0 + warpM * 32 + mt * 16 + qr;
#pragma unroll
        for (int nt = 0; nt < 4; nt++) {
            int col = n0 + warpN * 32 + nt * 8 + qc;
            float b0 = __ldg(bias + col), b1 = __ldg(bias + col + 1);
#pragma unroll
            for (int h = 0; h < 2; h++) {
                int row = row0 + h * 8;
                if (row >= nrows) continue;
                float x0 = fmaxf(cacc[mt][nt][h * 2 + 0] + b0, 0.f);
                float x1 = fmaxf(cacc[mt][nt][h * 2 + 1] + b1, 0.f);
                *(uint32_t*)(outHid + (size_t)row * NCOL + col) =
                    h2u(__floats2half2_rn(x0, x1));
            }
        }
    }
}

// ---------------------------------------------------------------------------
// GEMM2: x[N,64] = hidden[N,256] @ W2h[64,256]^T + b2.
// Outputs x fp32 AND s0 = dinv_r * x (fp16, pre-scaled Chebyshev state).
// ---------------------------------------------------------------------------
__global__ __launch_bounds__(256, 2)
void gemm2_kernel(const __half* __restrict__ Ah16, const __half* __restrict__ Bh16,
                  const float* __restrict__ bias, const float* __restrict__ dinv,
                  float* __restrict__ outF, __half* __restrict__ outS0, int nrows) {
    constexpr int KT = NHID;               // 256
    constexpr int NCOL = NOUT;             // 64
    constexpr int CH = KT / 64;            // 4
    constexpr uint32_t ASZ = 8192, BSZ = 8192;
    constexpr uint32_t BOFF2 = 3 * ASZ;

    extern __shared__ char smem[];
    const uint32_t sb = smem_u32(smem);
    const int tid = threadIdx.x, lane = tid & 31, wid = tid >> 5;
    const int warpM = wid >> 2, warpN = wid & 3;
    const int m0 = blockIdx.y * 64;
    const int s = tid & 7, rb = tid >> 3;

    float cacc[2][2][4];
#pragma unroll
    for (int mt = 0; mt < 2; mt++)
#pragma unroll
        for (int nt = 0; nt < 2; nt++)
#pragma unroll
            for (int q = 0; q < 4; q++) cacc[mt][nt][q] = 0.0f;

    auto ISSUE_A = [&](int c, int st) {
        const uint32_t aB = sb + (uint32_t)st * ASZ;
#pragma unroll
        for (int it = 0; it < 2; it++) {
            int r = rb + it * 32;
            int g = m0 + r;
            uint32_t zf = (g < nrows) ? 16u : 0u;
            uint32_t off = (uint32_t)r * 128u + (uint32_t)((s ^ (r & 7)) << 4);
            const char* src = (const char*)(Ah16 + (size_t)g * KT + c * 64 + s * 8);
            CP_ASYNC16(aB + off, src, zf);
        }
    };

    auto ISSUE_B = [&](int c, int st) {
        const uint32_t bB = sb + BOFF2 + (uint32_t)st * BSZ;
#pragma unroll
        for (int it = 0; it < 2; it++) {
            int r = rb + it * 32;
            uint32_t off = (uint32_t)r * 128u + (uint32_t)((s ^ (r & 7)) << 4);
            const char* src = (const char*)(Bh16 + (size_t)r * KT + c * 64 + s * 8);
            CP_ASYNC16(bB + off, src, 16);
        }
    };

    auto COMPUTE = [&](int c) {
        const uint32_t aB = sb + (uint32_t)(c % 3) * ASZ;
        const uint32_t bB = sb + BOFF2 + (uint32_t)(c % 3) * BSZ;
        const int g = lane >> 3, r = lane & 7;
#pragma unroll
        for (int ks = 0; ks < 4; ks++) {
            uint32_t Afr[2][4], Bfr[1][4];
#pragma unroll
            for (int mt = 0; mt < 2; mt++) {
                int row = warpM * 32 + mt * 16 + (g & 1) * 8 + r;
                int seg = ks * 2 + (g >> 1);
                uint32_t off = (uint32_t)row * 128u + (uint32_t)((seg ^ (row & 7)) << 4);
                LDSM4(Afr[mt], aB + off);
            }
            {
                int row = warpN * 16 + (g >> 1) * 8 + r;
                int seg = ks * 2 + (g & 1);
                uint32_t off = (uint32_t)row * 128u + (uint32_t)((seg ^ (row & 7)) << 4);
                LDSM4(Bfr[0], bB + off);
            }
#pragma unroll
            for (int mt = 0; mt < 2; mt++)
#pragma unroll
                for (int nt = 0; nt < 2; nt++) {
                    const uint32_t* b = &Bfr[0][nt * 2];
                    MMA16816F16(cacc[mt][nt], Afr[mt], b[0], b[1]);
                }
        }
    };

    ISSUE_A(0, 0); ISSUE_B(0, 0); CP_COMMIT();
    ISSUE_A(1, 1); ISSUE_B(1, 1); CP_COMMIT();

    for (int c = 0; c < CH; c++) {
        CP_WAIT1();
        __syncthreads();
        if (c + 2 < CH) { ISSUE_A(c + 2, (c + 2) % 3); ISSUE_B(c + 2, (c + 2) % 3); }
        CP_COMMIT();
        COMPUTE(c);
    }

    const int qr = lane >> 2, qc = (lane & 3) * 2;
#pragma unroll
    for (int mt = 0; mt < 2; mt++) {
        int row0 = m0 + warpM * 32 + mt * 16 + qr;
#pragma unroll
        for (int nt = 0; nt < 2; nt++) {
            int col = warpN * 16 + nt * 8 + qc;
            float b0 = __ldg(bias + col), b1 = __ldg(bias + col + 1);
#pragma unroll
            for (int h = 0; h < 2; h++) {
                int row = row0 + h * 8;
                if (row >= nrows) continue;
                float x0 = cacc[mt][nt][h * 2 + 0] + b0;
                float x1 = cacc[mt][nt][h * 2 + 1] + b1;
                *(float2*)(outF + (size_t)row * NCOL + col) = make_float2(x0, x1);
                float dv = __ldg(dinv + row);
                *(uint32_t*)(outS0 + (size_t)row * NCOL + col) =
                    h2u(__floats2half2_rn(dv * x0, dv * x1));
            }
        }
    }
}

// ---------------------------------------------------------------------------
// Chebyshev coefficients
// ---------------------------------------------------------------------------
__global__ void cheb_coeffs_kernel(const float* __restrict__ temp) {
    int i = threadIdx.x;
    if (i > KORD) return;
    const float PI = 3.14159265358979323846f;
    float s = 0.0f;
    for (int j = 0; j <= KORD; j++) {
        float t = fmaxf(temp[j], 0.0f);
        float theta = (KORD - j + 0.5f) * PI / (KORD + 1);
        s += t * cosf((float)i * theta);
    }
    float c = (2.0f / (KORD + 1)) * s;
    if (i == 0) c *= 0.5f;
    g_coe[i] = c;
}

// ---------------------------------------------------------------------------
// Graph preprocessing (each undirected pair handled once, 2 atomics)
// ---------------------------------------------------------------------------
__global__ void degree_kernel(const int* __restrict__ src, const int* __restrict__ dst,
                              int ehalf) {
    int e = blockIdx.x * blockDim.x + threadIdx.x;
    if (e >= ehalf) return;
    atomicAdd(&g_deg[src[e]], 1);
    atomicAdd(&g_deg[dst[e]], 1);
}

__global__ void dinv_kernel(int n) {
    int i = blockIdx.x * blockDim.x + threadIdx.x;
    if (i >= n) return;
    int d = g_deg[i];
    float dv = (d > 0) ? rsqrtf((float)d) : 0.0f;
    g_dinv[i] = dv;
    g_d2[i] = dv * dv;
    g_sqd[i] = (d > 0) ? sqrtf((float)d) : 0.0f;
}

__global__ void scan_kernel(int n) {
    __shared__ int sums[1024];
    int tid = threadIdx.x;
    int chunk = (n + 1023) / 1024;
    int start = tid * chunk;
    int end = min(start + chunk, n);
    int s = 0;
    for (int i = start; i < end; i++) s += g_deg[i];
    sums[tid] = s;
    __syncthreads();
    for (int off = 1; off < 1024; off <<= 1) {
        int v = 0;
        if (tid >= off) v = sums[tid - off];
        __syncthreads();
        if (tid >= off) sums[tid] += v;
        __syncthreads();
    }
    int prefix = (tid == 0) ? 0 : sums[tid - 1];
    for (int i = start; i < end; i++) {
        g_rowptr[i] = prefix;
        prefix += g_deg[i];
    }
    if (tid == 1023) g_rowptr[n] = prefix;
}

__global__ void build_csr_kernel(const int* __restrict__ src, const int* __restrict__ dst,
                                 int ehalf) {
    int e = blockIdx.x * blockDim.x + threadIdx.x;
    if (e >= ehalf) return;
    int s = src[e];
    int d = dst[e];
    int p1 = g_rowptr[s] + atomicAdd(&g_cursor[s], 1);
    g_col[p1] = d;
    int p2 = g_rowptr[d] + atomicAdd(&g_cursor[d], 1);
    g_col[p2] = s;
}

// ---------------------------------------------------------------------------
// Propagation over pre-scaled state s_i = dinv * Tx_i:
//   G_r = sum_{c in N(r)} s_i[c]     (UNWEIGHTED gather)
//   s_{i+1} = -2 * d2_r * G - s_{i-1}
// 4 nodes/warp, 8 lanes/node, lane owns 8 feats (uint4 of fp16).
// ---------------------------------------------------------------------------
__device__ __forceinline__ void csr_gather8u(const __half* __restrict__ v,
                                             int beg, int end, int lane,
                                             float* __restrict__ acc) {
    const int lane8 = lane & 7;
    const int grpBase = lane & 24;     // (lane>>3)*8
    for (int j = beg; __any_sync(0xffffffffu, j < end); j += 8) {
        int myc = -1;
        int idx = j + lane8;
        if (idx < end && j < end) myc = g_col[idx];
#pragma unroll
        for (int t = 0; t < 8; t++) {
            int c = __shfl_sync(0xffffffffu, myc, grpBase + t);
            if (c >= 0) {
                uint4 hv = *(const uint4*)(v + ((size_t)c << 6) + (lane8 << 3));
                const __half2* hp = (const __half2*)&hv;
                float2 f0 = __half22float2(hp[0]);
                float2 f1 = __half22float2(hp[1]);
                float2 f2 = __half22float2(hp[2]);
                float2 f3 = __half22float2(hp[3]);
                acc[0] += f0.x;  acc[1] += f0.y;
                acc[2] += f1.x;  acc[3] += f1.y;
                acc[4] += f2.x;  acc[5] += f2.y;
                acc[6] += f3.x;  acc[7] += f3.y;
            }
        }
    }
}

__device__ __forceinline__ uint4 pack_h8(const float* a) {
    uint4 r;
    *(__half2*)&r.x = __floats2half2_rn(a[0], a[1]);
    *(__half2*)&r.y = __floats2half2_rn(a[2], a[3]);
    *(__half2*)&r.z = __floats2half2_rn(a[4], a[5]);
    *(__half2*)&r.w = __floats2half2_rn(a[6], a[7]);
    return r;
}

// s1 = -d2 * gather(s0)
__global__ __launch_bounds__(256)
void prop_first_kernel(const __half* __restrict__ s0, __half* __restrict__ s1, int n) {
    int gw = (blockIdx.x * blockDim.x + threadIdx.x) >> 5;
    int lane = threadIdx.x & 31;
    int node = gw * 4 + (lane >> 3);
    bool ok = node < n;
    int beg = 0, end = 0;
    if (ok) { beg = g_rowptr[node]; end = g_rowptr[node + 1]; }
    float acc[8] = {0.f, 0.f, 0.f, 0.f, 0.f, 0.f, 0.f, 0.f};
    csr_gather8u(s0, beg, end, lane, acc);
    if (!ok) return;
    float md2 = -g_d2[node];
#pragma unroll
    for (int q = 0; q < 8; q++) acc[q] *= md2;
    size_t fb = ((size_t)node << 6) + ((lane & 7) << 3);
    *(uint4*)(s1 + fb) = pack_h8(acc);
}

// s_{i+1} = -2*d2*gather(s_i) - s_{i-1}
__global__ __launch_bounds__(256)
void prop_step_kernel(const __half* __restrict__ si, const __half* __restrict__ sim1,
                      __half* __restrict__ sip1, int n) {
    int gw = (blockIdx.x * blockDim.x + threadIdx.x) >> 5;
    int lane = threadIdx.x & 31;
    int node = gw * 4 + (lane >> 3);
    bool ok = node < n;
    int beg = 0, end = 0;
    if (ok) { beg = g_rowptr[node]; end = g_rowptr[node + 1]; }
    float acc[8] = {0.f, 0.f, 0.f, 0.f, 0.f, 0.f, 0.f, 0.f};
    csr_gather8u(si, beg, end, lane, acc);
    if (!ok) return;
    float m2d2 = -2.0f * g_d2[node];
    size_t fb = ((size_t)node << 6) + ((lane & 7) << 3);
    uint4 t0v = *(const uint4*)(sim1 + fb);
    const __half2* t0p = (const __half2*)&t0v;
    float t2[8];
    {
        float2 a = __half22float2(t0p[0]), b = __half22float2(t0p[1]);
        float2 c = __half22float2(t0p[2]), d = __half22float2(t0p[3]);
        t2[0] = fmaf(m2d2, acc[0], -a.x);  t2[1] = fmaf(m2d2, acc[1], -a.y);
        t2[2] = fmaf(m2d2, acc[2], -b.x);  t2[3] = fmaf(m2d2, acc[3], -b.y);
        t2[4] = fmaf(m2d2, acc[4], -c.x);  t2[5] = fmaf(m2d2, acc[5], -c.y);
        t2[6] = fmaf(m2d2, acc[6], -d.x);  t2[7] = fmaf(m2d2, acc[7], -d.y);
    }
    *(uint4*)(sip1 + fb) = pack_h8(t2);
}

// Last step fused with combine:
// s10 = -2*d2*gather(s9) - s8 (regs)
// deg>0: out = c0*x + sqd_r * (sum_{k=1..9} coe_k s_k + coe_10 s10)
// deg=0: out = (c0 - coe2 + coe4 - coe6 + coe8 - coe10) * x
__global__ __launch_bounds__(256)
void prop_last_kernel(const __half* __restrict__ s9, const __half* __restrict__ s8,
                      const __half* __restrict__ sT, const float* __restrict__ xf,
                      float* __restrict__ out, int n) {
    int gw = (blockIdx.x * blockDim.x + threadIdx.x) >> 5;
    int lane = threadIdx.x & 31;
    int node = gw * 4 + (lane >> 3);
    bool ok = node < n;
    int beg = 0, end = 0;
    if (ok) { beg = g_rowptr[node]; end = g_rowptr[node + 1]; }
    float acc[8] = {0.f, 0.f, 0.f, 0.f, 0.f, 0.f, 0.f, 0.f};
    csr_gather8u(s9, beg, end, lane, acc);
    if (!ok) return;
    size_t fb = ((size_t)node << 6) + ((lane & 7) << 3);

    float sqd = g_sqd[node];
    float c0 = g_coe[0];   // pre-halved
    float4 x0 = *(const float4*)(xf + fb);
    float4 x1 = *(const float4*)(xf + fb + 4);

    if (sqd == 0.0f) {     // isolated node: Tx_k = cos(k*pi/2) * x exactly
        float cfb = c0 - g_coe[2] + g_coe[4] - g_coe[6] + g_coe[8] - g_coe[10];
        *(float4*)(out + fb) = make_float4(cfb * x0.x, cfb * x0.y, cfb * x0.z, cfb * x0.w);
        *(float4*)(out + fb + 4) = make_float4(cfb * x1.x, cfb * x1.y, cfb * x1.z, cfb * x1.w);
        return;
    }

    // s10 in regs
    float m2d2 = -2.0f * g_d2[node];
    float s10[8];
    {
        uint4 t0v = *(const uint4*)(s8 + fb);
        const __half2* t0p = (const __half2*)&t0v;
        float2 a = __half22float2(t0p[0]), b = __half22float2(t0p[1]);
        float2 c = __half22float2(t0p[2]), d = __half22float2(t0p[3]);
        s10[0] = fmaf(m2d2, acc[0], -a.x);  s10[1] = fmaf(m2d2, acc[1], -a.y);
        s10[2] = fmaf(m2d2, acc[2], -b.x);  s10[3] = fmaf(m2d2, acc[3], -b.y);
        s10[4] = fmaf(m2d2, acc[4], -c.x);  s10[5] = fmaf(m2d2, acc[5], -c.y);
        s10[6] = fmaf(m2d2, acc[6], -d.x);  s10[7] = fmaf(m2d2, acc[7], -d.y);
    }

    float res[8] = {0.f, 0.f, 0.f, 0.f, 0.f, 0.f, 0.f, 0.f};
#pragma unroll
    for (int k = 1; k <= KORD - 1; k++) {
        float ck = g_coe[k];
        uint4 v = *(const uint4*)(sT + (size_t)(k - 1) * SZNO + fb);
        const __half2* hp = (const __half2*)&v;
        float2 f0 = __half22float2(hp[0]);
        float2 f1 = __half22float2(hp[1]);
        float2 f2 = __half22float2(hp[2]);
        float2 f3 = __half22float2(hp[3]);
        res[0] = fmaf(ck, f0.x, res[0]);
        res[1] = fmaf(ck, f0.y, res[1]);
        res[2] = fmaf(ck, f1.x, res[2]);
        res[3] = fmaf(ck, f1.y, res[3]);
        res[4] = fmaf(ck, f2.x, res[4]);
        res[5] = fmaf(ck, f2.y, res[5]);
        res[6] = fmaf(ck, f3.x, res[6]);
        res[7] = fmaf(ck, f3.y, res[7]);
    }
    float cK = g_coe[KORD];
#pragma unroll
    for (int q = 0; q < 8; q++) res[q] = fmaf(cK, s10[q], res[q]);

    float o[8];
    o[0] = fmaf(sqd, res[0], c0 * x0.x);
    o[1] = fmaf(sqd, res[1], c0 * x0.y);
    o[2] = fmaf(sqd, res[2], c0 * x0.z);
    o[3] = fmaf(sqd, res[3], c0 * x0.w);
    o[4] = fmaf(sqd, res[4], c0 * x1.x);
    o[5] = fmaf(sqd, res[5], c0 * x1.y);
    o[6] = fmaf(sqd, res[6], c0 * x1.z);
    o[7] = fmaf(sqd, res[7], c0 * x1.w);
    *(float4*)(out + fb) = make_float4(o[0], o[1], o[2], o[3]);
    *(float4*)(out + fb + 4) = make_float4(o[4], o[5], o[6], o[7]);
}

// ---------------------------------------------------------------------------
// Launch
// ---------------------------------------------------------------------------
extern "C" void kernel_launch(void* const* d_in, const int* in_sizes, int n_in,
                              void* d_out, int out_size) {
    const float* feature = (const float*)d_in[0];
    const float* W1      = (const float*)d_in[1];
    const float* b1      = (const float*)d_in[2];
    const float* W2      = (const float*)d_in[3];
    const float* b2      = (const float*)d_in[4];
    const float* temp    = (const float*)d_in[5];
    const int*   edge    = (const int*)d_in[6];

    const int n = NNODES;
    const int E = in_sizes[6] / 2;            // 3,200,000 directed
    const int Eh = E / 2;                     // 1,600,000 pairs
    const int* src = edge;                    // row = [src; dst]
    const int* dst = edge + Eh;               // since row=concat(src,dst), col=concat(dst,src)
    float* out = (float*)d_out;

    void *p_xf, *p_s0, *p_sT, *p_deg, *p_cursor, *p_hidH, *p_w1h, *p_w2h, *p_dinv;
    cudaGetSymbolAddress(&p_xf, g_xf);
    cudaGetSymbolAddress(&p_s0, g_s0);
    cudaGetSymbolAddress(&p_sT, g_sT);
    cudaGetSymbolAddress(&p_deg, g_deg);
    cudaGetSymbolAddress(&p_cursor, g_cursor);
    cudaGetSymbolAddress(&p_hidH, g_hidH);
    cudaGetSymbolAddress(&p_w1h, g_W1h);
    cudaGetSymbolAddress(&p_w2h, g_W2h);
    cudaGetSymbolAddress(&p_dinv, g_dinv);

    // 1. Chebyshev coefficients + weight conversion
    cheb_coeffs_kernel<<<1, 32>>>(temp);
    tohalf_kernel<<<(NHID * NFEAT + 255) / 256, 256>>>(W1, (__half*)p_w1h, NHID * NFEAT);
    tohalf_kernel<<<(NOUT * NHID + 255) / 256, 256>>>(W2, (__half*)p_w2h, NOUT * NHID);

    // 2. Graph preprocessing -> CSR (columns only) BEFORE GEMM2 (needs dinv)
    cudaMemsetAsync(p_deg, 0, n * sizeof(int), 0);
    cudaMemsetAsync(p_cursor, 0, n * sizeof(int), 0);
    degree_kernel<<<(Eh + 255) / 256, 256>>>(src, dst, Eh);
    dinv_kernel<<<(n + 255) / 256, 256>>>(n);
    scan_kernel<<<1, 1024>>>(n);
    build_csr_kernel<<<(Eh + 255) / 256, 256>>>(src, dst, Eh);

    // 3. MLP on mma.sync tensor cores
    {
        const int mblocks = (n + 63) / 64;                   // 1563
        const int smem1 = 3 * 16384 + 2 * 8192 + 3 * 16384;  // 114688
        const int smem2 = 3 * 8192 + 3 * 8192;               // 49152
        cudaFuncSetAttribute(gemm1_kernel,
                             cudaFuncAttributeMaxDynamicSharedMemorySize, smem1);
        cudaFuncSetAttribute(gemm2_kernel,
                             cudaFuncAttributeMaxDynamicSharedMemorySize, smem2);
        dim3 grid1(NHID / 128, mblocks);
        gemm1_kernel<<<grid1, 256, smem1>>>(feature, (const __half*)p_w1h, b1,
                                            (__half*)p_hidH, n);
        dim3 grid2(1, mblocks);
        gemm2_kernel<<<grid2, 256, smem2>>>((const __half*)p_hidH, (const __half*)p_w2h,
                                            b2, (const float*)p_dinv,
                                            (float*)p_xf, (__half*)p_s0, n);
    }

    // 4. Chebyshev propagation over scaled state; last step fused w/ combine
    int nwarps = (n + 3) / 4;                      // 25000
    int pblocks = (nwarps + 7) / 8;                // 3125
    __half* s0 = (__half*)p_s0;
    __half* sT = (__half*)p_sT;
    prop_first_kernel<<<pblocks, 256>>>(s0, sT, n);                       // s1
    prop_step_kernel<<<pblocks, 256>>>(sT, s0, sT + SZNO, n);             // s2
    for (int i = 3; i <= KORD - 1; i++) {
        prop_step_kernel<<<pblocks, 256>>>(sT + (size_t)(i - 2) * SZNO,
                                           sT + (size_t)(i - 3) * SZNO,
                                           sT + (size_t)(i - 1) * SZNO, n);
    }
    prop_last_kernel<<<pblocks, 256>>>(sT + (size_t)(KORD - 2) * SZNO,
                                       sT + (size_t)(KORD - 3) * SZNO,
                                       sT, (const float*)p_xf, out, n);

    (void)n_in; (void)out_size;
}